// round 7
// baseline (speedup 1.0000x reference)
#include <cuda_runtime.h>

#define NMAX 50000
#define EMAX 1600000

// ---------------- static device scratch ----------------
__device__ int   g_cnt[NMAX];          // zero at load; re-zeroed by scan each run
__device__ int   g_off[NMAX + 1];
__device__ int   g_cur[NMAX];
__device__ int   g_epk[EMAX];          // src node per CSR slot
__device__ int   g_slot[EMAX];         // edge id -> CSR slot
__device__ float g_q[NMAX * 64];
__device__ float g_k[NMAX * 64];
__device__ float g_v[NMAX * 64];
__device__ float g_h[NMAX * 64];
__device__ float g_A[NMAX * 32];
__device__ float g_B[NMAX * 32];
__device__ float g_e[EMAX * 32];
__device__ float g_bias[EMAX * 4];     // score bias in CSR-slot order

// ---------------- f32x2 packed helpers (sm_103a FFMA2 path) ----------------
__device__ __forceinline__ unsigned long long pk2(float a, float b) {
    unsigned long long r;
    asm("mov.b64 %0, {%1, %2};" : "=l"(r) : "f"(a), "f"(b));
    return r;
}
__device__ __forceinline__ void upk2(unsigned long long v, float& a, float& b) {
    asm("mov.b64 {%0, %1}, %2;" : "=f"(a), "=f"(b) : "l"(v));
}
__device__ __forceinline__ unsigned long long fma2(unsigned long long a,
                                                   unsigned long long b,
                                                   unsigned long long c) {
    unsigned long long d;
    asm("fma.rn.f32x2 %0, %1, %2, %3;" : "=l"(d) : "l"(a), "l"(b), "l"(c));
    return d;
}

// ---------------- count ----------------
__global__ void k_count(const int* __restrict__ dst, int e) {
    int i = blockIdx.x * blockDim.x + threadIdx.x;
    if (i < e) atomicAdd(&g_cnt[dst[i]], 1);
}

// ---------------- fused: block0 = exclusive scan (+re-zero cnt), rest = qkv proj ----------------
__global__ void k_scanproj(int n, const float* __restrict__ hin, int useG,
                           const float* __restrict__ Wq, const float* __restrict__ Wk,
                           const float* __restrict__ Wv, int withScan) {
    __shared__ float sq[4096], sk[4096], sv[4096];
    __shared__ int swi[32];
    int t = threadIdx.x;
    if (withScan && blockIdx.x == 0) {
        int lane = t & 31, w = t >> 5;
        int carry = 0;
        for (int base = 0; base < n; base += 1024) {
            int i = base + t;
            int v = (i < n) ? g_cnt[i] : 0;
            if (i < n) g_cnt[i] = 0;              // reset for next run
            int x = v;
#pragma unroll
            for (int o = 1; o < 32; o <<= 1) {
                int y = __shfl_up_sync(0xffffffffu, x, o);
                if (lane >= o) x += y;
            }
            if (lane == 31) swi[w] = x;
            __syncthreads();
            if (t < 32) {
                int s = swi[t];
#pragma unroll
                for (int o = 1; o < 32; o <<= 1) {
                    int y = __shfl_up_sync(0xffffffffu, s, o);
                    if (t >= o) s += y;
                }
                swi[t] = s;
            }
            __syncthreads();
            int pref = (w > 0) ? swi[w - 1] : 0;
            int excl = carry + pref + x - v;
            if (i < n) { g_off[i] = excl; g_cur[i] = excl; }
            carry += swi[31];
            __syncthreads();
        }
        if (t == 0) g_off[n] = carry;
        return;
    }
    int bp = blockIdx.x - withScan;
    for (int i = t; i < 4096; i += 1024) { sq[i] = Wq[i]; sk[i] = Wk[i]; sv[i] = Wv[i]; }
    __syncthreads();
    const float* h = useG ? g_h : hin;
    int lane = t & 31, w = t >> 5;
    int r0 = (bp * 32 + w) * 4;
    float h0[4], h1[4];
#pragma unroll
    for (int r = 0; r < 4; r++) {
        int row = r0 + r;
        h0[r] = (row < n) ? h[row * 64 + lane] : 0.f;
        h1[r] = (row < n) ? h[row * 64 + lane + 32] : 0.f;
    }
    float aq0[4] = {0,0,0,0}, aq1[4] = {0,0,0,0};
    float ak0[4] = {0,0,0,0}, ak1[4] = {0,0,0,0};
    float av0[4] = {0,0,0,0}, av1[4] = {0,0,0,0};
#pragma unroll
    for (int j = 0; j < 32; j++) {
        float wq0 = sq[j * 64 + lane], wq1 = sq[j * 64 + lane + 32];
        float wk0 = sk[j * 64 + lane], wk1 = sk[j * 64 + lane + 32];
        float wv0 = sv[j * 64 + lane], wv1 = sv[j * 64 + lane + 32];
#pragma unroll
        for (int r = 0; r < 4; r++) {
            float hj = __shfl_sync(0xffffffffu, h0[r], j);
            aq0[r] += hj * wq0; aq1[r] += hj * wq1;
            ak0[r] += hj * wk0; ak1[r] += hj * wk1;
            av0[r] += hj * wv0; av1[r] += hj * wv1;
        }
    }
#pragma unroll
    for (int j = 0; j < 32; j++) {
        float wq0 = sq[(j + 32) * 64 + lane], wq1 = sq[(j + 32) * 64 + lane + 32];
        float wk0 = sk[(j + 32) * 64 + lane], wk1 = sk[(j + 32) * 64 + lane + 32];
        float wv0 = sv[(j + 32) * 64 + lane], wv1 = sv[(j + 32) * 64 + lane + 32];
#pragma unroll
        for (int r = 0; r < 4; r++) {
            float hj = __shfl_sync(0xffffffffu, h1[r], j);
            aq0[r] += hj * wq0; aq1[r] += hj * wq1;
            ak0[r] += hj * wk0; ak1[r] += hj * wk1;
            av0[r] += hj * wv0; av1[r] += hj * wv1;
        }
    }
#pragma unroll
    for (int r = 0; r < 4; r++) {
        int row = r0 + r;
        if (row >= n) break;
        g_q[row * 64 + lane] = aq0[r]; g_q[row * 64 + lane + 32] = aq1[r];
        g_k[row * 64 + lane] = ak0[r]; g_k[row * 64 + lane + 32] = ak1[r];
        g_v[row * 64 + lane] = av0[r]; g_v[row * 64 + lane + 32] = av1[r];
    }
}

// ---------------- fused scatter + layer-0 bias ----------------
__global__ void k_scatbias(const int* __restrict__ src, const int* __restrict__ dstp,
                           const float* __restrict__ ef, const float* __restrict__ We, int e) {
    __shared__ float sW[128];
    __shared__ float buf[4][32 * 33];
    int t = threadIdx.x;
    if (t < 128) sW[t] = We[t];
    __syncthreads();
    int w = t >> 5, lane = t & 31;
    int base = (blockIdx.x * 4 + w) * 32;
    float* b = buf[w];
    int ed0 = base + lane;
    int slot = -1;
    if (ed0 < e) {
        int d = __ldg(dstp + ed0);
        slot = atomicAdd(&g_cur[d], 1);
        g_epk[slot] = __ldg(src + ed0);
        g_slot[ed0] = slot;
    }
#pragma unroll 4
    for (int j = 0; j < 32; j++) {
        int ed = base + j;
        b[j * 33 + lane] = (ed < e) ? __ldg(ef + (size_t)ed * 32 + lane) : 0.f;
    }
    __syncwarp();
    if (ed0 >= e) return;
    float4 bb = make_float4(0.f, 0.f, 0.f, 0.f);
#pragma unroll
    for (int k = 0; k < 32; k++) {
        float ek = b[lane * 33 + k];
        float4 wv = *(const float4*)(sW + k * 4);
        bb.x += ek * wv.x; bb.y += ek * wv.y; bb.z += ek * wv.z; bb.w += ek * wv.w;
    }
    ((float4*)g_bias)[slot] = bb;
}

// ---------------- fused attention + node update ----------------
// attention (unroll-4, direct exp) -> agg row lives in warp registers ->
// redistribute via 8 shfls -> h = LN(h + agg@Wo) -> optional A,B = h_new @ Wem[0:128]
__global__ void __launch_bounds__(512)
k_attnln(const float* __restrict__ hin, int useGin,
         const float* __restrict__ Wo, const float* __restrict__ gn,
         const float* __restrict__ bn, const float* __restrict__ Wab,
         float* __restrict__ outp, int useOut, int doAB, int n) {
    __shared__ float sWo[4096];
    __shared__ float sAB[4096];
    int t = threadIdx.x;
    for (int i = t; i < 4096; i += 512) {
        sWo[i] = Wo[i];
        if (doAB) sAB[i] = Wab[i];
    }
    __syncthreads();
    int lane = t & 31, w = t >> 5;
    int node = blockIdx.x * 16 + w;
    if (node >= n) return;
    int half = lane >> 4;
    int sub = lane & 15;
    int head = sub >> 2;
    int beg = g_off[node], end = g_off[node + 1];
    float4 q4 = *(const float4*)(g_q + (size_t)node * 64 + sub * 4);
    q4.x *= 0.25f; q4.y *= 0.25f; q4.z *= 0.25f; q4.w *= 0.25f;
    float4 acc = make_float4(0.f, 0.f, 0.f, 0.f);
    float d = 0.f;
    for (int p = beg; p < end; p += 4) {
        int i0 = p + half;
        int i1 = p + 2 + half;
        bool u0 = (i0 < end), u1 = (i1 < end);
        int e0 = u0 ? i0 : beg;          // clamped reads stay in-bounds
        int e1 = u1 ? i1 : beg;
        int s0 = __ldg(&g_epk[e0]);
        int s1 = __ldg(&g_epk[e1]);
        float4 k0 = __ldg((const float4*)(g_k + (size_t)s0 * 64) + sub);
        float4 k1 = __ldg((const float4*)(g_k + (size_t)s1 * 64) + sub);
        float4 w0 = __ldg((const float4*)(g_v + (size_t)s0 * 64) + sub);
        float4 w1 = __ldg((const float4*)(g_v + (size_t)s1 * 64) + sub);
        float b0 = __ldg(g_bias + (size_t)e0 * 4 + head);
        float b1 = __ldg(g_bias + (size_t)e1 * 4 + head);
        float dt0 = q4.x * k0.x + q4.y * k0.y + q4.z * k0.z + q4.w * k0.w;
        float dt1 = q4.x * k1.x + q4.y * k1.y + q4.z * k1.z + q4.w * k1.w;
        dt0 += __shfl_xor_sync(0xffffffffu, dt0, 1);
        dt1 += __shfl_xor_sync(0xffffffffu, dt1, 1);
        dt0 += __shfl_xor_sync(0xffffffffu, dt0, 2);
        dt1 += __shfl_xor_sync(0xffffffffu, dt1, 2);
        float ex0 = u0 ? __expf(dt0 + b0) : 0.f;
        float ex1 = u1 ? __expf(dt1 + b1) : 0.f;
        d += ex0; d += ex1;
        acc.x += ex0 * w0.x; acc.y += ex0 * w0.y; acc.z += ex0 * w0.z; acc.w += ex0 * w0.w;
        acc.x += ex1 * w1.x; acc.y += ex1 * w1.y; acc.z += ex1 * w1.z; acc.w += ex1 * w1.w;
    }
    acc.x += __shfl_xor_sync(0xffffffffu, acc.x, 16);
    acc.y += __shfl_xor_sync(0xffffffffu, acc.y, 16);
    acc.z += __shfl_xor_sync(0xffffffffu, acc.z, 16);
    acc.w += __shfl_xor_sync(0xffffffffu, acc.w, 16);
    d     += __shfl_xor_sync(0xffffffffu, d, 16);
    float inv = 1.f / (d + 1e-9f);
    float4 o;
    o.x = acc.x * inv; o.y = acc.y * inv; o.z = acc.z * inv; o.w = acc.w * inv;

    // redistribute: a0 = agg[lane], a1 = agg[lane+32]
    int srcl = lane >> 2, c = lane & 3;
    float rx = __shfl_sync(0xffffffffu, o.x, srcl);
    float ry = __shfl_sync(0xffffffffu, o.y, srcl);
    float rz = __shfl_sync(0xffffffffu, o.z, srcl);
    float rw = __shfl_sync(0xffffffffu, o.w, srcl);
    float a0 = (c == 0) ? rx : (c == 1) ? ry : (c == 2) ? rz : rw;
    rx = __shfl_sync(0xffffffffu, o.x, 8 + srcl);
    ry = __shfl_sync(0xffffffffu, o.y, 8 + srcl);
    rz = __shfl_sync(0xffffffffu, o.z, 8 + srcl);
    rw = __shfl_sync(0xffffffffu, o.w, 8 + srcl);
    float a1 = (c == 0) ? rx : (c == 1) ? ry : (c == 2) ? rz : rw;

    // node update: h = LN(h + agg@Wo)
    const float* h = useGin ? g_h : hin;
    float o0 = 0.f, o1 = 0.f;
#pragma unroll
    for (int j = 0; j < 32; j++) {
        float aj = __shfl_sync(0xffffffffu, a0, j);
        o0 += aj * sWo[j * 64 + lane];
        o1 += aj * sWo[j * 64 + lane + 32];
    }
#pragma unroll
    for (int j = 0; j < 32; j++) {
        float aj = __shfl_sync(0xffffffffu, a1, j);
        o0 += aj * sWo[(j + 32) * 64 + lane];
        o1 += aj * sWo[(j + 32) * 64 + lane + 32];
    }
    float x0 = h[(size_t)node * 64 + lane] + o0;
    float x1 = h[(size_t)node * 64 + lane + 32] + o1;
    float s = x0 + x1;
#pragma unroll
    for (int ofs = 16; ofs; ofs >>= 1) s += __shfl_xor_sync(0xffffffffu, s, ofs);
    float mu = s * (1.f / 64.f);
    float d0 = x0 - mu, d1 = x1 - mu;
    float vs = d0 * d0 + d1 * d1;
#pragma unroll
    for (int ofs = 16; ofs; ofs >>= 1) vs += __shfl_xor_sync(0xffffffffu, vs, ofs);
    float inv2 = rsqrtf(vs * (1.f / 64.f) + 1e-5f);
    float y0 = d0 * inv2 * __ldg(gn + lane) + __ldg(bn + lane);
    float y1 = d1 * inv2 * __ldg(gn + lane + 32) + __ldg(bn + lane + 32);
    float* hp = useOut ? outp : g_h;
    hp[(size_t)node * 64 + lane] = y0;
    hp[(size_t)node * 64 + lane + 32] = y1;
    if (doAB) {
        float A = 0.f, B = 0.f;
#pragma unroll
        for (int j = 0; j < 32; j++) {
            float yj = __shfl_sync(0xffffffffu, y0, j);
            A += yj * sAB[j * 32 + lane];
            B += yj * sAB[(j + 64) * 32 + lane];
        }
#pragma unroll
        for (int j = 0; j < 32; j++) {
            float yj = __shfl_sync(0xffffffffu, y1, j);
            A += yj * sAB[(j + 32) * 32 + lane];
            B += yj * sAB[(j + 96) * 32 + lane];
        }
        g_A[node * 32 + lane] = A;
        g_B[node * 32 + lane] = B;
    }
}

// ---------------- edge update (single pass, f32x2 GEMM via reinterpreted smem) ----------------
__global__ void k_edge(const float* __restrict__ ein, int useGE,
                       const float* __restrict__ Wem2, const float* __restrict__ bem,
                       const float* __restrict__ ge, const float* __restrict__ be,
                       const float* __restrict__ WeN,
                       const int* __restrict__ src, const int* __restrict__ dstp,
                       int e, int storeE) {
    __shared__ float sW[1024];
    __shared__ float sWeN[128];
    __shared__ float sbem[32], sge[32], sbe[32];
    __shared__ float buf[4][32 * 33];
    int t = threadIdx.x;
    for (int i = t; i < 1024; i += 128) sW[i] = Wem2[i];
    if (t < 128) sWeN[t] = WeN[t];
    if (t < 32) { sbem[t] = bem[t]; sge[t] = ge[t]; sbe[t] = be[t]; }
    __syncthreads();
    int w = t >> 5, lane = t & 31;
    int base = (blockIdx.x * 4 + w) * 32;
    float* b = buf[w];
    const float* ebase = useGE ? (const float*)g_e : ein;

#pragma unroll 4
    for (int j = 0; j < 32; j++) {
        int ed = base + j;
        b[j * 33 + lane] = (ed < e) ? __ldg(ebase + (size_t)ed * 32 + lane) : 0.f;
    }
    __syncwarp();
    float er[32];
#pragma unroll
    for (int k = 0; k < 32; k++) er[k] = b[lane * 33 + k];
    __syncwarp();

    int ed0 = base + lane;
    int s_l = (ed0 < e) ? __ldg(src + ed0)  : 0;
    int d_l = (ed0 < e) ? __ldg(dstp + ed0) : 0;

#pragma unroll 4
    for (int j = 0; j < 32; j++) {
        int sj = __shfl_sync(0xffffffffu, s_l, j);
        b[j * 33 + lane] = __ldg(g_A + (size_t)sj * 32 + lane);
    }
    __syncwarp();
    float acc[32];
#pragma unroll
    for (int k = 0; k < 32; k++) acc[k] = b[lane * 33 + k] + sbem[k];
    __syncwarp();
#pragma unroll 4
    for (int j = 0; j < 32; j++) {
        int dj = __shfl_sync(0xffffffffu, d_l, j);
        b[j * 33 + lane] = __ldg(g_B + (size_t)dj * 32 + lane);
    }
    __syncwarp();
#pragma unroll
    for (int k = 0; k < 32; k++) acc[k] += b[lane * 33 + k];
    __syncwarp();

    // e @ Wem2 on packed f32x2: W pairs read directly as u64 from smem (no repacking)
    unsigned long long acc2[16];
#pragma unroll
    for (int j = 0; j < 16; j++) acc2[j] = pk2(acc[2 * j], acc[2 * j + 1]);
#pragma unroll
    for (int k = 0; k < 32; k++) {
        unsigned long long ek2 = pk2(er[k], er[k]);
        const ulonglong2* wr = (const ulonglong2*)(sW + k * 32);
#pragma unroll
        for (int j = 0; j < 8; j++) {
            ulonglong2 ww = wr[j];
            acc2[2 * j]     = fma2(ek2, ww.x, acc2[2 * j]);
            acc2[2 * j + 1] = fma2(ek2, ww.y, acc2[2 * j + 1]);
        }
    }
#pragma unroll
    for (int j = 0; j < 16; j++) upk2(acc2[j], acc[2 * j], acc[2 * j + 1]);

    float mu = 0.f;
#pragma unroll
    for (int j = 0; j < 32; j++) {
        float u = acc[j];
        float z = 0.7978845608028654f * (u + 0.044715f * u * u * u);
        float th = 1.f - 2.f / (__expf(2.f * z) + 1.f);
        float x = er[j] + 0.5f * u * (1.f + th);
        acc[j] = x;
        mu += x;
    }
    mu *= (1.f / 32.f);
    float var = 0.f;
#pragma unroll
    for (int j = 0; j < 32; j++) { float dx = acc[j] - mu; var += dx * dx; }
    float inv = rsqrtf(var * (1.f / 32.f) + 1e-5f);
    float4 bb = make_float4(0.f, 0.f, 0.f, 0.f);
#pragma unroll
    for (int j = 0; j < 32; j++) {
        float y = (acc[j] - mu) * inv * sge[j] + sbe[j];
        acc[j] = y;
        float4 wv = *(const float4*)(sWeN + j * 4);
        bb.x += y * wv.x; bb.y += y * wv.y; bb.z += y * wv.z; bb.w += y * wv.w;
    }
    if (ed0 < e) {
        int slot = __ldg(g_slot + ed0);
        ((float4*)g_bias)[slot] = bb;
    }
    if (storeE) {
        __syncwarp();
#pragma unroll
        for (int k = 0; k < 32; k++) b[lane * 33 + k] = acc[k];
        __syncwarp();
#pragma unroll 4
        for (int j = 0; j < 32; j++) {
            int ed = base + j;
            if (ed < e) g_e[(size_t)ed * 32 + lane] = b[j * 33 + lane];
        }
    }
}

// ---------------- launch ----------------
extern "C" void kernel_launch(void* const* d_in, const int* in_sizes, int n_in,
                              void* d_out, int out_size) {
    const float* nodef = (const float*)d_in[0];
    const float* edgef = (const float*)d_in[1];
    const int*   ei    = (const int*)d_in[2];
    const float* Wq    = (const float*)d_in[3];
    const float* Wk    = (const float*)d_in[4];
    const float* Wv    = (const float*)d_in[5];
    const float* Wo    = (const float*)d_in[6];
    const float* We    = (const float*)d_in[7];
    const float* Wem   = (const float*)d_in[8];
    const float* bem   = (const float*)d_in[9];
    const float* gn    = (const float*)d_in[10];
    const float* bn    = (const float*)d_in[11];
    const float* ge    = (const float*)d_in[12];
    const float* be    = (const float*)d_in[13];
    float* out = (float*)d_out;

    int n = in_sizes[0] / 64;
    int e = in_sizes[1] / 32;
    const int* src = ei;
    const int* dst = ei + e;
    int projBlocks = (n + 127) / 128;

    // 0: count  1: scan+proj(L0)  2: scatter+bias0  3: attnln(L0) <- profiled
    k_count<<<(e + 255) / 256, 256>>>(dst, e);
    k_scanproj<<<projBlocks + 1, 1024>>>(n, nodef, 0, Wq, Wk, Wv, 1);
    k_scatbias<<<(e + 127) / 128, 128>>>(src, dst, edgef, We, e);

    for (int i = 0; i < 3; i++) {
        if (i > 0)
            k_scanproj<<<projBlocks, 1024>>>(n, nodef, 1,
                                             Wq + i * 4096, Wk + i * 4096, Wv + i * 4096, 0);
        int last = (i == 2);
        k_attnln<<<(n + 15) / 16, 512>>>(nodef, (i > 0),
                                         Wo + i * 4096, gn + i * 64, bn + i * 64,
                                         Wem + i * 5120, out, last, !last, n);
        if (!last) {
            k_edge<<<(e + 127) / 128, 128>>>(edgef, (i > 0),
                                             Wem + i * 5120 + 4096, bem + i * 32,
                                             ge + i * 32, be + i * 32,
                                             We + (i + 1) * 128,
                                             src, dst, e, (i == 0) ? 1 : 0);
        }
    }
}

// round 8
// speedup vs baseline: 1.0374x; 1.0374x over previous
#include <cuda_runtime.h>

#define NMAX 50000
#define EMAX 1600000

// ---------------- static device scratch ----------------
__device__ int   g_cnt[NMAX];          // zero at load; re-zeroed by scan each run
__device__ int   g_off[NMAX + 1];
__device__ int   g_cur[NMAX];
__device__ int   g_epk[EMAX];          // src node per CSR slot
__device__ int   g_slot[EMAX];         // edge id -> CSR slot
__device__ float g_q[NMAX * 64];
__device__ float g_k[NMAX * 64];
__device__ float g_v[NMAX * 64];
__device__ float g_agg[NMAX * 64];
__device__ float g_h[NMAX * 64];
__device__ float g_A[NMAX * 32];
__device__ float g_B[NMAX * 32];
__device__ float g_e[EMAX * 32];
__device__ float g_bias[EMAX * 4];     // score bias in CSR-slot order

// ---------------- f32x2 packed helpers (sm_103a FFMA2 path) ----------------
__device__ __forceinline__ unsigned long long pk2(float a, float b) {
    unsigned long long r;
    asm("mov.b64 %0, {%1, %2};" : "=l"(r) : "f"(a), "f"(b));
    return r;
}
__device__ __forceinline__ void upk2(unsigned long long v, float& a, float& b) {
    asm("mov.b64 {%0, %1}, %2;" : "=f"(a), "=f"(b) : "l"(v));
}
__device__ __forceinline__ unsigned long long fma2(unsigned long long a,
                                                   unsigned long long b,
                                                   unsigned long long c) {
    unsigned long long d;
    asm("fma.rn.f32x2 %0, %1, %2, %3;" : "=l"(d) : "l"(a), "l"(b), "l"(c));
    return d;
}

// ---------------- count ----------------
__global__ void k_count(const int* __restrict__ dst, int e) {
    int i = blockIdx.x * blockDim.x + threadIdx.x;
    if (i < e) atomicAdd(&g_cnt[dst[i]], 1);
}

// ---------------- fused: block0 = exclusive scan (+re-zero cnt), rest = qkv proj ----------------
__global__ void k_scanproj(int n, const float* __restrict__ hin, int useG,
                           const float* __restrict__ Wq, const float* __restrict__ Wk,
                           const float* __restrict__ Wv, int withScan) {
    __shared__ float sq[4096], sk[4096], sv[4096];
    __shared__ int swi[32];
    int t = threadIdx.x;
    if (withScan && blockIdx.x == 0) {
        int lane = t & 31, w = t >> 5;
        int carry = 0;
        for (int base = 0; base < n; base += 1024) {
            int i = base + t;
            int v = (i < n) ? g_cnt[i] : 0;
            if (i < n) g_cnt[i] = 0;              // reset for next run
            int x = v;
#pragma unroll
            for (int o = 1; o < 32; o <<= 1) {
                int y = __shfl_up_sync(0xffffffffu, x, o);
                if (lane >= o) x += y;
            }
            if (lane == 31) swi[w] = x;
            __syncthreads();
            if (t < 32) {
                int s = swi[t];
#pragma unroll
                for (int o = 1; o < 32; o <<= 1) {
                    int y = __shfl_up_sync(0xffffffffu, s, o);
                    if (t >= o) s += y;
                }
                swi[t] = s;
            }
            __syncthreads();
            int pref = (w > 0) ? swi[w - 1] : 0;
            int excl = carry + pref + x - v;
            if (i < n) { g_off[i] = excl; g_cur[i] = excl; }
            carry += swi[31];
            __syncthreads();
        }
        if (t == 0) g_off[n] = carry;
        return;
    }
    int bp = blockIdx.x - withScan;
    for (int i = t; i < 4096; i += 1024) { sq[i] = Wq[i]; sk[i] = Wk[i]; sv[i] = Wv[i]; }
    __syncthreads();
    const float* h = useG ? g_h : hin;
    int lane = t & 31, w = t >> 5;
    int r0 = (bp * 32 + w) * 4;
    float h0[4], h1[4];
#pragma unroll
    for (int r = 0; r < 4; r++) {
        int row = r0 + r;
        h0[r] = (row < n) ? h[row * 64 + lane] : 0.f;
        h1[r] = (row < n) ? h[row * 64 + lane + 32] : 0.f;
    }
    float aq0[4] = {0,0,0,0}, aq1[4] = {0,0,0,0};
    float ak0[4] = {0,0,0,0}, ak1[4] = {0,0,0,0};
    float av0[4] = {0,0,0,0}, av1[4] = {0,0,0,0};
#pragma unroll
    for (int j = 0; j < 32; j++) {
        float wq0 = sq[j * 64 + lane], wq1 = sq[j * 64 + lane + 32];
        float wk0 = sk[j * 64 + lane], wk1 = sk[j * 64 + lane + 32];
        float wv0 = sv[j * 64 + lane], wv1 = sv[j * 64 + lane + 32];
#pragma unroll
        for (int r = 0; r < 4; r++) {
            float hj = __shfl_sync(0xffffffffu, h0[r], j);
            aq0[r] += hj * wq0; aq1[r] += hj * wq1;
            ak0[r] += hj * wk0; ak1[r] += hj * wk1;
            av0[r] += hj * wv0; av1[r] += hj * wv1;
        }
    }
#pragma unroll
    for (int j = 0; j < 32; j++) {
        float wq0 = sq[(j + 32) * 64 + lane], wq1 = sq[(j + 32) * 64 + lane + 32];
        float wk0 = sk[(j + 32) * 64 + lane], wk1 = sk[(j + 32) * 64 + lane + 32];
        float wv0 = sv[(j + 32) * 64 + lane], wv1 = sv[(j + 32) * 64 + lane + 32];
#pragma unroll
        for (int r = 0; r < 4; r++) {
            float hj = __shfl_sync(0xffffffffu, h1[r], j);
            aq0[r] += hj * wq0; aq1[r] += hj * wq1;
            ak0[r] += hj * wk0; ak1[r] += hj * wk1;
            av0[r] += hj * wv0; av1[r] += hj * wv1;
        }
    }
#pragma unroll
    for (int r = 0; r < 4; r++) {
        int row = r0 + r;
        if (row >= n) break;
        g_q[row * 64 + lane] = aq0[r]; g_q[row * 64 + lane + 32] = aq1[r];
        g_k[row * 64 + lane] = ak0[r]; g_k[row * 64 + lane + 32] = ak1[r];
        g_v[row * 64 + lane] = av0[r]; g_v[row * 64 + lane + 32] = av1[r];
    }
}

// ---------------- fused scatter + layer-0 bias ----------------
__global__ void k_scatbias(const int* __restrict__ src, const int* __restrict__ dstp,
                           const float* __restrict__ ef, const float* __restrict__ We, int e) {
    __shared__ float sW[128];
    __shared__ float buf[4][32 * 33];
    int t = threadIdx.x;
    if (t < 128) sW[t] = We[t];
    __syncthreads();
    int w = t >> 5, lane = t & 31;
    int base = (blockIdx.x * 4 + w) * 32;
    float* b = buf[w];
    int ed0 = base + lane;
    int slot = -1;
    if (ed0 < e) {
        int d = __ldg(dstp + ed0);
        slot = atomicAdd(&g_cur[d], 1);
        g_epk[slot] = __ldg(src + ed0);
        g_slot[ed0] = slot;
    }
#pragma unroll 4
    for (int j = 0; j < 32; j++) {
        int ed = base + j;
        b[j * 33 + lane] = (ed < e) ? __ldg(ef + (size_t)ed * 32 + lane) : 0.f;
    }
    __syncwarp();
    if (ed0 >= e) return;
    float4 bb = make_float4(0.f, 0.f, 0.f, 0.f);
#pragma unroll
    for (int k = 0; k < 32; k++) {
        float ek = b[lane * 33 + k];
        float4 wv = *(const float4*)(sW + k * 4);
        bb.x += ek * wv.x; bb.y += ek * wv.y; bb.z += ek * wv.z; bb.w += ek * wv.w;
    }
    ((float4*)g_bias)[slot] = bb;
}

// ---------------- attention: warp/node, unroll-4, pure-memory kernel ----------------
__global__ void k_attn(int n) {
    int lane = threadIdx.x & 31;
    int node = blockIdx.x * 8 + (threadIdx.x >> 5);
    if (node >= n) return;
    int half = lane >> 4;
    int sub = lane & 15;
    int head = sub >> 2;
    int beg = g_off[node], end = g_off[node + 1];
    if (beg >= end) {
        if (half == 0)
            *(float4*)(g_agg + (size_t)node * 64 + sub * 4) = make_float4(0.f, 0.f, 0.f, 0.f);
        return;
    }
    float4 q4 = *(const float4*)(g_q + (size_t)node * 64 + sub * 4);
    q4.x *= 0.25f; q4.y *= 0.25f; q4.z *= 0.25f; q4.w *= 0.25f;
    float4 acc = make_float4(0.f, 0.f, 0.f, 0.f);
    float d = 0.f;
    for (int p = beg; p < end; p += 4) {
        int i0 = p + half;
        int i1 = p + 2 + half;
        bool u0 = (i0 < end), u1 = (i1 < end);
        int e0 = u0 ? i0 : beg;          // clamped reads stay in-bounds
        int e1 = u1 ? i1 : beg;
        int s0 = __ldg(&g_epk[e0]);
        int s1 = __ldg(&g_epk[e1]);
        float4 k0 = __ldg((const float4*)(g_k + (size_t)s0 * 64) + sub);
        float4 k1 = __ldg((const float4*)(g_k + (size_t)s1 * 64) + sub);
        float4 w0 = __ldg((const float4*)(g_v + (size_t)s0 * 64) + sub);
        float4 w1 = __ldg((const float4*)(g_v + (size_t)s1 * 64) + sub);
        float b0 = __ldg(g_bias + (size_t)e0 * 4 + head);
        float b1 = __ldg(g_bias + (size_t)e1 * 4 + head);
        float dt0 = q4.x * k0.x + q4.y * k0.y + q4.z * k0.z + q4.w * k0.w;
        float dt1 = q4.x * k1.x + q4.y * k1.y + q4.z * k1.z + q4.w * k1.w;
        dt0 += __shfl_xor_sync(0xffffffffu, dt0, 1);
        dt1 += __shfl_xor_sync(0xffffffffu, dt1, 1);
        dt0 += __shfl_xor_sync(0xffffffffu, dt0, 2);
        dt1 += __shfl_xor_sync(0xffffffffu, dt1, 2);
        float ex0 = u0 ? __expf(dt0 + b0) : 0.f;
        float ex1 = u1 ? __expf(dt1 + b1) : 0.f;
        d += ex0; d += ex1;
        acc.x += ex0 * w0.x; acc.y += ex0 * w0.y; acc.z += ex0 * w0.z; acc.w += ex0 * w0.w;
        acc.x += ex1 * w1.x; acc.y += ex1 * w1.y; acc.z += ex1 * w1.z; acc.w += ex1 * w1.w;
    }
    acc.x += __shfl_xor_sync(0xffffffffu, acc.x, 16);
    acc.y += __shfl_xor_sync(0xffffffffu, acc.y, 16);
    acc.z += __shfl_xor_sync(0xffffffffu, acc.z, 16);
    acc.w += __shfl_xor_sync(0xffffffffu, acc.w, 16);
    d     += __shfl_xor_sync(0xffffffffu, d, 16);
    if (half == 0) {
        float inv = 1.f / (d + 1e-9f);
        float4 o;
        o.x = acc.x * inv; o.y = acc.y * inv;
        o.z = acc.z * inv; o.w = acc.w * inv;
        *(float4*)(g_agg + (size_t)node * 64 + sub * 4) = o;
    }
}

// ---------------- node update (512 thr): h = LN(h + agg@Wo); fused A,B ----------------
__global__ void __launch_bounds__(512)
k_lnnode(const float* __restrict__ hin, int useGin,
         const float* __restrict__ Wo, const float* __restrict__ gn,
         const float* __restrict__ bn, const float* __restrict__ Wab,
         float* __restrict__ outp, int useOut, int doAB, int n) {
    __shared__ float sWo[4096];
    __shared__ float sAB[4096];
    for (int i = threadIdx.x; i < 4096; i += 512) {
        sWo[i] = Wo[i];
        if (doAB) sAB[i] = Wab[i];
    }
    __syncthreads();
    int lane = threadIdx.x & 31, w = threadIdx.x >> 5;
    int row = blockIdx.x * 16 + w;
    if (row >= n) return;
    const float* h = useGin ? g_h : hin;
    float a0 = g_agg[row * 64 + lane], a1 = g_agg[row * 64 + lane + 32];
    float o0 = 0.f, o1 = 0.f;
#pragma unroll
    for (int j = 0; j < 32; j++) {
        float aj = __shfl_sync(0xffffffffu, a0, j);
        o0 += aj * sWo[j * 64 + lane];
        o1 += aj * sWo[j * 64 + lane + 32];
    }
#pragma unroll
    for (int j = 0; j < 32; j++) {
        float aj = __shfl_sync(0xffffffffu, a1, j);
        o0 += aj * sWo[(j + 32) * 64 + lane];
        o1 += aj * sWo[(j + 32) * 64 + lane + 32];
    }
    float x0 = h[row * 64 + lane] + o0;
    float x1 = h[row * 64 + lane + 32] + o1;
    float s = x0 + x1;
#pragma unroll
    for (int o = 16; o; o >>= 1) s += __shfl_xor_sync(0xffffffffu, s, o);
    float mu = s * (1.f / 64.f);
    float d0 = x0 - mu, d1 = x1 - mu;
    float vs = d0 * d0 + d1 * d1;
#pragma unroll
    for (int o = 16; o; o >>= 1) vs += __shfl_xor_sync(0xffffffffu, vs, o);
    float inv = rsqrtf(vs * (1.f / 64.f) + 1e-5f);
    float y0 = d0 * inv * __ldg(gn + lane) + __ldg(bn + lane);
    float y1 = d1 * inv * __ldg(gn + lane + 32) + __ldg(bn + lane + 32);
    float* hp = useOut ? outp : g_h;
    hp[row * 64 + lane] = y0;
    hp[row * 64 + lane + 32] = y1;
    if (doAB) {
        float A = 0.f, B = 0.f;
#pragma unroll
        for (int j = 0; j < 32; j++) {
            float yj = __shfl_sync(0xffffffffu, y0, j);
            A += yj * sAB[j * 32 + lane];
            B += yj * sAB[(j + 64) * 32 + lane];
        }
#pragma unroll
        for (int j = 0; j < 32; j++) {
            float yj = __shfl_sync(0xffffffffu, y1, j);
            A += yj * sAB[(j + 32) * 32 + lane];
            B += yj * sAB[(j + 96) * 32 + lane];
        }
        g_A[row * 32 + lane] = A;
        g_B[row * 32 + lane] = B;
    }
}

// ---------------- edge update (single pass, f32x2 GEMM via reinterpreted smem) ----------------
__global__ void k_edge(const float* __restrict__ ein, int useGE,
                       const float* __restrict__ Wem2, const float* __restrict__ bem,
                       const float* __restrict__ ge, const float* __restrict__ be,
                       const float* __restrict__ WeN,
                       const int* __restrict__ src, const int* __restrict__ dstp,
                       int e, int storeE) {
    __shared__ float sW[1024];
    __shared__ float sWeN[128];
    __shared__ float sbem[32], sge[32], sbe[32];
    __shared__ float buf[4][32 * 33];
    int t = threadIdx.x;
    for (int i = t; i < 1024; i += 128) sW[i] = Wem2[i];
    if (t < 128) sWeN[t] = WeN[t];
    if (t < 32) { sbem[t] = bem[t]; sge[t] = ge[t]; sbe[t] = be[t]; }
    __syncthreads();
    int w = t >> 5, lane = t & 31;
    int base = (blockIdx.x * 4 + w) * 32;
    float* b = buf[w];
    const float* ebase = useGE ? (const float*)g_e : ein;

#pragma unroll 4
    for (int j = 0; j < 32; j++) {
        int ed = base + j;
        b[j * 33 + lane] = (ed < e) ? __ldg(ebase + (size_t)ed * 32 + lane) : 0.f;
    }
    __syncwarp();
    float er[32];
#pragma unroll
    for (int k = 0; k < 32; k++) er[k] = b[lane * 33 + k];
    __syncwarp();

    int ed0 = base + lane;
    int s_l = (ed0 < e) ? __ldg(src + ed0)  : 0;
    int d_l = (ed0 < e) ? __ldg(dstp + ed0) : 0;

#pragma unroll 4
    for (int j = 0; j < 32; j++) {
        int sj = __shfl_sync(0xffffffffu, s_l, j);
        b[j * 33 + lane] = __ldg(g_A + (size_t)sj * 32 + lane);
    }
    __syncwarp();
    float acc[32];
#pragma unroll
    for (int k = 0; k < 32; k++) acc[k] = b[lane * 33 + k] + sbem[k];
    __syncwarp();
#pragma unroll 4
    for (int j = 0; j < 32; j++) {
        int dj = __shfl_sync(0xffffffffu, d_l, j);
        b[j * 33 + lane] = __ldg(g_B + (size_t)dj * 32 + lane);
    }
    __syncwarp();
#pragma unroll
    for (int k = 0; k < 32; k++) acc[k] += b[lane * 33 + k];
    __syncwarp();

    // e @ Wem2 on packed f32x2: W pairs read directly as u64 from smem (no repacking)
    unsigned long long acc2[16];
#pragma unroll
    for (int j = 0; j < 16; j++) acc2[j] = pk2(acc[2 * j], acc[2 * j + 1]);
#pragma unroll
    for (int k = 0; k < 32; k++) {
        unsigned long long ek2 = pk2(er[k], er[k]);
        const ulonglong2* wr = (const ulonglong2*)(sW + k * 32);
#pragma unroll
        for (int j = 0; j < 8; j++) {
            ulonglong2 ww = wr[j];
            acc2[2 * j]     = fma2(ek2, ww.x, acc2[2 * j]);
            acc2[2 * j + 1] = fma2(ek2, ww.y, acc2[2 * j + 1]);
        }
    }
#pragma unroll
    for (int j = 0; j < 16; j++) upk2(acc2[j], acc[2 * j], acc[2 * j + 1]);

    float mu = 0.f;
#pragma unroll
    for (int j = 0; j < 32; j++) {
        float u = acc[j];
        float z = 0.7978845608028654f * (u + 0.044715f * u * u * u);
        float th = 1.f - 2.f / (__expf(2.f * z) + 1.f);
        float x = er[j] + 0.5f * u * (1.f + th);
        acc[j] = x;
        mu += x;
    }
    mu *= (1.f / 32.f);
    float var = 0.f;
#pragma unroll
    for (int j = 0; j < 32; j++) { float dx = acc[j] - mu; var += dx * dx; }
    float inv = rsqrtf(var * (1.f / 32.f) + 1e-5f);
    float4 bb = make_float4(0.f, 0.f, 0.f, 0.f);
#pragma unroll
    for (int j = 0; j < 32; j++) {
        float y = (acc[j] - mu) * inv * sge[j] + sbe[j];
        acc[j] = y;
        float4 wv = *(const float4*)(sWeN + j * 4);
        bb.x += y * wv.x; bb.y += y * wv.y; bb.z += y * wv.z; bb.w += y * wv.w;
    }
    if (ed0 < e) {
        int slot = __ldg(g_slot + ed0);
        ((float4*)g_bias)[slot] = bb;
    }
    if (storeE) {
        __syncwarp();
#pragma unroll
        for (int k = 0; k < 32; k++) b[lane * 33 + k] = acc[k];
        __syncwarp();
#pragma unroll 4
        for (int j = 0; j < 32; j++) {
            int ed = base + j;
            if (ed < e) g_e[(size_t)ed * 32 + lane] = b[j * 33 + lane];
        }
    }
}

// ---------------- launch ----------------
extern "C" void kernel_launch(void* const* d_in, const int* in_sizes, int n_in,
                              void* d_out, int out_size) {
    const float* nodef = (const float*)d_in[0];
    const float* edgef = (const float*)d_in[1];
    const int*   ei    = (const int*)d_in[2];
    const float* Wq    = (const float*)d_in[3];
    const float* Wk    = (const float*)d_in[4];
    const float* Wv    = (const float*)d_in[5];
    const float* Wo    = (const float*)d_in[6];
    const float* We    = (const float*)d_in[7];
    const float* Wem   = (const float*)d_in[8];
    const float* bem   = (const float*)d_in[9];
    const float* gn    = (const float*)d_in[10];
    const float* bn    = (const float*)d_in[11];
    const float* ge    = (const float*)d_in[12];
    const float* be    = (const float*)d_in[13];
    float* out = (float*)d_out;

    int n = in_sizes[0] / 64;
    int e = in_sizes[1] / 32;
    const int* src = ei;
    const int* dst = ei + e;
    int projBlocks = (n + 127) / 128;

    // side stream + events for edge/proj overlap (created once; not during capture)
    static cudaStream_t s2 = 0;
    static cudaEvent_t evA = 0, evB = 0;
    static int tried = 0;
    if (!tried) {
        tried = 1;
        if (cudaStreamCreateWithFlags(&s2, cudaStreamNonBlocking) != cudaSuccess) s2 = 0;
        if (cudaEventCreateWithFlags(&evA, cudaEventDisableTiming) != cudaSuccess) evA = 0;
        if (cudaEventCreateWithFlags(&evB, cudaEventDisableTiming) != cudaSuccess) evB = 0;
    }
    bool useS2 = (s2 != 0) && (evA != 0) && (evB != 0);

    // 0: count  1: scan+proj(L0)  2: scatter+bias0  3: attn(L0) <- profiled
    k_count<<<(e + 255) / 256, 256>>>(dst, e);
    k_scanproj<<<projBlocks + 1, 1024>>>(n, nodef, 0, Wq, Wk, Wv, 1);
    k_scatbias<<<(e + 127) / 128, 128>>>(src, dst, edgef, We, e);

    for (int i = 0; i < 3; i++) {
        if (i > 0) {
            k_scanproj<<<projBlocks, 1024>>>(n, nodef, 1,
                                             Wq + i * 4096, Wk + i * 4096, Wv + i * 4096, 0);
            if (useS2) cudaStreamWaitEvent(0, evB, 0);   // join edge(i-1) before attn(i)
        }
        k_attn<<<(n + 7) / 8, 256>>>(n);
        int last = (i == 2);
        k_lnnode<<<(n + 15) / 16, 512>>>(nodef, (i > 0),
                                         Wo + i * 4096, gn + i * 64, bn + i * 64,
                                         Wem + i * 5120, out, last, !last, n);
        if (!last) {
            if (useS2) {
                cudaEventRecord(evA, 0);
                cudaStreamWaitEvent(s2, evA, 0);
                k_edge<<<(e + 127) / 128, 128, 0, s2>>>(edgef, (i > 0),
                                                        Wem + i * 5120 + 4096, bem + i * 32,
                                                        ge + i * 32, be + i * 32,
                                                        We + (i + 1) * 128,
                                                        src, dst, e, (i == 0) ? 1 : 0);
                cudaEventRecord(evB, s2);
            } else {
                k_edge<<<(e + 127) / 128, 128>>>(edgef, (i > 0),
                                                 Wem + i * 5120 + 4096, bem + i * 32,
                                                 ge + i * 32, be + i * 32,
                                                 We + (i + 1) * 128,
                                                 src, dst, e, (i == 0) ? 1 : 0);
            }
        }
    }
}

// round 9
// speedup vs baseline: 1.0548x; 1.0168x over previous
#include <cuda_runtime.h>
#include <cuda_fp16.h>

#define NMAX 50000
#define EMAX 1600000

// ---------------- static device scratch ----------------
__device__ int    g_cnt[NMAX];         // zero at load; re-zeroed by scan each run
__device__ int    g_off[NMAX + 1];
__device__ int    g_cur[NMAX];
__device__ int    g_epk[EMAX];         // src node per CSR slot
__device__ int    g_slot[EMAX];        // edge id -> CSR slot
__device__ float  g_q[NMAX * 64];
__device__ __half g_kh[NMAX * 64];     // fp16 k (halves attn L2 traffic)
__device__ __half g_vh[NMAX * 64];     // fp16 v
__device__ float  g_agg[NMAX * 64];
__device__ float  g_h[NMAX * 64];
__device__ float  g_A[NMAX * 32];
__device__ float  g_B[NMAX * 32];
__device__ __half g_eh[EMAX * 32];     // fp16 edge features (in-place per layer)
__device__ float  g_bias[EMAX * 4];    // score bias in CSR-slot order

// ---------------- f32x2 packed helpers (sm_103a FFMA2 path) ----------------
__device__ __forceinline__ unsigned long long pk2(float a, float b) {
    unsigned long long r;
    asm("mov.b64 %0, {%1, %2};" : "=l"(r) : "f"(a), "f"(b));
    return r;
}
__device__ __forceinline__ void upk2(unsigned long long v, float& a, float& b) {
    asm("mov.b64 {%0, %1}, %2;" : "=f"(a), "=f"(b) : "l"(v));
}
__device__ __forceinline__ unsigned long long fma2(unsigned long long a,
                                                   unsigned long long b,
                                                   unsigned long long c) {
    unsigned long long d;
    asm("fma.rn.f32x2 %0, %1, %2, %3;" : "=l"(d) : "l"(a), "l"(b), "l"(c));
    return d;
}

// ---------------- count ----------------
__global__ void k_count(const int* __restrict__ dst, int e) {
    int i = blockIdx.x * blockDim.x + threadIdx.x;
    if (i < e) atomicAdd(&g_cnt[dst[i]], 1);
}

// ---------------- fused: block0 = exclusive scan (+re-zero cnt), rest = qkv proj ----------------
__global__ void k_scanproj(int n, const float* __restrict__ hin, int useG,
                           const float* __restrict__ Wq, const float* __restrict__ Wk,
                           const float* __restrict__ Wv, int withScan) {
    __shared__ float sq[4096], sk[4096], sv[4096];
    __shared__ int swi[32];
    int t = threadIdx.x;
    if (withScan && blockIdx.x == 0) {
        int lane = t & 31, w = t >> 5;
        int carry = 0;
        for (int base = 0; base < n; base += 1024) {
            int i = base + t;
            int v = (i < n) ? g_cnt[i] : 0;
            if (i < n) g_cnt[i] = 0;              // reset for next run
            int x = v;
#pragma unroll
            for (int o = 1; o < 32; o <<= 1) {
                int y = __shfl_up_sync(0xffffffffu, x, o);
                if (lane >= o) x += y;
            }
            if (lane == 31) swi[w] = x;
            __syncthreads();
            if (t < 32) {
                int s = swi[t];
#pragma unroll
                for (int o = 1; o < 32; o <<= 1) {
                    int y = __shfl_up_sync(0xffffffffu, s, o);
                    if (t >= o) s += y;
                }
                swi[t] = s;
            }
            __syncthreads();
            int pref = (w > 0) ? swi[w - 1] : 0;
            int excl = carry + pref + x - v;
            if (i < n) { g_off[i] = excl; g_cur[i] = excl; }
            carry += swi[31];
            __syncthreads();
        }
        if (t == 0) g_off[n] = carry;
        return;
    }
    int bp = blockIdx.x - withScan;
    for (int i = t; i < 4096; i += 1024) { sq[i] = Wq[i]; sk[i] = Wk[i]; sv[i] = Wv[i]; }
    __syncthreads();
    const float* h = useG ? g_h : hin;
    int lane = t & 31, w = t >> 5;
    int r0 = (bp * 32 + w) * 4;
    float h0[4], h1[4];
#pragma unroll
    for (int r = 0; r < 4; r++) {
        int row = r0 + r;
        h0[r] = (row < n) ? h[row * 64 + lane] : 0.f;
        h1[r] = (row < n) ? h[row * 64 + lane + 32] : 0.f;
    }
    float aq0[4] = {0,0,0,0}, aq1[4] = {0,0,0,0};
    float ak0[4] = {0,0,0,0}, ak1[4] = {0,0,0,0};
    float av0[4] = {0,0,0,0}, av1[4] = {0,0,0,0};
#pragma unroll
    for (int j = 0; j < 32; j++) {
        float wq0 = sq[j * 64 + lane], wq1 = sq[j * 64 + lane + 32];
        float wk0 = sk[j * 64 + lane], wk1 = sk[j * 64 + lane + 32];
        float wv0 = sv[j * 64 + lane], wv1 = sv[j * 64 + lane + 32];
#pragma unroll
        for (int r = 0; r < 4; r++) {
            float hj = __shfl_sync(0xffffffffu, h0[r], j);
            aq0[r] += hj * wq0; aq1[r] += hj * wq1;
            ak0[r] += hj * wk0; ak1[r] += hj * wk1;
            av0[r] += hj * wv0; av1[r] += hj * wv1;
        }
    }
#pragma unroll
    for (int j = 0; j < 32; j++) {
        float wq0 = sq[(j + 32) * 64 + lane], wq1 = sq[(j + 32) * 64 + lane + 32];
        float wk0 = sk[(j + 32) * 64 + lane], wk1 = sk[(j + 32) * 64 + lane + 32];
        float wv0 = sv[(j + 32) * 64 + lane], wv1 = sv[(j + 32) * 64 + lane + 32];
#pragma unroll
        for (int r = 0; r < 4; r++) {
            float hj = __shfl_sync(0xffffffffu, h1[r], j);
            aq0[r] += hj * wq0; aq1[r] += hj * wq1;
            ak0[r] += hj * wk0; ak1[r] += hj * wk1;
            av0[r] += hj * wv0; av1[r] += hj * wv1;
        }
    }
#pragma unroll
    for (int r = 0; r < 4; r++) {
        int row = r0 + r;
        if (row >= n) break;
        g_q[row * 64 + lane] = aq0[r]; g_q[row * 64 + lane + 32] = aq1[r];
        g_kh[row * 64 + lane] = __float2half(ak0[r]);
        g_kh[row * 64 + lane + 32] = __float2half(ak1[r]);
        g_vh[row * 64 + lane] = __float2half(av0[r]);
        g_vh[row * 64 + lane + 32] = __float2half(av1[r]);
    }
}

// ---------------- fused scatter + layer-0 bias + fp16 e copy ----------------
__global__ void k_scatbias(const int* __restrict__ src, const int* __restrict__ dstp,
                           const float* __restrict__ ef, const float* __restrict__ We, int e) {
    __shared__ float sW[128];
    __shared__ float buf[4][32 * 33];
    int t = threadIdx.x;
    if (t < 128) sW[t] = We[t];
    __syncthreads();
    int w = t >> 5, lane = t & 31;
    int base = (blockIdx.x * 4 + w) * 32;
    float* b = buf[w];
    int ed0 = base + lane;
    int slot = -1;
    if (ed0 < e) {
        int d = __ldg(dstp + ed0);
        slot = atomicAdd(&g_cur[d], 1);
        g_epk[slot] = __ldg(src + ed0);
        g_slot[ed0] = slot;
    }
#pragma unroll 4
    for (int j = 0; j < 32; j++) {
        int ed = base + j;
        b[j * 33 + lane] = (ed < e) ? __ldg(ef + (size_t)ed * 32 + lane) : 0.f;
    }
    __syncwarp();
    // fp16 copy of e0 (edge layers read this instead of re-streaming edgef)
#pragma unroll 4
    for (int j = 0; j < 32; j++) {
        int ed = base + j;
        if (ed < e) g_eh[(size_t)ed * 32 + lane] = __float2half(b[j * 33 + lane]);
    }
    if (ed0 >= e) return;
    float4 bb = make_float4(0.f, 0.f, 0.f, 0.f);
#pragma unroll
    for (int k = 0; k < 32; k++) {
        float ek = b[lane * 33 + k];
        float4 wv = *(const float4*)(sW + k * 4);
        bb.x += ek * wv.x; bb.y += ek * wv.y; bb.z += ek * wv.z; bb.w += ek * wv.w;
    }
    ((float4*)g_bias)[slot] = bb;
}

// ---------------- attention: warp/node, unroll-4, fp16 k/v ----------------
__global__ void k_attn(int n) {
    int lane = threadIdx.x & 31;
    int node = blockIdx.x * 8 + (threadIdx.x >> 5);
    if (node >= n) return;
    int half = lane >> 4;
    int sub = lane & 15;
    int head = sub >> 2;
    int beg = g_off[node], end = g_off[node + 1];
    if (beg >= end) {
        if (half == 0)
            *(float4*)(g_agg + (size_t)node * 64 + sub * 4) = make_float4(0.f, 0.f, 0.f, 0.f);
        return;
    }
    float4 q4 = *(const float4*)(g_q + (size_t)node * 64 + sub * 4);
    q4.x *= 0.25f; q4.y *= 0.25f; q4.z *= 0.25f; q4.w *= 0.25f;
    float4 acc = make_float4(0.f, 0.f, 0.f, 0.f);
    float d = 0.f;
    for (int p = beg; p < end; p += 4) {
        int i0 = p + half;
        int i1 = p + 2 + half;
        bool u0 = (i0 < end), u1 = (i1 < end);
        int e0 = u0 ? i0 : beg;          // clamped reads stay in-bounds
        int e1 = u1 ? i1 : beg;
        int s0 = __ldg(&g_epk[e0]);
        int s1 = __ldg(&g_epk[e1]);
        uint2 kr0 = __ldg((const uint2*)(g_kh + (size_t)s0 * 64) + sub);
        uint2 kr1 = __ldg((const uint2*)(g_kh + (size_t)s1 * 64) + sub);
        uint2 vr0 = __ldg((const uint2*)(g_vh + (size_t)s0 * 64) + sub);
        uint2 vr1 = __ldg((const uint2*)(g_vh + (size_t)s1 * 64) + sub);
        float b0 = __ldg(g_bias + (size_t)e0 * 4 + head);
        float b1 = __ldg(g_bias + (size_t)e1 * 4 + head);
        float2 k0a = __half22float2(*(__half2*)&kr0.x);
        float2 k0b = __half22float2(*(__half2*)&kr0.y);
        float2 k1a = __half22float2(*(__half2*)&kr1.x);
        float2 k1b = __half22float2(*(__half2*)&kr1.y);
        float dt0 = q4.x * k0a.x + q4.y * k0a.y + q4.z * k0b.x + q4.w * k0b.y;
        float dt1 = q4.x * k1a.x + q4.y * k1a.y + q4.z * k1b.x + q4.w * k1b.y;
        dt0 += __shfl_xor_sync(0xffffffffu, dt0, 1);
        dt1 += __shfl_xor_sync(0xffffffffu, dt1, 1);
        dt0 += __shfl_xor_sync(0xffffffffu, dt0, 2);
        dt1 += __shfl_xor_sync(0xffffffffu, dt1, 2);
        float ex0 = u0 ? __expf(dt0 + b0) : 0.f;
        float ex1 = u1 ? __expf(dt1 + b1) : 0.f;
        d += ex0; d += ex1;
        float2 v0a = __half22float2(*(__half2*)&vr0.x);
        float2 v0b = __half22float2(*(__half2*)&vr0.y);
        float2 v1a = __half22float2(*(__half2*)&vr1.x);
        float2 v1b = __half22float2(*(__half2*)&vr1.y);
        acc.x += ex0 * v0a.x; acc.y += ex0 * v0a.y; acc.z += ex0 * v0b.x; acc.w += ex0 * v0b.y;
        acc.x += ex1 * v1a.x; acc.y += ex1 * v1a.y; acc.z += ex1 * v1b.x; acc.w += ex1 * v1b.y;
    }
    acc.x += __shfl_xor_sync(0xffffffffu, acc.x, 16);
    acc.y += __shfl_xor_sync(0xffffffffu, acc.y, 16);
    acc.z += __shfl_xor_sync(0xffffffffu, acc.z, 16);
    acc.w += __shfl_xor_sync(0xffffffffu, acc.w, 16);
    d     += __shfl_xor_sync(0xffffffffu, d, 16);
    if (half == 0) {
        float inv = 1.f / (d + 1e-9f);
        float4 o;
        o.x = acc.x * inv; o.y = acc.y * inv;
        o.z = acc.z * inv; o.w = acc.w * inv;
        *(float4*)(g_agg + (size_t)node * 64 + sub * 4) = o;
    }
}

// ---------------- node update (512 thr): h = LN(h + agg@Wo); fused A,B ----------------
__global__ void __launch_bounds__(512)
k_lnnode(const float* __restrict__ hin, int useGin,
         const float* __restrict__ Wo, const float* __restrict__ gn,
         const float* __restrict__ bn, const float* __restrict__ Wab,
         float* __restrict__ outp, int useOut, int doAB, int n) {
    __shared__ float sWo[4096];
    __shared__ float sAB[4096];
    for (int i = threadIdx.x; i < 4096; i += 512) {
        sWo[i] = Wo[i];
        if (doAB) sAB[i] = Wab[i];
    }
    __syncthreads();
    int lane = threadIdx.x & 31, w = threadIdx.x >> 5;
    int row = blockIdx.x * 16 + w;
    if (row >= n) return;
    const float* h = useGin ? g_h : hin;
    float a0 = g_agg[row * 64 + lane], a1 = g_agg[row * 64 + lane + 32];
    float o0 = 0.f, o1 = 0.f;
#pragma unroll
    for (int j = 0; j < 32; j++) {
        float aj = __shfl_sync(0xffffffffu, a0, j);
        o0 += aj * sWo[j * 64 + lane];
        o1 += aj * sWo[j * 64 + lane + 32];
    }
#pragma unroll
    for (int j = 0; j < 32; j++) {
        float aj = __shfl_sync(0xffffffffu, a1, j);
        o0 += aj * sWo[(j + 32) * 64 + lane];
        o1 += aj * sWo[(j + 32) * 64 + lane + 32];
    }
    float x0 = h[row * 64 + lane] + o0;
    float x1 = h[row * 64 + lane + 32] + o1;
    float s = x0 + x1;
#pragma unroll
    for (int o = 16; o; o >>= 1) s += __shfl_xor_sync(0xffffffffu, s, o);
    float mu = s * (1.f / 64.f);
    float d0 = x0 - mu, d1 = x1 - mu;
    float vs = d0 * d0 + d1 * d1;
#pragma unroll
    for (int o = 16; o; o >>= 1) vs += __shfl_xor_sync(0xffffffffu, vs, o);
    float inv = rsqrtf(vs * (1.f / 64.f) + 1e-5f);
    float y0 = d0 * inv * __ldg(gn + lane) + __ldg(bn + lane);
    float y1 = d1 * inv * __ldg(gn + lane + 32) + __ldg(bn + lane + 32);
    float* hp = useOut ? outp : g_h;
    hp[row * 64 + lane] = y0;
    hp[row * 64 + lane + 32] = y1;
    if (doAB) {
        float A = 0.f, B = 0.f;
#pragma unroll
        for (int j = 0; j < 32; j++) {
            float yj = __shfl_sync(0xffffffffu, y0, j);
            A += yj * sAB[j * 32 + lane];
            B += yj * sAB[(j + 64) * 32 + lane];
        }
#pragma unroll
        for (int j = 0; j < 32; j++) {
            float yj = __shfl_sync(0xffffffffu, y1, j);
            A += yj * sAB[(j + 32) * 32 + lane];
            B += yj * sAB[(j + 96) * 32 + lane];
        }
        g_A[row * 32 + lane] = A;
        g_B[row * 32 + lane] = B;
    }
}

// ---------------- edge update: reads/writes fp16 g_eh in place, f32x2 GEMM ----------------
__global__ void k_edge(const float* __restrict__ Wem2, const float* __restrict__ bem,
                       const float* __restrict__ ge, const float* __restrict__ be,
                       const float* __restrict__ WeN,
                       const int* __restrict__ src, const int* __restrict__ dstp,
                       int e, int storeE) {
    __shared__ float sW[1024];
    __shared__ float sWeN[128];
    __shared__ float sbem[32], sge[32], sbe[32];
    __shared__ float buf[4][32 * 33];
    int t = threadIdx.x;
    for (int i = t; i < 1024; i += 128) sW[i] = Wem2[i];
    if (t < 128) sWeN[t] = WeN[t];
    if (t < 32) { sbem[t] = bem[t]; sge[t] = ge[t]; sbe[t] = be[t]; }
    __syncthreads();
    int w = t >> 5, lane = t & 31;
    int base = (blockIdx.x * 4 + w) * 32;
    float* b = buf[w];

#pragma unroll 4
    for (int j = 0; j < 32; j++) {
        int ed = base + j;
        b[j * 33 + lane] = (ed < e) ? __half2float(__ldg(g_eh + (size_t)ed * 32 + lane)) : 0.f;
    }
    __syncwarp();
    float er[32];
#pragma unroll
    for (int k = 0; k < 32; k++) er[k] = b[lane * 33 + k];
    __syncwarp();

    int ed0 = base + lane;
    int s_l = (ed0 < e) ? __ldg(src + ed0)  : 0;
    int d_l = (ed0 < e) ? __ldg(dstp + ed0) : 0;

#pragma unroll 4
    for (int j = 0; j < 32; j++) {
        int sj = __shfl_sync(0xffffffffu, s_l, j);
        b[j * 33 + lane] = __ldg(g_A + (size_t)sj * 32 + lane);
    }
    __syncwarp();
    float acc[32];
#pragma unroll
    for (int k = 0; k < 32; k++) acc[k] = b[lane * 33 + k] + sbem[k];
    __syncwarp();
#pragma unroll 4
    for (int j = 0; j < 32; j++) {
        int dj = __shfl_sync(0xffffffffu, d_l, j);
        b[j * 33 + lane] = __ldg(g_B + (size_t)dj * 32 + lane);
    }
    __syncwarp();
#pragma unroll
    for (int k = 0; k < 32; k++) acc[k] += b[lane * 33 + k];
    __syncwarp();

    // e @ Wem2 on packed f32x2: W pairs read directly as u64 from smem (no repacking)
    unsigned long long acc2[16];
#pragma unroll
    for (int j = 0; j < 16; j++) acc2[j] = pk2(acc[2 * j], acc[2 * j + 1]);
#pragma unroll
    for (int k = 0; k < 32; k++) {
        unsigned long long ek2 = pk2(er[k], er[k]);
        const ulonglong2* wr = (const ulonglong2*)(sW + k * 32);
#pragma unroll
        for (int j = 0; j < 8; j++) {
            ulonglong2 ww = wr[j];
            acc2[2 * j]     = fma2(ek2, ww.x, acc2[2 * j]);
            acc2[2 * j + 1] = fma2(ek2, ww.y, acc2[2 * j + 1]);
        }
    }
#pragma unroll
    for (int j = 0; j < 16; j++) upk2(acc2[j], acc[2 * j], acc[2 * j + 1]);

    float mu = 0.f;
#pragma unroll
    for (int j = 0; j < 32; j++) {
        float u = acc[j];
        float z = 0.7978845608028654f * (u + 0.044715f * u * u * u);
        float th = 1.f - 2.f / (__expf(2.f * z) + 1.f);
        float x = er[j] + 0.5f * u * (1.f + th);
        acc[j] = x;
        mu += x;
    }
    mu *= (1.f / 32.f);
    float var = 0.f;
#pragma unroll
    for (int j = 0; j < 32; j++) { float dx = acc[j] - mu; var += dx * dx; }
    float inv = rsqrtf(var * (1.f / 32.f) + 1e-5f);
    float4 bb = make_float4(0.f, 0.f, 0.f, 0.f);
#pragma unroll
    for (int j = 0; j < 32; j++) {
        float y = (acc[j] - mu) * inv * sge[j] + sbe[j];
        acc[j] = y;
        float4 wv = *(const float4*)(sWeN + j * 4);
        bb.x += y * wv.x; bb.y += y * wv.y; bb.z += y * wv.z; bb.w += y * wv.w;
    }
    if (ed0 < e) {
        int slot = __ldg(g_slot + ed0);
        ((float4*)g_bias)[slot] = bb;
    }
    if (storeE) {
        __syncwarp();
#pragma unroll
        for (int k = 0; k < 32; k++) b[lane * 33 + k] = acc[k];
        __syncwarp();
#pragma unroll 4
        for (int j = 0; j < 32; j++) {
            int ed = base + j;
            if (ed < e) g_eh[(size_t)ed * 32 + lane] = __float2half(b[j * 33 + lane]);
        }
    }
}

// ---------------- launch ----------------
extern "C" void kernel_launch(void* const* d_in, const int* in_sizes, int n_in,
                              void* d_out, int out_size) {
    const float* nodef = (const float*)d_in[0];
    const float* edgef = (const float*)d_in[1];
    const int*   ei    = (const int*)d_in[2];
    const float* Wq    = (const float*)d_in[3];
    const float* Wk    = (const float*)d_in[4];
    const float* Wv    = (const float*)d_in[5];
    const float* Wo    = (const float*)d_in[6];
    const float* We    = (const float*)d_in[7];
    const float* Wem   = (const float*)d_in[8];
    const float* bem   = (const float*)d_in[9];
    const float* gn    = (const float*)d_in[10];
    const float* bn    = (const float*)d_in[11];
    const float* ge    = (const float*)d_in[12];
    const float* be    = (const float*)d_in[13];
    float* out = (float*)d_out;

    int n = in_sizes[0] / 64;
    int e = in_sizes[1] / 32;
    const int* src = ei;
    const int* dst = ei + e;
    int projBlocks = (n + 127) / 128;

    // side stream + events for edge/proj overlap (created once; not during capture)
    static cudaStream_t s2 = 0;
    static cudaEvent_t evA = 0, evB = 0;
    static int tried = 0;
    if (!tried) {
        tried = 1;
        if (cudaStreamCreateWithFlags(&s2, cudaStreamNonBlocking) != cudaSuccess) s2 = 0;
        if (cudaEventCreateWithFlags(&evA, cudaEventDisableTiming) != cudaSuccess) evA = 0;
        if (cudaEventCreateWithFlags(&evB, cudaEventDisableTiming) != cudaSuccess) evB = 0;
    }
    bool useS2 = (s2 != 0) && (evA != 0) && (evB != 0);

    // 0: count  1: scan+proj(L0)  2: scatbias  3: attn(L0) <- profiled
    k_count<<<(e + 255) / 256, 256>>>(dst, e);
    k_scanproj<<<projBlocks + 1, 1024>>>(n, nodef, 0, Wq, Wk, Wv, 1);
    k_scatbias<<<(e + 127) / 128, 128>>>(src, dst, edgef, We, e);

    for (int i = 0; i < 3; i++) {
        if (i > 0) {
            k_scanproj<<<projBlocks, 1024>>>(n, nodef, 1,
                                             Wq + i * 4096, Wk + i * 4096, Wv + i * 4096, 0);
            if (useS2) cudaStreamWaitEvent(0, evB, 0);   // join edge(i-1) before attn(i)
        }
        k_attn<<<(n + 7) / 8, 256>>>(n);
        int last = (i == 2);
        k_lnnode<<<(n + 15) / 16, 512>>>(nodef, (i > 0),
                                         Wo + i * 4096, gn + i * 64, bn + i * 64,
                                         Wem + i * 5120, out, last, !last, n);
        if (!last) {
            if (useS2) {
                cudaEventRecord(evA, 0);
                cudaStreamWaitEvent(s2, evA, 0);
                k_edge<<<(e + 127) / 128, 128, 0, s2>>>(Wem + i * 5120 + 4096, bem + i * 32,
                                                        ge + i * 32, be + i * 32,
                                                        We + (i + 1) * 128,
                                                        src, dst, e, (i == 0) ? 1 : 0);
                cudaEventRecord(evB, s2);
            } else {
                k_edge<<<(e + 127) / 128, 128>>>(Wem + i * 5120 + 4096, bem + i * 32,
                                                 ge + i * 32, be + i * 32,
                                                 We + (i + 1) * 128,
                                                 src, dst, e, (i == 0) ? 1 : 0);
            }
        }
    }
}

// round 10
// speedup vs baseline: 1.3149x; 1.2466x over previous
#include <cuda_runtime.h>
#include <cuda_fp16.h>

#define NMAX 50000
#define EMAX 1600000

// ---------------- static device scratch ----------------
__device__ int    g_cnt[NMAX];         // zero at load; re-zeroed by scan each run
__device__ int    g_off[NMAX + 1];
__device__ int    g_cur[NMAX];
__device__ int    g_epk[EMAX];         // src node per CSR slot
__device__ int    g_slot[EMAX];        // edge id -> CSR slot
__device__ float  g_q[NMAX * 64];
__device__ __half g_kh[NMAX * 64];     // fp16 k
__device__ __half g_vh[NMAX * 64];     // fp16 v
__device__ float  g_agg[NMAX * 64];
__device__ float  g_h[NMAX * 64];
__device__ float  g_A[NMAX * 32];
__device__ float  g_B[NMAX * 32];
__device__ __half g_eh[EMAX * 32];     // fp16 edge features (in-place per layer)
__device__ float  g_bias[EMAX * 4];    // score bias in CSR-slot order

// ---------------- f32x2 packed helpers (sm_103a FFMA2 path) ----------------
__device__ __forceinline__ unsigned long long pk2(float a, float b) {
    unsigned long long r;
    asm("mov.b64 %0, {%1, %2};" : "=l"(r) : "f"(a), "f"(b));
    return r;
}
__device__ __forceinline__ void upk2(unsigned long long v, float& a, float& b) {
    asm("mov.b64 {%0, %1}, %2;" : "=f"(a), "=f"(b) : "l"(v));
}
__device__ __forceinline__ unsigned long long fma2(unsigned long long a,
                                                   unsigned long long b,
                                                   unsigned long long c) {
    unsigned long long d;
    asm("fma.rn.f32x2 %0, %1, %2, %3;" : "=l"(d) : "l"(a), "l"(b), "l"(c));
    return d;
}
__device__ __forceinline__ float tanh_approx(float x) {
    float y;
    asm("tanh.approx.f32 %0, %1;" : "=f"(y) : "f"(x));
    return y;
}

// ---------------- count ----------------
__global__ void k_count(const int* __restrict__ dst, int e) {
    int i = blockIdx.x * blockDim.x + threadIdx.x;
    if (i < e) atomicAdd(&g_cnt[dst[i]], 1);
}

// ---------------- fused: block0 = exclusive scan (+re-zero cnt), rest = qkv proj ----------------
__global__ void k_scanproj(int n, const float* __restrict__ hin, int useG,
                           const float* __restrict__ Wq, const float* __restrict__ Wk,
                           const float* __restrict__ Wv, int withScan) {
    __shared__ float sq[4096], sk[4096], sv[4096];
    __shared__ int swi[32];
    int t = threadIdx.x;
    if (withScan && blockIdx.x == 0) {
        int lane = t & 31, w = t >> 5;
        int carry = 0;
        for (int base = 0; base < n; base += 1024) {
            int i = base + t;
            int v = (i < n) ? g_cnt[i] : 0;
            if (i < n) g_cnt[i] = 0;              // reset for next run
            int x = v;
#pragma unroll
            for (int o = 1; o < 32; o <<= 1) {
                int y = __shfl_up_sync(0xffffffffu, x, o);
                if (lane >= o) x += y;
            }
            if (lane == 31) swi[w] = x;
            __syncthreads();
            if (t < 32) {
                int s = swi[t];
#pragma unroll
                for (int o = 1; o < 32; o <<= 1) {
                    int y = __shfl_up_sync(0xffffffffu, s, o);
                    if (t >= o) s += y;
                }
                swi[t] = s;
            }
            __syncthreads();
            int pref = (w > 0) ? swi[w - 1] : 0;
            int excl = carry + pref + x - v;
            if (i < n) { g_off[i] = excl; g_cur[i] = excl; }
            carry += swi[31];
            __syncthreads();
        }
        if (t == 0) g_off[n] = carry;
        return;
    }
    int bp = blockIdx.x - withScan;
    for (int i = t; i < 4096; i += 1024) { sq[i] = Wq[i]; sk[i] = Wk[i]; sv[i] = Wv[i]; }
    __syncthreads();
    const float* h = useG ? g_h : hin;
    int lane = t & 31, w = t >> 5;
    int r0 = (bp * 32 + w) * 4;
    float h0[4], h1[4];
#pragma unroll
    for (int r = 0; r < 4; r++) {
        int row = r0 + r;
        h0[r] = (row < n) ? h[row * 64 + lane] : 0.f;
        h1[r] = (row < n) ? h[row * 64 + lane + 32] : 0.f;
    }
    float aq0[4] = {0,0,0,0}, aq1[4] = {0,0,0,0};
    float ak0[4] = {0,0,0,0}, ak1[4] = {0,0,0,0};
    float av0[4] = {0,0,0,0}, av1[4] = {0,0,0,0};
#pragma unroll
    for (int j = 0; j < 32; j++) {
        float wq0 = sq[j * 64 + lane], wq1 = sq[j * 64 + lane + 32];
        float wk0 = sk[j * 64 + lane], wk1 = sk[j * 64 + lane + 32];
        float wv0 = sv[j * 64 + lane], wv1 = sv[j * 64 + lane + 32];
#pragma unroll
        for (int r = 0; r < 4; r++) {
            float hj = __shfl_sync(0xffffffffu, h0[r], j);
            aq0[r] += hj * wq0; aq1[r] += hj * wq1;
            ak0[r] += hj * wk0; ak1[r] += hj * wk1;
            av0[r] += hj * wv0; av1[r] += hj * wv1;
        }
    }
#pragma unroll
    for (int j = 0; j < 32; j++) {
        float wq0 = sq[(j + 32) * 64 + lane], wq1 = sq[(j + 32) * 64 + lane + 32];
        float wk0 = sk[(j + 32) * 64 + lane], wk1 = sk[(j + 32) * 64 + lane + 32];
        float wv0 = sv[(j + 32) * 64 + lane], wv1 = sv[(j + 32) * 64 + lane + 32];
#pragma unroll
        for (int r = 0; r < 4; r++) {
            float hj = __shfl_sync(0xffffffffu, h1[r], j);
            aq0[r] += hj * wq0; aq1[r] += hj * wq1;
            ak0[r] += hj * wk0; ak1[r] += hj * wk1;
            av0[r] += hj * wv0; av1[r] += hj * wv1;
        }
    }
#pragma unroll
    for (int r = 0; r < 4; r++) {
        int row = r0 + r;
        if (row >= n) break;
        g_q[row * 64 + lane] = aq0[r]; g_q[row * 64 + lane + 32] = aq1[r];
        g_kh[row * 64 + lane] = __float2half(ak0[r]);
        g_kh[row * 64 + lane + 32] = __float2half(ak1[r]);
        g_vh[row * 64 + lane] = __float2half(av0[r]);
        g_vh[row * 64 + lane + 32] = __float2half(av1[r]);
    }
}

// ---------------- fused scatter + layer-0 bias + fp16 e copy ----------------
__global__ void k_scatbias(const int* __restrict__ src, const int* __restrict__ dstp,
                           const float* __restrict__ ef, const float* __restrict__ We, int e) {
    __shared__ float sW[128];
    __shared__ float buf[4][32 * 33];
    int t = threadIdx.x;
    if (t < 128) sW[t] = We[t];
    __syncthreads();
    int w = t >> 5, lane = t & 31;
    int base = (blockIdx.x * 4 + w) * 32;
    float* b = buf[w];
    int ed0 = base + lane;
    int slot = -1;
    if (ed0 < e) {
        int d = __ldg(dstp + ed0);
        slot = atomicAdd(&g_cur[d], 1);
        g_epk[slot] = __ldg(src + ed0);
        g_slot[ed0] = slot;
    }
#pragma unroll 4
    for (int j = 0; j < 32; j++) {
        int ed = base + j;
        b[j * 33 + lane] = (ed < e) ? __ldg(ef + (size_t)ed * 32 + lane) : 0.f;
    }
    __syncwarp();
    // fp16 copy of e0 (edge layers read this instead of re-streaming edgef)
#pragma unroll 4
    for (int j = 0; j < 32; j++) {
        int ed = base + j;
        if (ed < e) g_eh[(size_t)ed * 32 + lane] = __float2half(b[j * 33 + lane]);
    }
    if (ed0 >= e) return;
    float4 bb = make_float4(0.f, 0.f, 0.f, 0.f);
#pragma unroll
    for (int k = 0; k < 32; k++) {
        float ek = b[lane * 33 + k];
        float4 wv = *(const float4*)(sW + k * 4);
        bb.x += ek * wv.x; bb.y += ek * wv.y; bb.z += ek * wv.z; bb.w += ek * wv.w;
    }
    ((float4*)g_bias)[slot] = bb;
}

// ---------------- attention: warp/node, unroll-4, fp16 k/v ----------------
__global__ void k_attn(int n) {
    int lane = threadIdx.x & 31;
    int node = blockIdx.x * 8 + (threadIdx.x >> 5);
    if (node >= n) return;
    int half = lane >> 4;
    int sub = lane & 15;
    int head = sub >> 2;
    int beg = g_off[node], end = g_off[node + 1];
    if (beg >= end) {
        if (half == 0)
            *(float4*)(g_agg + (size_t)node * 64 + sub * 4) = make_float4(0.f, 0.f, 0.f, 0.f);
        return;
    }
    float4 q4 = *(const float4*)(g_q + (size_t)node * 64 + sub * 4);
    q4.x *= 0.25f; q4.y *= 0.25f; q4.z *= 0.25f; q4.w *= 0.25f;
    float4 acc = make_float4(0.f, 0.f, 0.f, 0.f);
    float d = 0.f;
    for (int p = beg; p < end; p += 4) {
        int i0 = p + half;
        int i1 = p + 2 + half;
        bool u0 = (i0 < end), u1 = (i1 < end);
        int e0 = u0 ? i0 : beg;          // clamped reads stay in-bounds
        int e1 = u1 ? i1 : beg;
        int s0 = __ldg(&g_epk[e0]);
        int s1 = __ldg(&g_epk[e1]);
        uint2 kr0 = __ldg((const uint2*)(g_kh + (size_t)s0 * 64) + sub);
        uint2 kr1 = __ldg((const uint2*)(g_kh + (size_t)s1 * 64) + sub);
        uint2 vr0 = __ldg((const uint2*)(g_vh + (size_t)s0 * 64) + sub);
        uint2 vr1 = __ldg((const uint2*)(g_vh + (size_t)s1 * 64) + sub);
        float b0 = __ldg(g_bias + (size_t)e0 * 4 + head);
        float b1 = __ldg(g_bias + (size_t)e1 * 4 + head);
        float2 k0a = __half22float2(*(__half2*)&kr0.x);
        float2 k0b = __half22float2(*(__half2*)&kr0.y);
        float2 k1a = __half22float2(*(__half2*)&kr1.x);
        float2 k1b = __half22float2(*(__half2*)&kr1.y);
        float dt0 = q4.x * k0a.x + q4.y * k0a.y + q4.z * k0b.x + q4.w * k0b.y;
        float dt1 = q4.x * k1a.x + q4.y * k1a.y + q4.z * k1b.x + q4.w * k1b.y;
        dt0 += __shfl_xor_sync(0xffffffffu, dt0, 1);
        dt1 += __shfl_xor_sync(0xffffffffu, dt1, 1);
        dt0 += __shfl_xor_sync(0xffffffffu, dt0, 2);
        dt1 += __shfl_xor_sync(0xffffffffu, dt1, 2);
        float ex0 = u0 ? __expf(dt0 + b0) : 0.f;
        float ex1 = u1 ? __expf(dt1 + b1) : 0.f;
        d += ex0; d += ex1;
        float2 v0a = __half22float2(*(__half2*)&vr0.x);
        float2 v0b = __half22float2(*(__half2*)&vr0.y);
        float2 v1a = __half22float2(*(__half2*)&vr1.x);
        float2 v1b = __half22float2(*(__half2*)&vr1.y);
        acc.x += ex0 * v0a.x; acc.y += ex0 * v0a.y; acc.z += ex0 * v0b.x; acc.w += ex0 * v0b.y;
        acc.x += ex1 * v1a.x; acc.y += ex1 * v1a.y; acc.z += ex1 * v1b.x; acc.w += ex1 * v1b.y;
    }
    acc.x += __shfl_xor_sync(0xffffffffu, acc.x, 16);
    acc.y += __shfl_xor_sync(0xffffffffu, acc.y, 16);
    acc.z += __shfl_xor_sync(0xffffffffu, acc.z, 16);
    acc.w += __shfl_xor_sync(0xffffffffu, acc.w, 16);
    d     += __shfl_xor_sync(0xffffffffu, d, 16);
    if (half == 0) {
        float inv = 1.f / (d + 1e-9f);
        float4 o;
        o.x = acc.x * inv; o.y = acc.y * inv;
        o.z = acc.z * inv; o.w = acc.w * inv;
        *(float4*)(g_agg + (size_t)node * 64 + sub * 4) = o;
    }
}

// ---------------- node update (512 thr): h = LN(h + agg@Wo); fused A,B ----------------
__global__ void __launch_bounds__(512)
k_lnnode(const float* __restrict__ hin, int useGin,
         const float* __restrict__ Wo, const float* __restrict__ gn,
         const float* __restrict__ bn, const float* __restrict__ Wab,
         float* __restrict__ outp, int useOut, int doAB, int n) {
    __shared__ float sWo[4096];
    __shared__ float sAB[4096];
    for (int i = threadIdx.x; i < 4096; i += 512) {
        sWo[i] = Wo[i];
        if (doAB) sAB[i] = Wab[i];
    }
    __syncthreads();
    int lane = threadIdx.x & 31, w = threadIdx.x >> 5;
    int row = blockIdx.x * 16 + w;
    if (row >= n) return;
    const float* h = useGin ? g_h : hin;
    float a0 = g_agg[row * 64 + lane], a1 = g_agg[row * 64 + lane + 32];
    float o0 = 0.f, o1 = 0.f;
#pragma unroll
    for (int j = 0; j < 32; j++) {
        float aj = __shfl_sync(0xffffffffu, a0, j);
        o0 += aj * sWo[j * 64 + lane];
        o1 += aj * sWo[j * 64 + lane + 32];
    }
#pragma unroll
    for (int j = 0; j < 32; j++) {
        float aj = __shfl_sync(0xffffffffu, a1, j);
        o0 += aj * sWo[(j + 32) * 64 + lane];
        o1 += aj * sWo[(j + 32) * 64 + lane + 32];
    }
    float x0 = h[row * 64 + lane] + o0;
    float x1 = h[row * 64 + lane + 32] + o1;
    float s = x0 + x1;
#pragma unroll
    for (int o = 16; o; o >>= 1) s += __shfl_xor_sync(0xffffffffu, s, o);
    float mu = s * (1.f / 64.f);
    float d0 = x0 - mu, d1 = x1 - mu;
    float vs = d0 * d0 + d1 * d1;
#pragma unroll
    for (int o = 16; o; o >>= 1) vs += __shfl_xor_sync(0xffffffffu, vs, o);
    float inv = rsqrtf(vs * (1.f / 64.f) + 1e-5f);
    float y0 = d0 * inv * __ldg(gn + lane) + __ldg(bn + lane);
    float y1 = d1 * inv * __ldg(gn + lane + 32) + __ldg(bn + lane + 32);
    float* hp = useOut ? outp : g_h;
    hp[row * 64 + lane] = y0;
    hp[row * 64 + lane + 32] = y1;
    if (doAB) {
        float A = 0.f, B = 0.f;
#pragma unroll
        for (int j = 0; j < 32; j++) {
            float yj = __shfl_sync(0xffffffffu, y0, j);
            A += yj * sAB[j * 32 + lane];
            B += yj * sAB[(j + 64) * 32 + lane];
        }
#pragma unroll
        for (int j = 0; j < 32; j++) {
            float yj = __shfl_sync(0xffffffffu, y1, j);
            A += yj * sAB[(j + 32) * 32 + lane];
            B += yj * sAB[(j + 96) * 32 + lane];
        }
        g_A[row * 32 + lane] = A;
        g_B[row * 32 + lane] = B;
    }
}

// ---------------- edge update: high-MLP staging, vectorized fp16 I/O, f32x2 GEMM ----------------
__global__ void __launch_bounds__(128)
k_edge(const float* __restrict__ Wem2, const float* __restrict__ bem,
       const float* __restrict__ ge, const float* __restrict__ be,
       const float* __restrict__ WeN,
       const int* __restrict__ src, const int* __restrict__ dstp,
       int e, int storeE) {
    __shared__ float sW[1024];
    __shared__ float sWeN[128];
    __shared__ float sbem[32], sge[32], sbe[32];
    __shared__ float bufA[4][32 * 33];
    __shared__ float bufB[4][32 * 33];
    __shared__ uint2 bufH[4][32 * 9];
    int t = threadIdx.x;
    for (int i = t; i < 1024; i += 128) sW[i] = Wem2[i];
    if (t < 128) sWeN[t] = WeN[t];
    if (t < 32) { sbem[t] = bem[t]; sge[t] = ge[t]; sbe[t] = be[t]; }
    __syncthreads();
    int w = t >> 5, lane = t & 31;
    int base = (blockIdx.x * 4 + w) * 32;
    float* bA = bufA[w];
    float* bB = bufB[w];
    uint2* bH = bufH[w];

    // ---- stage e rows: 8 x LDG.64 per warp (4 halves/lane) ----
    int lrow = lane >> 3, lidx = lane & 7;
#pragma unroll
    for (int j = 0; j < 8; j++) {
        int r = j * 4 + lrow;
        int ed = base + r;
        uint2 v = make_uint2(0u, 0u);
        if (ed < e) v = __ldg((const uint2*)(g_eh + (size_t)ed * 32) + lidx);
        bH[r * 9 + lidx] = v;
    }
    __syncwarp();
    float er[32];
#pragma unroll
    for (int k = 0; k < 8; k++) {
        uint2 v = bH[lane * 9 + k];
        float2 f0 = __half22float2(*(__half2*)&v.x);
        float2 f1 = __half22float2(*(__half2*)&v.y);
        er[k * 4 + 0] = f0.x; er[k * 4 + 1] = f0.y;
        er[k * 4 + 2] = f1.x; er[k * 4 + 3] = f1.y;
    }

    int ed0 = base + lane;
    int s_l = (ed0 < e) ? __ldg(src + ed0)  : 0;
    int d_l = (ed0 < e) ? __ldg(dstp + ed0) : 0;

    // ---- stage A[src] and B[dst] interleaved (16 outstanding LDGs) ----
#pragma unroll 8
    for (int j = 0; j < 32; j++) {
        int sj = __shfl_sync(0xffffffffu, s_l, j);
        int dj = __shfl_sync(0xffffffffu, d_l, j);
        bA[j * 33 + lane] = __ldg(g_A + (size_t)sj * 32 + lane);
        bB[j * 33 + lane] = __ldg(g_B + (size_t)dj * 32 + lane);
    }
    __syncwarp();
    float acc[32];
#pragma unroll
    for (int k = 0; k < 32; k++) acc[k] = bA[lane * 33 + k] + bB[lane * 33 + k] + sbem[k];

    // ---- e @ Wem2 on packed f32x2 (W pairs read as u64 from smem) ----
    unsigned long long acc2[16];
#pragma unroll
    for (int j = 0; j < 16; j++) acc2[j] = pk2(acc[2 * j], acc[2 * j + 1]);
#pragma unroll
    for (int k = 0; k < 32; k++) {
        unsigned long long ek2 = pk2(er[k], er[k]);
        const ulonglong2* wr = (const ulonglong2*)(sW + k * 32);
#pragma unroll
        for (int j = 0; j < 8; j++) {
            ulonglong2 ww = wr[j];
            acc2[2 * j]     = fma2(ek2, ww.x, acc2[2 * j]);
            acc2[2 * j + 1] = fma2(ek2, ww.y, acc2[2 * j + 1]);
        }
    }
#pragma unroll
    for (int j = 0; j < 16; j++) upk2(acc2[j], acc[2 * j], acc[2 * j + 1]);

    // ---- gelu (tanh.approx) + residual + LN ----
    float mu = 0.f;
#pragma unroll
    for (int j = 0; j < 32; j++) {
        float u = acc[j];
        float z = 0.7978845608028654f * (u + 0.044715f * u * u * u);
        float x = er[j] + 0.5f * u * (1.f + tanh_approx(z));
        acc[j] = x;
        mu += x;
    }
    mu *= (1.f / 32.f);
    float var = 0.f;
#pragma unroll
    for (int j = 0; j < 32; j++) { float dx = acc[j] - mu; var += dx * dx; }
    float inv = rsqrtf(var * (1.f / 32.f) + 1e-5f);
    float4 bb = make_float4(0.f, 0.f, 0.f, 0.f);
#pragma unroll
    for (int j = 0; j < 32; j++) {
        float y = (acc[j] - mu) * inv * sge[j] + sbe[j];
        acc[j] = y;
        float4 wv = *(const float4*)(sWeN + j * 4);
        bb.x += y * wv.x; bb.y += y * wv.y; bb.z += y * wv.z; bb.w += y * wv.w;
    }
    if (ed0 < e) {
        int slot = __ldg(g_slot + ed0);
        ((float4*)g_bias)[slot] = bb;
    }
    if (storeE) {
        __syncwarp();
#pragma unroll
        for (int k = 0; k < 8; k++) {
            __half2 h0 = __floats2half2_rn(acc[k * 4 + 0], acc[k * 4 + 1]);
            __half2 h1 = __floats2half2_rn(acc[k * 4 + 2], acc[k * 4 + 3]);
            uint2 v;
            v.x = *(unsigned*)&h0;
            v.y = *(unsigned*)&h1;
            bH[lane * 9 + k] = v;
        }
        __syncwarp();
#pragma unroll
        for (int j = 0; j < 8; j++) {
            int r = j * 4 + lrow;
            int ed = base + r;
            if (ed < e)
                *((uint2*)(g_eh + (size_t)ed * 32) + lidx) = bH[r * 9 + lidx];
        }
    }
}

// ---------------- launch ----------------
extern "C" void kernel_launch(void* const* d_in, const int* in_sizes, int n_in,
                              void* d_out, int out_size) {
    const float* nodef = (const float*)d_in[0];
    const float* edgef = (const float*)d_in[1];
    const int*   ei    = (const int*)d_in[2];
    const float* Wq    = (const float*)d_in[3];
    const float* Wk    = (const float*)d_in[4];
    const float* Wv    = (const float*)d_in[5];
    const float* Wo    = (const float*)d_in[6];
    const float* We    = (const float*)d_in[7];
    const float* Wem   = (const float*)d_in[8];
    const float* bem   = (const float*)d_in[9];
    const float* gn    = (const float*)d_in[10];
    const float* bn    = (const float*)d_in[11];
    const float* ge    = (const float*)d_in[12];
    const float* be    = (const float*)d_in[13];
    float* out = (float*)d_out;

    int n = in_sizes[0] / 64;
    int e = in_sizes[1] / 32;
    const int* src = ei;
    const int* dst = ei + e;
    int projBlocks = (n + 127) / 128;

    // side stream + events for edge/proj overlap (created once; not during capture)
    static cudaStream_t s2 = 0;
    static cudaEvent_t evA = 0, evB = 0;
    static int tried = 0;
    if (!tried) {
        tried = 1;
        if (cudaStreamCreateWithFlags(&s2, cudaStreamNonBlocking) != cudaSuccess) s2 = 0;
        if (cudaEventCreateWithFlags(&evA, cudaEventDisableTiming) != cudaSuccess) evA = 0;
        if (cudaEventCreateWithFlags(&evB, cudaEventDisableTiming) != cudaSuccess) evB = 0;
    }
    bool useS2 = (s2 != 0) && (evA != 0) && (evB != 0);

    // 0: count  1: scan+proj(L0)  2: scatbias  3: attn(L0) <- profiled
    k_count<<<(e + 255) / 256, 256>>>(dst, e);
    k_scanproj<<<projBlocks + 1, 1024>>>(n, nodef, 0, Wq, Wk, Wv, 1);
    k_scatbias<<<(e + 127) / 128, 128>>>(src, dst, edgef, We, e);

    for (int i = 0; i < 3; i++) {
        if (i > 0) {
            k_scanproj<<<projBlocks, 1024>>>(n, nodef, 1,
                                             Wq + i * 4096, Wk + i * 4096, Wv + i * 4096, 0);
            if (useS2) cudaStreamWaitEvent(0, evB, 0);   // join edge(i-1) before attn(i)
        }
        k_attn<<<(n + 7) / 8, 256>>>(n);
        int last = (i == 2);
        k_lnnode<<<(n + 15) / 16, 512>>>(nodef, (i > 0),
                                         Wo + i * 4096, gn + i * 64, bn + i * 64,
                                         Wem + i * 5120, out, last, !last, n);
        if (!last) {
            if (useS2) {
                cudaEventRecord(evA, 0);
                cudaStreamWaitEvent(s2, evA, 0);
                k_edge<<<(e + 127) / 128, 128, 0, s2>>>(Wem + i * 5120 + 4096, bem + i * 32,
                                                        ge + i * 32, be + i * 32,
                                                        We + (i + 1) * 128,
                                                        src, dst, e, (i == 0) ? 1 : 0);
                cudaEventRecord(evB, s2);
            } else {
                k_edge<<<(e + 127) / 128, 128>>>(Wem + i * 5120 + 4096, bem + i * 32,
                                                 ge + i * 32, be + i * 32,
                                                 We + (i + 1) * 128,
                                                 src, dst, e, (i == 0) ? 1 : 0);
            }
        }
    }
}

// round 11
// speedup vs baseline: 1.4139x; 1.0753x over previous
#include <cuda_runtime.h>
#include <cuda_fp16.h>

#define NMAX 50000
#define EMAX 1600000

// ---------------- static device scratch ----------------
__device__ int    g_cnt[NMAX];         // zero at load; re-zeroed by scan each run
__device__ int    g_off[NMAX + 1];
__device__ int    g_cur[NMAX];
__device__ int    g_epk[EMAX];         // src node per CSR slot
__device__ int    g_slot[EMAX];        // edge id -> CSR slot
__device__ float  g_q[NMAX * 64];
__device__ __half g_kh[NMAX * 64];     // fp16 k
__device__ __half g_vh[NMAX * 64];     // fp16 v
__device__ float  g_agg[NMAX * 64];
__device__ float  g_h[NMAX * 64];
__device__ __half g_Ah[NMAX * 32];     // fp16 A = h @ Wem[0:64]
__device__ __half g_Bh[NMAX * 32];     // fp16 B = h @ Wem[64:128]
__device__ __half g_eh[EMAX * 32];     // fp16 edge features (in-place per layer)
__device__ float  g_bias[EMAX * 4];    // score bias in CSR-slot order

// ---------------- f32x2 packed helpers (sm_103a FFMA2 path) ----------------
__device__ __forceinline__ unsigned long long pk2(float a, float b) {
    unsigned long long r;
    asm("mov.b64 %0, {%1, %2};" : "=l"(r) : "f"(a), "f"(b));
    return r;
}
__device__ __forceinline__ void upk2(unsigned long long v, float& a, float& b) {
    asm("mov.b64 {%0, %1}, %2;" : "=f"(a), "=f"(b) : "l"(v));
}
__device__ __forceinline__ unsigned long long fma2(unsigned long long a,
                                                   unsigned long long b,
                                                   unsigned long long c) {
    unsigned long long d;
    asm("fma.rn.f32x2 %0, %1, %2, %3;" : "=l"(d) : "l"(a), "l"(b), "l"(c));
    return d;
}
__device__ __forceinline__ float tanh_approx(float x) {
    float y;
    asm("tanh.approx.f32 %0, %1;" : "=f"(y) : "f"(x));
    return y;
}

// ---------------- count ----------------
__global__ void k_count(const int* __restrict__ dst, int e) {
    int i = blockIdx.x * blockDim.x + threadIdx.x;
    if (i < e) atomicAdd(&g_cnt[dst[i]], 1);
}

// ---------------- fused: block0 = exclusive scan (+re-zero cnt), rest = qkv proj ----------------
__global__ void k_scanproj(int n, const float* __restrict__ hin, int useG,
                           const float* __restrict__ Wq, const float* __restrict__ Wk,
                           const float* __restrict__ Wv, int withScan) {
    __shared__ float sq[4096], sk[4096], sv[4096];
    __shared__ int swi[32];
    int t = threadIdx.x;
    if (withScan && blockIdx.x == 0) {
        int lane = t & 31, w = t >> 5;
        int carry = 0;
        for (int base = 0; base < n; base += 1024) {
            int i = base + t;
            int v = (i < n) ? g_cnt[i] : 0;
            if (i < n) g_cnt[i] = 0;              // reset for next run
            int x = v;
#pragma unroll
            for (int o = 1; o < 32; o <<= 1) {
                int y = __shfl_up_sync(0xffffffffu, x, o);
                if (lane >= o) x += y;
            }
            if (lane == 31) swi[w] = x;
            __syncthreads();
            if (t < 32) {
                int s = swi[t];
#pragma unroll
                for (int o = 1; o < 32; o <<= 1) {
                    int y = __shfl_up_sync(0xffffffffu, s, o);
                    if (t >= o) s += y;
                }
                swi[t] = s;
            }
            __syncthreads();
            int pref = (w > 0) ? swi[w - 1] : 0;
            int excl = carry + pref + x - v;
            if (i < n) { g_off[i] = excl; g_cur[i] = excl; }
            carry += swi[31];
            __syncthreads();
        }
        if (t == 0) g_off[n] = carry;
        return;
    }
    int bp = blockIdx.x - withScan;
    for (int i = t; i < 4096; i += 1024) { sq[i] = Wq[i]; sk[i] = Wk[i]; sv[i] = Wv[i]; }
    __syncthreads();
    const float* h = useG ? g_h : hin;
    int lane = t & 31, w = t >> 5;
    int r0 = (bp * 32 + w) * 4;
    float h0[4], h1[4];
#pragma unroll
    for (int r = 0; r < 4; r++) {
        int row = r0 + r;
        h0[r] = (row < n) ? h[row * 64 + lane] : 0.f;
        h1[r] = (row < n) ? h[row * 64 + lane + 32] : 0.f;
    }
    float aq0[4] = {0,0,0,0}, aq1[4] = {0,0,0,0};
    float ak0[4] = {0,0,0,0}, ak1[4] = {0,0,0,0};
    float av0[4] = {0,0,0,0}, av1[4] = {0,0,0,0};
#pragma unroll
    for (int j = 0; j < 32; j++) {
        float wq0 = sq[j * 64 + lane], wq1 = sq[j * 64 + lane + 32];
        float wk0 = sk[j * 64 + lane], wk1 = sk[j * 64 + lane + 32];
        float wv0 = sv[j * 64 + lane], wv1 = sv[j * 64 + lane + 32];
#pragma unroll
        for (int r = 0; r < 4; r++) {
            float hj = __shfl_sync(0xffffffffu, h0[r], j);
            aq0[r] += hj * wq0; aq1[r] += hj * wq1;
            ak0[r] += hj * wk0; ak1[r] += hj * wk1;
            av0[r] += hj * wv0; av1[r] += hj * wv1;
        }
    }
#pragma unroll
    for (int j = 0; j < 32; j++) {
        float wq0 = sq[(j + 32) * 64 + lane], wq1 = sq[(j + 32) * 64 + lane + 32];
        float wk0 = sk[(j + 32) * 64 + lane], wk1 = sk[(j + 32) * 64 + lane + 32];
        float wv0 = sv[(j + 32) * 64 + lane], wv1 = sv[(j + 32) * 64 + lane + 32];
#pragma unroll
        for (int r = 0; r < 4; r++) {
            float hj = __shfl_sync(0xffffffffu, h1[r], j);
            aq0[r] += hj * wq0; aq1[r] += hj * wq1;
            ak0[r] += hj * wk0; ak1[r] += hj * wk1;
            av0[r] += hj * wv0; av1[r] += hj * wv1;
        }
    }
#pragma unroll
    for (int r = 0; r < 4; r++) {
        int row = r0 + r;
        if (row >= n) break;
        g_q[row * 64 + lane] = aq0[r]; g_q[row * 64 + lane + 32] = aq1[r];
        g_kh[row * 64 + lane] = __float2half(ak0[r]);
        g_kh[row * 64 + lane + 32] = __float2half(ak1[r]);
        g_vh[row * 64 + lane] = __float2half(av0[r]);
        g_vh[row * 64 + lane + 32] = __float2half(av1[r]);
    }
}

// ---------------- fused scatter + layer-0 bias + fp16 e copy ----------------
__global__ void k_scatbias(const int* __restrict__ src, const int* __restrict__ dstp,
                           const float* __restrict__ ef, const float* __restrict__ We, int e) {
    __shared__ float sW[128];
    __shared__ float buf[4][32 * 33];
    int t = threadIdx.x;
    if (t < 128) sW[t] = We[t];
    __syncthreads();
    int w = t >> 5, lane = t & 31;
    int base = (blockIdx.x * 4 + w) * 32;
    float* b = buf[w];
    int ed0 = base + lane;
    int slot = -1;
    if (ed0 < e) {
        int d = __ldg(dstp + ed0);
        slot = atomicAdd(&g_cur[d], 1);
        g_epk[slot] = __ldg(src + ed0);
        g_slot[ed0] = slot;
    }
#pragma unroll 4
    for (int j = 0; j < 32; j++) {
        int ed = base + j;
        b[j * 33 + lane] = (ed < e) ? __ldg(ef + (size_t)ed * 32 + lane) : 0.f;
    }
    __syncwarp();
    // fp16 copy of e0 (edge layers read this instead of re-streaming edgef)
#pragma unroll 4
    for (int j = 0; j < 32; j++) {
        int ed = base + j;
        if (ed < e) g_eh[(size_t)ed * 32 + lane] = __float2half(b[j * 33 + lane]);
    }
    if (ed0 >= e) return;
    float4 bb = make_float4(0.f, 0.f, 0.f, 0.f);
#pragma unroll
    for (int k = 0; k < 32; k++) {
        float ek = b[lane * 33 + k];
        float4 wv = *(const float4*)(sW + k * 4);
        bb.x += ek * wv.x; bb.y += ek * wv.y; bb.z += ek * wv.z; bb.w += ek * wv.w;
    }
    ((float4*)g_bias)[slot] = bb;
}

// ---------------- attention: warp/node, unroll-4, fp16 k/v ----------------
__global__ void k_attn(int n) {
    int lane = threadIdx.x & 31;
    int node = blockIdx.x * 8 + (threadIdx.x >> 5);
    if (node >= n) return;
    int half = lane >> 4;
    int sub = lane & 15;
    int head = sub >> 2;
    int beg = g_off[node], end = g_off[node + 1];
    if (beg >= end) {
        if (half == 0)
            *(float4*)(g_agg + (size_t)node * 64 + sub * 4) = make_float4(0.f, 0.f, 0.f, 0.f);
        return;
    }
    float4 q4 = *(const float4*)(g_q + (size_t)node * 64 + sub * 4);
    q4.x *= 0.25f; q4.y *= 0.25f; q4.z *= 0.25f; q4.w *= 0.25f;
    float4 acc = make_float4(0.f, 0.f, 0.f, 0.f);
    float d = 0.f;
    for (int p = beg; p < end; p += 4) {
        int i0 = p + half;
        int i1 = p + 2 + half;
        bool u0 = (i0 < end), u1 = (i1 < end);
        int e0 = u0 ? i0 : beg;          // clamped reads stay in-bounds
        int e1 = u1 ? i1 : beg;
        int s0 = __ldg(&g_epk[e0]);
        int s1 = __ldg(&g_epk[e1]);
        uint2 kr0 = __ldg((const uint2*)(g_kh + (size_t)s0 * 64) + sub);
        uint2 kr1 = __ldg((const uint2*)(g_kh + (size_t)s1 * 64) + sub);
        uint2 vr0 = __ldg((const uint2*)(g_vh + (size_t)s0 * 64) + sub);
        uint2 vr1 = __ldg((const uint2*)(g_vh + (size_t)s1 * 64) + sub);
        float b0 = __ldg(g_bias + (size_t)e0 * 4 + head);
        float b1 = __ldg(g_bias + (size_t)e1 * 4 + head);
        float2 k0a = __half22float2(*(__half2*)&kr0.x);
        float2 k0b = __half22float2(*(__half2*)&kr0.y);
        float2 k1a = __half22float2(*(__half2*)&kr1.x);
        float2 k1b = __half22float2(*(__half2*)&kr1.y);
        float dt0 = q4.x * k0a.x + q4.y * k0a.y + q4.z * k0b.x + q4.w * k0b.y;
        float dt1 = q4.x * k1a.x + q4.y * k1a.y + q4.z * k1b.x + q4.w * k1b.y;
        dt0 += __shfl_xor_sync(0xffffffffu, dt0, 1);
        dt1 += __shfl_xor_sync(0xffffffffu, dt1, 1);
        dt0 += __shfl_xor_sync(0xffffffffu, dt0, 2);
        dt1 += __shfl_xor_sync(0xffffffffu, dt1, 2);
        float ex0 = u0 ? __expf(dt0 + b0) : 0.f;
        float ex1 = u1 ? __expf(dt1 + b1) : 0.f;
        d += ex0; d += ex1;
        float2 v0a = __half22float2(*(__half2*)&vr0.x);
        float2 v0b = __half22float2(*(__half2*)&vr0.y);
        float2 v1a = __half22float2(*(__half2*)&vr1.x);
        float2 v1b = __half22float2(*(__half2*)&vr1.y);
        acc.x += ex0 * v0a.x; acc.y += ex0 * v0a.y; acc.z += ex0 * v0b.x; acc.w += ex0 * v0b.y;
        acc.x += ex1 * v1a.x; acc.y += ex1 * v1a.y; acc.z += ex1 * v1b.x; acc.w += ex1 * v1b.y;
    }
    acc.x += __shfl_xor_sync(0xffffffffu, acc.x, 16);
    acc.y += __shfl_xor_sync(0xffffffffu, acc.y, 16);
    acc.z += __shfl_xor_sync(0xffffffffu, acc.z, 16);
    acc.w += __shfl_xor_sync(0xffffffffu, acc.w, 16);
    d     += __shfl_xor_sync(0xffffffffu, d, 16);
    if (half == 0) {
        float inv = 1.f / (d + 1e-9f);
        float4 o;
        o.x = acc.x * inv; o.y = acc.y * inv;
        o.z = acc.z * inv; o.w = acc.w * inv;
        *(float4*)(g_agg + (size_t)node * 64 + sub * 4) = o;
    }
}

// ---------------- node update (512 thr): h = LN(h + agg@Wo); fused fp16 A,B ----------------
__global__ void __launch_bounds__(512)
k_lnnode(const float* __restrict__ hin, int useGin,
         const float* __restrict__ Wo, const float* __restrict__ gn,
         const float* __restrict__ bn, const float* __restrict__ Wab,
         float* __restrict__ outp, int useOut, int doAB, int n) {
    __shared__ float sWo[4096];
    __shared__ float sAB[4096];
    for (int i = threadIdx.x; i < 4096; i += 512) {
        sWo[i] = Wo[i];
        if (doAB) sAB[i] = Wab[i];
    }
    __syncthreads();
    int lane = threadIdx.x & 31, w = threadIdx.x >> 5;
    int row = blockIdx.x * 16 + w;
    if (row >= n) return;
    const float* h = useGin ? g_h : hin;
    float a0 = g_agg[row * 64 + lane], a1 = g_agg[row * 64 + lane + 32];
    float o0 = 0.f, o1 = 0.f;
#pragma unroll
    for (int j = 0; j < 32; j++) {
        float aj = __shfl_sync(0xffffffffu, a0, j);
        o0 += aj * sWo[j * 64 + lane];
        o1 += aj * sWo[j * 64 + lane + 32];
    }
#pragma unroll
    for (int j = 0; j < 32; j++) {
        float aj = __shfl_sync(0xffffffffu, a1, j);
        o0 += aj * sWo[(j + 32) * 64 + lane];
        o1 += aj * sWo[(j + 32) * 64 + lane + 32];
    }
    float x0 = h[row * 64 + lane] + o0;
    float x1 = h[row * 64 + lane + 32] + o1;
    float s = x0 + x1;
#pragma unroll
    for (int o = 16; o; o >>= 1) s += __shfl_xor_sync(0xffffffffu, s, o);
    float mu = s * (1.f / 64.f);
    float d0 = x0 - mu, d1 = x1 - mu;
    float vs = d0 * d0 + d1 * d1;
#pragma unroll
    for (int o = 16; o; o >>= 1) vs += __shfl_xor_sync(0xffffffffu, vs, o);
    float inv = rsqrtf(vs * (1.f / 64.f) + 1e-5f);
    float y0 = d0 * inv * __ldg(gn + lane) + __ldg(bn + lane);
    float y1 = d1 * inv * __ldg(gn + lane + 32) + __ldg(bn + lane + 32);
    float* hp = useOut ? outp : g_h;
    hp[row * 64 + lane] = y0;
    hp[row * 64 + lane + 32] = y1;
    if (doAB) {
        float A = 0.f, B = 0.f;
#pragma unroll
        for (int j = 0; j < 32; j++) {
            float yj = __shfl_sync(0xffffffffu, y0, j);
            A += yj * sAB[j * 32 + lane];
            B += yj * sAB[(j + 64) * 32 + lane];
        }
#pragma unroll
        for (int j = 0; j < 32; j++) {
            float yj = __shfl_sync(0xffffffffu, y1, j);
            A += yj * sAB[(j + 32) * 32 + lane];
            B += yj * sAB[(j + 96) * 32 + lane];
        }
        g_Ah[row * 32 + lane] = __float2half(A);
        g_Bh[row * 32 + lane] = __float2half(B);
    }
}

// ---------------- edge update: fp16 gathers/staging, low-reg, f32x2 GEMM ----------------
__global__ void __launch_bounds__(128)
k_edge(const float* __restrict__ Wem2, const float* __restrict__ bem,
       const float* __restrict__ ge, const float* __restrict__ be,
       const float* __restrict__ WeN,
       const int* __restrict__ src, const int* __restrict__ dstp,
       int e, int storeE) {
    __shared__ float sW[1024];
    __shared__ float sWeN[128];
    __shared__ float sbem[32], sge[32], sbe[32];
    __shared__ __half bufA[4][32 * 34];
    __shared__ __half bufB[4][32 * 34];
    __shared__ uint2 bufH[4][32 * 9];
    int t = threadIdx.x;
    for (int i = t; i < 1024; i += 128) sW[i] = Wem2[i];
    if (t < 128) sWeN[t] = WeN[t];
    if (t < 32) { sbem[t] = bem[t]; sge[t] = ge[t]; sbe[t] = be[t]; }
    __syncthreads();
    int w = t >> 5, lane = t & 31;
    int base = (blockIdx.x * 4 + w) * 32;
    __half* bA = bufA[w];
    __half* bB = bufB[w];
    uint2* bH = bufH[w];
    const __half* eHalf = (const __half*)bH;   // lane's e row k at [lane*36+k]

    // ---- stage e rows: 8 x LDG.64 per warp (4 halves/lane) ----
    int lrow = lane >> 3, lidx = lane & 7;
#pragma unroll
    for (int j = 0; j < 8; j++) {
        int r = j * 4 + lrow;
        int ed = base + r;
        uint2 v = make_uint2(0u, 0u);
        if (ed < e) v = __ldg((const uint2*)(g_eh + (size_t)ed * 32) + lidx);
        bH[r * 9 + lidx] = v;
    }

    int ed0 = base + lane;
    int s_l = (ed0 < e) ? __ldg(src + ed0)  : 0;
    int d_l = (ed0 < e) ? __ldg(dstp + ed0) : 0;

    // ---- stage fp16 A[src], B[dst] interleaved (high MLP, 2B/lane coalesced) ----
#pragma unroll 8
    for (int j = 0; j < 32; j++) {
        int sj = __shfl_sync(0xffffffffu, s_l, j);
        int dj = __shfl_sync(0xffffffffu, d_l, j);
        bA[j * 34 + lane] = __ldg(g_Ah + (size_t)sj * 32 + lane);
        bB[j * 34 + lane] = __ldg(g_Bh + (size_t)dj * 32 + lane);
    }
    __syncwarp();

    float acc[32];
#pragma unroll
    for (int k = 0; k < 32; k++)
        acc[k] = __half2float(bA[lane * 34 + k]) + __half2float(bB[lane * 34 + k]) + sbem[k];

    // ---- e @ Wem2 on packed f32x2; e-values read from smem (no er regs) ----
    unsigned long long acc2[16];
#pragma unroll
    for (int j = 0; j < 16; j++) acc2[j] = pk2(acc[2 * j], acc[2 * j + 1]);
#pragma unroll
    for (int k = 0; k < 32; k++) {
        float ek = __half2float(eHalf[lane * 36 + k]);
        unsigned long long ek2 = pk2(ek, ek);
        const ulonglong2* wr = (const ulonglong2*)(sW + k * 32);
#pragma unroll
        for (int j = 0; j < 8; j++) {
            ulonglong2 ww = wr[j];
            acc2[2 * j]     = fma2(ek2, ww.x, acc2[2 * j]);
            acc2[2 * j + 1] = fma2(ek2, ww.y, acc2[2 * j + 1]);
        }
    }
#pragma unroll
    for (int j = 0; j < 16; j++) upk2(acc2[j], acc[2 * j], acc[2 * j + 1]);

    // ---- gelu (tanh.approx) + residual + LN (residual re-read from smem) ----
    float mu = 0.f;
#pragma unroll
    for (int j = 0; j < 32; j++) {
        float u = acc[j];
        float z = 0.7978845608028654f * (u + 0.044715f * u * u * u);
        float x = __half2float(eHalf[lane * 36 + j]) + 0.5f * u * (1.f + tanh_approx(z));
        acc[j] = x;
        mu += x;
    }
    mu *= (1.f / 32.f);
    float var = 0.f;
#pragma unroll
    for (int j = 0; j < 32; j++) { float dx = acc[j] - mu; var += dx * dx; }
    float inv = rsqrtf(var * (1.f / 32.f) + 1e-5f);
    float4 bb = make_float4(0.f, 0.f, 0.f, 0.f);
#pragma unroll
    for (int j = 0; j < 32; j++) {
        float y = (acc[j] - mu) * inv * sge[j] + sbe[j];
        acc[j] = y;
        float4 wv = *(const float4*)(sWeN + j * 4);
        bb.x += y * wv.x; bb.y += y * wv.y; bb.z += y * wv.z; bb.w += y * wv.w;
    }
    if (ed0 < e) {
        int slot = __ldg(g_slot + ed0);
        ((float4*)g_bias)[slot] = bb;
    }
    if (storeE) {
        __syncwarp();
#pragma unroll
        for (int k = 0; k < 8; k++) {
            __half2 h0 = __floats2half2_rn(acc[k * 4 + 0], acc[k * 4 + 1]);
            __half2 h1 = __floats2half2_rn(acc[k * 4 + 2], acc[k * 4 + 3]);
            uint2 v;
            v.x = *(unsigned*)&h0;
            v.y = *(unsigned*)&h1;
            bH[lane * 9 + k] = v;
        }
        __syncwarp();
#pragma unroll
        for (int j = 0; j < 8; j++) {
            int r = j * 4 + lrow;
            int ed = base + r;
            if (ed < e)
                *((uint2*)(g_eh + (size_t)ed * 32) + lidx) = bH[r * 9 + lidx];
        }
    }
}

// ---------------- launch ----------------
extern "C" void kernel_launch(void* const* d_in, const int* in_sizes, int n_in,
                              void* d_out, int out_size) {
    const float* nodef = (const float*)d_in[0];
    const float* edgef = (const float*)d_in[1];
    const int*   ei    = (const int*)d_in[2];
    const float* Wq    = (const float*)d_in[3];
    const float* Wk    = (const float*)d_in[4];
    const float* Wv    = (const float*)d_in[5];
    const float* Wo    = (const float*)d_in[6];
    const float* We    = (const float*)d_in[7];
    const float* Wem   = (const float*)d_in[8];
    const float* bem   = (const float*)d_in[9];
    const float* gn    = (const float*)d_in[10];
    const float* bn    = (const float*)d_in[11];
    const float* ge    = (const float*)d_in[12];
    const float* be    = (const float*)d_in[13];
    float* out = (float*)d_out;

    int n = in_sizes[0] / 64;
    int e = in_sizes[1] / 32;
    const int* src = ei;
    const int* dst = ei + e;
    int projBlocks = (n + 127) / 128;

    // side stream + events for edge/proj overlap (created once; not during capture)
    static cudaStream_t s2 = 0;
    static cudaEvent_t evA = 0, evB = 0;
    static int tried = 0;
    if (!tried) {
        tried = 1;
        if (cudaStreamCreateWithFlags(&s2, cudaStreamNonBlocking) != cudaSuccess) s2 = 0;
        if (cudaEventCreateWithFlags(&evA, cudaEventDisableTiming) != cudaSuccess) evA = 0;
        if (cudaEventCreateWithFlags(&evB, cudaEventDisableTiming) != cudaSuccess) evB = 0;
    }
    bool useS2 = (s2 != 0) && (evA != 0) && (evB != 0);

    // 0: count  1: scan+proj(L0)  2: scatbias  3: attn(L0) <- profiled
    k_count<<<(e + 255) / 256, 256>>>(dst, e);
    k_scanproj<<<projBlocks + 1, 1024>>>(n, nodef, 0, Wq, Wk, Wv, 1);
    k_scatbias<<<(e + 127) / 128, 128>>>(src, dst, edgef, We, e);

    for (int i = 0; i < 3; i++) {
        if (i > 0) {
            k_scanproj<<<projBlocks, 1024>>>(n, nodef, 1,
                                             Wq + i * 4096, Wk + i * 4096, Wv + i * 4096, 0);
            if (useS2) cudaStreamWaitEvent(0, evB, 0);   // join edge(i-1) before attn(i)
        }
        k_attn<<<(n + 7) / 8, 256>>>(n);
        int last = (i == 2);
        k_lnnode<<<(n + 15) / 16, 512>>>(nodef, (i > 0),
                                         Wo + i * 4096, gn + i * 64, bn + i * 64,
                                         Wem + i * 5120, out, last, !last, n);
        if (!last) {
            if (useS2) {
                cudaEventRecord(evA, 0);
                cudaStreamWaitEvent(s2, evA, 0);
                k_edge<<<(e + 127) / 128, 128, 0, s2>>>(Wem + i * 5120 + 4096, bem + i * 32,
                                                        ge + i * 32, be + i * 32,
                                                        We + (i + 1) * 128,
                                                        src, dst, e, (i == 0) ? 1 : 0);
                cudaEventRecord(evB, s2);
            } else {
                k_edge<<<(e + 127) / 128, 128>>>(Wem + i * 5120 + 4096, bem + i * 32,
                                                 ge + i * 32, be + i * 32,
                                                 We + (i + 1) * 128,
                                                 src, dst, e, (i == 0) ? 1 : 0);
            }
        }
    }
}

// round 12
// speedup vs baseline: 1.4793x; 1.0462x over previous
#include <cuda_runtime.h>
#include <cuda_fp16.h>

#define NMAX 50000
#define EMAX 1600000

// ---------------- static device scratch ----------------
__device__ int    g_cnt[NMAX];         // zero at load; re-zeroed by scan each run
__device__ int    g_off[NMAX + 1];
__device__ int    g_cur[NMAX];
__device__ int    g_epk[EMAX];         // src node per CSR slot
__device__ int    g_slot[EMAX];        // edge id -> CSR slot
__device__ float  g_q[NMAX * 64];
__device__ __half g_kh[NMAX * 64];     // fp16 k
__device__ __half g_vh[NMAX * 64];     // fp16 v
__device__ float  g_agg[NMAX * 64];
__device__ float  g_h[NMAX * 64];
__device__ __half g_Ah[NMAX * 32];     // fp16 A = h @ Wem[0:64]
__device__ __half g_Bh[NMAX * 32];     // fp16 B = h @ Wem[64:128]
__device__ __half g_eh[EMAX * 32];     // fp16 edge features (in-place per layer)
__device__ float  g_bias[EMAX * 4];    // score bias in CSR-slot order

// ---------------- f32x2 packed helpers (sm_103a FFMA2 path) ----------------
__device__ __forceinline__ unsigned long long pk2(float a, float b) {
    unsigned long long r;
    asm("mov.b64 %0, {%1, %2};" : "=l"(r) : "f"(a), "f"(b));
    return r;
}
__device__ __forceinline__ void upk2(unsigned long long v, float& a, float& b) {
    asm("mov.b64 {%0, %1}, %2;" : "=f"(a), "=f"(b) : "l"(v));
}
__device__ __forceinline__ unsigned long long fma2(unsigned long long a,
                                                   unsigned long long b,
                                                   unsigned long long c) {
    unsigned long long d;
    asm("fma.rn.f32x2 %0, %1, %2, %3;" : "=l"(d) : "l"(a), "l"(b), "l"(c));
    return d;
}
__device__ __forceinline__ float tanh_approx(float x) {
    float y;
    asm("tanh.approx.f32 %0, %1;" : "=f"(y) : "f"(x));
    return y;
}

// ---------------- count ----------------
__global__ void k_count(const int* __restrict__ dst, int e) {
    int i = blockIdx.x * blockDim.x + threadIdx.x;
    if (i < e) atomicAdd(&g_cnt[dst[i]], 1);
}

// ---------------- fused: block0 = exclusive scan (+re-zero cnt), rest = qkv proj ----------------
__global__ void k_scanproj(int n, const float* __restrict__ hin, int useG,
                           const float* __restrict__ Wq, const float* __restrict__ Wk,
                           const float* __restrict__ Wv, int withScan) {
    __shared__ float sq[4096], sk[4096], sv[4096];
    __shared__ int swi[32];
    int t = threadIdx.x;
    if (withScan && blockIdx.x == 0) {
        int lane = t & 31, w = t >> 5;
        int carry = 0;
        for (int base = 0; base < n; base += 1024) {
            int i = base + t;
            int v = (i < n) ? g_cnt[i] : 0;
            if (i < n) g_cnt[i] = 0;              // reset for next run
            int x = v;
#pragma unroll
            for (int o = 1; o < 32; o <<= 1) {
                int y = __shfl_up_sync(0xffffffffu, x, o);
                if (lane >= o) x += y;
            }
            if (lane == 31) swi[w] = x;
            __syncthreads();
            if (t < 32) {
                int s = swi[t];
#pragma unroll
                for (int o = 1; o < 32; o <<= 1) {
                    int y = __shfl_up_sync(0xffffffffu, s, o);
                    if (t >= o) s += y;
                }
                swi[t] = s;
            }
            __syncthreads();
            int pref = (w > 0) ? swi[w - 1] : 0;
            int excl = carry + pref + x - v;
            if (i < n) { g_off[i] = excl; g_cur[i] = excl; }
            carry += swi[31];
            __syncthreads();
        }
        if (t == 0) g_off[n] = carry;
        return;
    }
    int bp = blockIdx.x - withScan;
    for (int i = t; i < 4096; i += 1024) { sq[i] = Wq[i]; sk[i] = Wk[i]; sv[i] = Wv[i]; }
    __syncthreads();
    const float* h = useG ? g_h : hin;
    int lane = t & 31, w = t >> 5;
    int r0 = (bp * 32 + w) * 4;
    float h0[4], h1[4];
#pragma unroll
    for (int r = 0; r < 4; r++) {
        int row = r0 + r;
        h0[r] = (row < n) ? h[row * 64 + lane] : 0.f;
        h1[r] = (row < n) ? h[row * 64 + lane + 32] : 0.f;
    }
    float aq0[4] = {0,0,0,0}, aq1[4] = {0,0,0,0};
    float ak0[4] = {0,0,0,0}, ak1[4] = {0,0,0,0};
    float av0[4] = {0,0,0,0}, av1[4] = {0,0,0,0};
#pragma unroll
    for (int j = 0; j < 32; j++) {
        float wq0 = sq[j * 64 + lane], wq1 = sq[j * 64 + lane + 32];
        float wk0 = sk[j * 64 + lane], wk1 = sk[j * 64 + lane + 32];
        float wv0 = sv[j * 64 + lane], wv1 = sv[j * 64 + lane + 32];
#pragma unroll
        for (int r = 0; r < 4; r++) {
            float hj = __shfl_sync(0xffffffffu, h0[r], j);
            aq0[r] += hj * wq0; aq1[r] += hj * wq1;
            ak0[r] += hj * wk0; ak1[r] += hj * wk1;
            av0[r] += hj * wv0; av1[r] += hj * wv1;
        }
    }
#pragma unroll
    for (int j = 0; j < 32; j++) {
        float wq0 = sq[(j + 32) * 64 + lane], wq1 = sq[(j + 32) * 64 + lane + 32];
        float wk0 = sk[(j + 32) * 64 + lane], wk1 = sk[(j + 32) * 64 + lane + 32];
        float wv0 = sv[(j + 32) * 64 + lane], wv1 = sv[(j + 32) * 64 + lane + 32];
#pragma unroll
        for (int r = 0; r < 4; r++) {
            float hj = __shfl_sync(0xffffffffu, h1[r], j);
            aq0[r] += hj * wq0; aq1[r] += hj * wq1;
            ak0[r] += hj * wk0; ak1[r] += hj * wk1;
            av0[r] += hj * wv0; av1[r] += hj * wv1;
        }
    }
#pragma unroll
    for (int r = 0; r < 4; r++) {
        int row = r0 + r;
        if (row >= n) break;
        g_q[row * 64 + lane] = aq0[r]; g_q[row * 64 + lane + 32] = aq1[r];
        g_kh[row * 64 + lane] = __float2half(ak0[r]);
        g_kh[row * 64 + lane + 32] = __float2half(ak1[r]);
        g_vh[row * 64 + lane] = __float2half(av0[r]);
        g_vh[row * 64 + lane + 32] = __float2half(av1[r]);
    }
}

// ---------------- fused scatter + layer-0 bias + fp16 e copy ----------------
__global__ void k_scatbias(const int* __restrict__ src, const int* __restrict__ dstp,
                           const float* __restrict__ ef, const float* __restrict__ We, int e) {
    __shared__ float sW[128];
    __shared__ float buf[4][32 * 33];
    int t = threadIdx.x;
    if (t < 128) sW[t] = We[t];
    __syncthreads();
    int w = t >> 5, lane = t & 31;
    int base = (blockIdx.x * 4 + w) * 32;
    float* b = buf[w];
    int ed0 = base + lane;
    int slot = -1;
    if (ed0 < e) {
        int d = __ldg(dstp + ed0);
        slot = atomicAdd(&g_cur[d], 1);
        g_epk[slot] = __ldg(src + ed0);
        g_slot[ed0] = slot;
    }
#pragma unroll 4
    for (int j = 0; j < 32; j++) {
        int ed = base + j;
        b[j * 33 + lane] = (ed < e) ? __ldg(ef + (size_t)ed * 32 + lane) : 0.f;
    }
    __syncwarp();
    // fp16 copy of e0 (edge layers read this instead of re-streaming edgef)
#pragma unroll 4
    for (int j = 0; j < 32; j++) {
        int ed = base + j;
        if (ed < e) g_eh[(size_t)ed * 32 + lane] = __float2half(b[j * 33 + lane]);
    }
    if (ed0 >= e) return;
    float4 bb = make_float4(0.f, 0.f, 0.f, 0.f);
#pragma unroll
    for (int k = 0; k < 32; k++) {
        float ek = b[lane * 33 + k];
        float4 wv = *(const float4*)(sW + k * 4);
        bb.x += ek * wv.x; bb.y += ek * wv.y; bb.z += ek * wv.z; bb.w += ek * wv.w;
    }
    ((float4*)g_bias)[slot] = bb;
}

// ---------------- attention: 8 lanes/edge (4 edges per warp-iter), fp16 k/v ----------------
// lane = g*8 + o: group g handles edge p+g; lane owns dims 8o..8o+7 (one head: o>>1).
__global__ void k_attn(int n) {
    int lane = threadIdx.x & 31;
    int node = blockIdx.x * 8 + (threadIdx.x >> 5);
    if (node >= n) return;
    int g = lane >> 3;
    int o = lane & 7;
    int head = o >> 1;
    int beg = g_off[node], end = g_off[node + 1];
    // q octet, scale 1/sqrt(16)=0.25 folded in
    float4 qa = *(const float4*)(g_q + (size_t)node * 64 + o * 8);
    float4 qb = *(const float4*)(g_q + (size_t)node * 64 + o * 8 + 4);
    qa.x *= 0.25f; qa.y *= 0.25f; qa.z *= 0.25f; qa.w *= 0.25f;
    qb.x *= 0.25f; qb.y *= 0.25f; qb.z *= 0.25f; qb.w *= 0.25f;
    float acc[8] = {0.f, 0.f, 0.f, 0.f, 0.f, 0.f, 0.f, 0.f};
    float den = 0.f;
    for (int p = beg; p < end; p += 4) {
        int eg = p + g;
        bool u = (eg < end);
        int idx = u ? eg : beg;           // clamped reads stay in-bounds
        int s = __ldg(&g_epk[idx]);
        uint4 kk = __ldg((const uint4*)(g_kh + (size_t)s * 64) + o);
        uint4 vv = __ldg((const uint4*)(g_vh + (size_t)s * 64) + o);
        float b = __ldg(g_bias + (size_t)idx * 4 + head);
        float2 k0 = __half22float2(*(__half2*)&kk.x);
        float2 k1 = __half22float2(*(__half2*)&kk.y);
        float2 k2 = __half22float2(*(__half2*)&kk.z);
        float2 k3 = __half22float2(*(__half2*)&kk.w);
        float dt = qa.x * k0.x + qa.y * k0.y + qa.z * k1.x + qa.w * k1.y
                 + qb.x * k2.x + qb.y * k2.y + qb.z * k3.x + qb.w * k3.y;
        dt += __shfl_xor_sync(0xffffffffu, dt, 1);   // pair -> full 16-dim head dot
        float ex = u ? __expf(dt + b) : 0.f;
        den += ex;
        float2 v0 = __half22float2(*(__half2*)&vv.x);
        float2 v1 = __half22float2(*(__half2*)&vv.y);
        float2 v2 = __half22float2(*(__half2*)&vv.z);
        float2 v3 = __half22float2(*(__half2*)&vv.w);
        acc[0] += ex * v0.x; acc[1] += ex * v0.y;
        acc[2] += ex * v1.x; acc[3] += ex * v1.y;
        acc[4] += ex * v2.x; acc[5] += ex * v2.y;
        acc[6] += ex * v3.x; acc[7] += ex * v3.y;
    }
    // merge 4 edge-groups
#pragma unroll
    for (int i = 0; i < 8; i++) {
        acc[i] += __shfl_xor_sync(0xffffffffu, acc[i], 8);
        acc[i] += __shfl_xor_sync(0xffffffffu, acc[i], 16);
    }
    den += __shfl_xor_sync(0xffffffffu, den, 8);
    den += __shfl_xor_sync(0xffffffffu, den, 16);
    if (g == 0) {
        float inv = 1.f / (den + 1e-9f);
        float4 o0 = make_float4(acc[0] * inv, acc[1] * inv, acc[2] * inv, acc[3] * inv);
        float4 o1 = make_float4(acc[4] * inv, acc[5] * inv, acc[6] * inv, acc[7] * inv);
        *(float4*)(g_agg + (size_t)node * 64 + o * 8)     = o0;
        *(float4*)(g_agg + (size_t)node * 64 + o * 8 + 4) = o1;
    }
}

// ---------------- node update (512 thr): h = LN(h + agg@Wo); fused fp16 A,B ----------------
__global__ void __launch_bounds__(512)
k_lnnode(const float* __restrict__ hin, int useGin,
         const float* __restrict__ Wo, const float* __restrict__ gn,
         const float* __restrict__ bn, const float* __restrict__ Wab,
         float* __restrict__ outp, int useOut, int doAB, int n) {
    __shared__ float sWo[4096];
    __shared__ float sAB[4096];
    for (int i = threadIdx.x; i < 4096; i += 512) {
        sWo[i] = Wo[i];
        if (doAB) sAB[i] = Wab[i];
    }
    __syncthreads();
    int lane = threadIdx.x & 31, w = threadIdx.x >> 5;
    int row = blockIdx.x * 16 + w;
    if (row >= n) return;
    const float* h = useGin ? g_h : hin;
    float a0 = g_agg[row * 64 + lane], a1 = g_agg[row * 64 + lane + 32];
    float o0 = 0.f, o1 = 0.f;
#pragma unroll
    for (int j = 0; j < 32; j++) {
        float aj = __shfl_sync(0xffffffffu, a0, j);
        o0 += aj * sWo[j * 64 + lane];
        o1 += aj * sWo[j * 64 + lane + 32];
    }
#pragma unroll
    for (int j = 0; j < 32; j++) {
        float aj = __shfl_sync(0xffffffffu, a1, j);
        o0 += aj * sWo[(j + 32) * 64 + lane];
        o1 += aj * sWo[(j + 32) * 64 + lane + 32];
    }
    float x0 = h[row * 64 + lane] + o0;
    float x1 = h[row * 64 + lane + 32] + o1;
    float s = x0 + x1;
#pragma unroll
    for (int o = 16; o; o >>= 1) s += __shfl_xor_sync(0xffffffffu, s, o);
    float mu = s * (1.f / 64.f);
    float d0 = x0 - mu, d1 = x1 - mu;
    float vs = d0 * d0 + d1 * d1;
#pragma unroll
    for (int o = 16; o; o >>= 1) vs += __shfl_xor_sync(0xffffffffu, vs, o);
    float inv = rsqrtf(vs * (1.f / 64.f) + 1e-5f);
    float y0 = d0 * inv * __ldg(gn + lane) + __ldg(bn + lane);
    float y1 = d1 * inv * __ldg(gn + lane + 32) + __ldg(bn + lane + 32);
    float* hp = useOut ? outp : g_h;
    hp[row * 64 + lane] = y0;
    hp[row * 64 + lane + 32] = y1;
    if (doAB) {
        float A = 0.f, B = 0.f;
#pragma unroll
        for (int j = 0; j < 32; j++) {
            float yj = __shfl_sync(0xffffffffu, y0, j);
            A += yj * sAB[j * 32 + lane];
            B += yj * sAB[(j + 64) * 32 + lane];
        }
#pragma unroll
        for (int j = 0; j < 32; j++) {
            float yj = __shfl_sync(0xffffffffu, y1, j);
            A += yj * sAB[(j + 32) * 32 + lane];
            B += yj * sAB[(j + 96) * 32 + lane];
        }
        g_Ah[row * 32 + lane] = __float2half(A);
        g_Bh[row * 32 + lane] = __float2half(B);
    }
}

// ---------------- edge update: vectorized fp16 staging, low-reg, f32x2 GEMM ----------------
__global__ void __launch_bounds__(128)
k_edge(const float* __restrict__ Wem2, const float* __restrict__ bem,
       const float* __restrict__ ge, const float* __restrict__ be,
       const float* __restrict__ WeN,
       const int* __restrict__ src, const int* __restrict__ dstp,
       int e, int storeE) {
    __shared__ float sW[1024];
    __shared__ float sWeN[128];
    __shared__ float sbem[32], sge[32], sbe[32];
    __shared__ uint2 bufA[4][32 * 9];
    __shared__ uint2 bufB[4][32 * 9];
    __shared__ uint2 bufH[4][32 * 9];
    int t = threadIdx.x;
    for (int i = t; i < 1024; i += 128) sW[i] = Wem2[i];
    if (t < 128) sWeN[t] = WeN[t];
    if (t < 32) { sbem[t] = bem[t]; sge[t] = ge[t]; sbe[t] = be[t]; }
    __syncthreads();
    int w = t >> 5, lane = t & 31;
    int base = (blockIdx.x * 4 + w) * 32;
    uint2* bA = bufA[w];
    uint2* bB = bufB[w];
    uint2* bH = bufH[w];
    const __half* eHalf = (const __half*)bH;   // lane's e row k at [lane*36+k]
    const __half* aHalf = (const __half*)bA;
    const __half* bHalf = (const __half*)bB;

    // ---- stage e rows: 8 x LDG.64 per warp (4 halves/lane) ----
    int lrow = lane >> 3, lidx = lane & 7;
#pragma unroll
    for (int j = 0; j < 8; j++) {
        int r = j * 4 + lrow;
        int ed = base + r;
        uint2 v = make_uint2(0u, 0u);
        if (ed < e) v = __ldg((const uint2*)(g_eh + (size_t)ed * 32) + lidx);
        bH[r * 9 + lidx] = v;
    }

    int ed0 = base + lane;
    int s_l = (ed0 < e) ? __ldg(src + ed0)  : 0;
    int d_l = (ed0 < e) ? __ldg(dstp + ed0) : 0;

    // ---- stage fp16 A[src], B[dst]: 4 rows/iter via uint2 (LDG.64) ----
#pragma unroll
    for (int j8 = 0; j8 < 8; j8++) {
        int r = j8 * 4 + lrow;
        int sj = __shfl_sync(0xffffffffu, s_l, r);
        int dj = __shfl_sync(0xffffffffu, d_l, r);
        bA[r * 9 + lidx] = __ldg((const uint2*)(g_Ah + (size_t)sj * 32) + lidx);
        bB[r * 9 + lidx] = __ldg((const uint2*)(g_Bh + (size_t)dj * 32) + lidx);
    }
    __syncwarp();

    float acc[32];
#pragma unroll
    for (int k = 0; k < 32; k++)
        acc[k] = __half2float(aHalf[lane * 36 + k]) + __half2float(bHalf[lane * 36 + k]) + sbem[k];

    // ---- e @ Wem2 on packed f32x2; e-values read from smem (no er regs) ----
    unsigned long long acc2[16];
#pragma unroll
    for (int j = 0; j < 16; j++) acc2[j] = pk2(acc[2 * j], acc[2 * j + 1]);
#pragma unroll
    for (int k = 0; k < 32; k++) {
        float ek = __half2float(eHalf[lane * 36 + k]);
        unsigned long long ek2 = pk2(ek, ek);
        const ulonglong2* wr = (const ulonglong2*)(sW + k * 32);
#pragma unroll
        for (int j = 0; j < 8; j++) {
            ulonglong2 ww = wr[j];
            acc2[2 * j]     = fma2(ek2, ww.x, acc2[2 * j]);
            acc2[2 * j + 1] = fma2(ek2, ww.y, acc2[2 * j + 1]);
        }
    }
#pragma unroll
    for (int j = 0; j < 16; j++) upk2(acc2[j], acc[2 * j], acc[2 * j + 1]);

    // ---- gelu (tanh.approx) + residual + LN (residual re-read from smem) ----
    float mu = 0.f;
#pragma unroll
    for (int j = 0; j < 32; j++) {
        float u = acc[j];
        float z = 0.7978845608028654f * (u + 0.044715f * u * u * u);
        float x = __half2float(eHalf[lane * 36 + j]) + 0.5f * u * (1.f + tanh_approx(z));
        acc[j] = x;
        mu += x;
    }
    mu *= (1.f / 32.f);
    float var = 0.f;
#pragma unroll
    for (int j = 0; j < 32; j++) { float dx = acc[j] - mu; var += dx * dx; }
    float inv = rsqrtf(var * (1.f / 32.f) + 1e-5f);
    float4 bb = make_float4(0.f, 0.f, 0.f, 0.f);
#pragma unroll
    for (int j = 0; j < 32; j++) {
        float y = (acc[j] - mu) * inv * sge[j] + sbe[j];
        acc[j] = y;
        float4 wv = *(const float4*)(sWeN + j * 4);
        bb.x += y * wv.x; bb.y += y * wv.y; bb.z += y * wv.z; bb.w += y * wv.w;
    }
    if (ed0 < e) {
        int slot = __ldg(g_slot + ed0);
        ((float4*)g_bias)[slot] = bb;
    }
    if (storeE) {
        __syncwarp();
#pragma unroll
        for (int k = 0; k < 8; k++) {
            __half2 h0 = __floats2half2_rn(acc[k * 4 + 0], acc[k * 4 + 1]);
            __half2 h1 = __floats2half2_rn(acc[k * 4 + 2], acc[k * 4 + 3]);
            uint2 v;
            v.x = *(unsigned*)&h0;
            v.y = *(unsigned*)&h1;
            bH[lane * 9 + k] = v;
        }
        __syncwarp();
#pragma unroll
        for (int j = 0; j < 8; j++) {
            int r = j * 4 + lrow;
            int ed = base + r;
            if (ed < e)
                *((uint2*)(g_eh + (size_t)ed * 32) + lidx) = bH[r * 9 + lidx];
        }
    }
}

// ---------------- launch ----------------
extern "C" void kernel_launch(void* const* d_in, const int* in_sizes, int n_in,
                              void* d_out, int out_size) {
    const float* nodef = (const float*)d_in[0];
    const float* edgef = (const float*)d_in[1];
    const int*   ei    = (const int*)d_in[2];
    const float* Wq    = (const float*)d_in[3];
    const float* Wk    = (const float*)d_in[4];
    const float* Wv    = (const float*)d_in[5];
    const float* Wo    = (const float*)d_in[6];
    const float* We    = (const float*)d_in[7];
    const float* Wem   = (const float*)d_in[8];
    const float* bem   = (const float*)d_in[9];
    const float* gn    = (const float*)d_in[10];
    const float* bn    = (const float*)d_in[11];
    const float* ge    = (const float*)d_in[12];
    const float* be    = (const float*)d_in[13];
    float* out = (float*)d_out;

    int n = in_sizes[0] / 64;
    int e = in_sizes[1] / 32;
    const int* src = ei;
    const int* dst = ei + e;
    int projBlocks = (n + 127) / 128;

    // side stream + events for edge/proj overlap (created once; not during capture)
    static cudaStream_t s2 = 0;
    static cudaEvent_t evA = 0, evB = 0;
    static int tried = 0;
    if (!tried) {
        tried = 1;
        if (cudaStreamCreateWithFlags(&s2, cudaStreamNonBlocking) != cudaSuccess) s2 = 0;
        if (cudaEventCreateWithFlags(&evA, cudaEventDisableTiming) != cudaSuccess) evA = 0;
        if (cudaEventCreateWithFlags(&evB, cudaEventDisableTiming) != cudaSuccess) evB = 0;
    }
    bool useS2 = (s2 != 0) && (evA != 0) && (evB != 0);

    // 0: count  1: scan+proj(L0)  2: scatbias  3: attn(L0) <- profiled
    k_count<<<(e + 255) / 256, 256>>>(dst, e);
    k_scanproj<<<projBlocks + 1, 1024>>>(n, nodef, 0, Wq, Wk, Wv, 1);
    k_scatbias<<<(e + 127) / 128, 128>>>(src, dst, edgef, We, e);

    for (int i = 0; i < 3; i++) {
        if (i > 0) {
            k_scanproj<<<projBlocks, 1024>>>(n, nodef, 1,
                                             Wq + i * 4096, Wk + i * 4096, Wv + i * 4096, 0);
            if (useS2) cudaStreamWaitEvent(0, evB, 0);   // join edge(i-1) before attn(i)
        }
        k_attn<<<(n + 7) / 8, 256>>>(n);
        int last = (i == 2);
        k_lnnode<<<(n + 15) / 16, 512>>>(nodef, (i > 0),
                                         Wo + i * 4096, gn + i * 64, bn + i * 64,
                                         Wem + i * 5120, out, last, !last, n);
        if (!last) {
            if (useS2) {
                cudaEventRecord(evA, 0);
                cudaStreamWaitEvent(s2, evA, 0);
                k_edge<<<(e + 127) / 128, 128, 0, s2>>>(Wem + i * 5120 + 4096, bem + i * 32,
                                                        ge + i * 32, be + i * 32,
                                                        We + (i + 1) * 128,
                                                        src, dst, e, (i == 0) ? 1 : 0);
                cudaEventRecord(evB, s2);
            } else {
                k_edge<<<(e + 127) / 128, 128>>>(Wem + i * 5120 + 4096, bem + i * 32,
                                                 ge + i * 32, be + i * 32,
                                                 We + (i + 1) * 128,
                                                 src, dst, e, (i == 0) ? 1 : 0);
            }
        }
    }
}

// round 13
// speedup vs baseline: 1.5061x; 1.0181x over previous
#include <cuda_runtime.h>
#include <cuda_fp16.h>

#define NMAX 50000
#define EMAX 1600000

// ---------------- static device scratch ----------------
__device__ int    g_cnt[NMAX];         // zero at load; re-zeroed by scan each run
__device__ int    g_off[NMAX + 1];
__device__ int    g_cur[NMAX];
__device__ int    g_epk[EMAX];         // src node per CSR slot
__device__ int    g_slot[EMAX];        // edge id -> CSR slot
__device__ float  g_q[NMAX * 64];
__device__ __half g_kh[NMAX * 64];     // fp16 k
__device__ __half g_vh[NMAX * 64];     // fp16 v
__device__ float  g_agg[NMAX * 64];
__device__ float  g_h[NMAX * 64];
__device__ __half g_Ah[NMAX * 32];     // fp16 A = h @ Wem[0:64]
__device__ __half g_Bh[NMAX * 32];     // fp16 B = h @ Wem[64:128]
__device__ __half g_eh[EMAX * 32];     // fp16 edge features (in-place per layer)
__device__ float  g_bias[EMAX * 4];    // score bias in CSR-slot order

// ---------------- f32x2 packed helpers (sm_103a FFMA2 path) ----------------
__device__ __forceinline__ unsigned long long pk2(float a, float b) {
    unsigned long long r;
    asm("mov.b64 %0, {%1, %2};" : "=l"(r) : "f"(a), "f"(b));
    return r;
}
__device__ __forceinline__ void upk2(unsigned long long v, float& a, float& b) {
    asm("mov.b64 {%0, %1}, %2;" : "=f"(a), "=f"(b) : "l"(v));
}
__device__ __forceinline__ unsigned long long fma2(unsigned long long a,
                                                   unsigned long long b,
                                                   unsigned long long c) {
    unsigned long long d;
    asm("fma.rn.f32x2 %0, %1, %2, %3;" : "=l"(d) : "l"(a), "l"(b), "l"(c));
    return d;
}
__device__ __forceinline__ float tanh_approx(float x) {
    float y;
    asm("tanh.approx.f32 %0, %1;" : "=f"(y) : "f"(x));
    return y;
}

// ---------------- count ----------------
__global__ void k_count(const int* __restrict__ dst, int e) {
    int i = blockIdx.x * blockDim.x + threadIdx.x;
    if (i < e) atomicAdd(&g_cnt[dst[i]], 1);
}

// ---------------- fused: block0 = exclusive scan (+re-zero cnt), rest = qkv proj ----------------
__global__ void k_scanproj(int n, const float* __restrict__ hin, int useG,
                           const float* __restrict__ Wq, const float* __restrict__ Wk,
                           const float* __restrict__ Wv, int withScan) {
    __shared__ float sq[4096], sk[4096], sv[4096];
    __shared__ int swi[32];
    int t = threadIdx.x;
    if (withScan && blockIdx.x == 0) {
        int lane = t & 31, w = t >> 5;
        int carry = 0;
        for (int base = 0; base < n; base += 1024) {
            int i = base + t;
            int v = (i < n) ? g_cnt[i] : 0;
            if (i < n) g_cnt[i] = 0;              // reset for next run
            int x = v;
#pragma unroll
            for (int o = 1; o < 32; o <<= 1) {
                int y = __shfl_up_sync(0xffffffffu, x, o);
                if (lane >= o) x += y;
            }
            if (lane == 31) swi[w] = x;
            __syncthreads();
            if (t < 32) {
                int s = swi[t];
#pragma unroll
                for (int o = 1; o < 32; o <<= 1) {
                    int y = __shfl_up_sync(0xffffffffu, s, o);
                    if (t >= o) s += y;
                }
                swi[t] = s;
            }
            __syncthreads();
            int pref = (w > 0) ? swi[w - 1] : 0;
            int excl = carry + pref + x - v;
            if (i < n) { g_off[i] = excl; g_cur[i] = excl; }
            carry += swi[31];
            __syncthreads();
        }
        if (t == 0) g_off[n] = carry;
        return;
    }
    int bp = blockIdx.x - withScan;
    for (int i = t; i < 4096; i += 1024) { sq[i] = Wq[i]; sk[i] = Wk[i]; sv[i] = Wv[i]; }
    __syncthreads();
    const float* h = useG ? g_h : hin;
    int lane = t & 31, w = t >> 5;
    int r0 = (bp * 32 + w) * 4;
    float h0[4], h1[4];
#pragma unroll
    for (int r = 0; r < 4; r++) {
        int row = r0 + r;
        h0[r] = (row < n) ? h[row * 64 + lane] : 0.f;
        h1[r] = (row < n) ? h[row * 64 + lane + 32] : 0.f;
    }
    float aq0[4] = {0,0,0,0}, aq1[4] = {0,0,0,0};
    float ak0[4] = {0,0,0,0}, ak1[4] = {0,0,0,0};
    float av0[4] = {0,0,0,0}, av1[4] = {0,0,0,0};
#pragma unroll
    for (int j = 0; j < 32; j++) {
        float wq0 = sq[j * 64 + lane], wq1 = sq[j * 64 + lane + 32];
        float wk0 = sk[j * 64 + lane], wk1 = sk[j * 64 + lane + 32];
        float wv0 = sv[j * 64 + lane], wv1 = sv[j * 64 + lane + 32];
#pragma unroll
        for (int r = 0; r < 4; r++) {
            float hj = __shfl_sync(0xffffffffu, h0[r], j);
            aq0[r] += hj * wq0; aq1[r] += hj * wq1;
            ak0[r] += hj * wk0; ak1[r] += hj * wk1;
            av0[r] += hj * wv0; av1[r] += hj * wv1;
        }
    }
#pragma unroll
    for (int j = 0; j < 32; j++) {
        float wq0 = sq[(j + 32) * 64 + lane], wq1 = sq[(j + 32) * 64 + lane + 32];
        float wk0 = sk[(j + 32) * 64 + lane], wk1 = sk[(j + 32) * 64 + lane + 32];
        float wv0 = sv[(j + 32) * 64 + lane], wv1 = sv[(j + 32) * 64 + lane + 32];
#pragma unroll
        for (int r = 0; r < 4; r++) {
            float hj = __shfl_sync(0xffffffffu, h1[r], j);
            aq0[r] += hj * wq0; aq1[r] += hj * wq1;
            ak0[r] += hj * wk0; ak1[r] += hj * wk1;
            av0[r] += hj * wv0; av1[r] += hj * wv1;
        }
    }
#pragma unroll
    for (int r = 0; r < 4; r++) {
        int row = r0 + r;
        if (row >= n) break;
        g_q[row * 64 + lane] = aq0[r]; g_q[row * 64 + lane + 32] = aq1[r];
        g_kh[row * 64 + lane] = __float2half(ak0[r]);
        g_kh[row * 64 + lane + 32] = __float2half(ak1[r]);
        g_vh[row * 64 + lane] = __float2half(av0[r]);
        g_vh[row * 64 + lane + 32] = __float2half(av1[r]);
    }
}

// ---------------- fused scatter + layer-0 bias + fp16 e copy ----------------
__global__ void k_scatbias(const int* __restrict__ src, const int* __restrict__ dstp,
                           const float* __restrict__ ef, const float* __restrict__ We, int e) {
    __shared__ float sW[128];
    __shared__ float buf[4][32 * 33];
    int t = threadIdx.x;
    if (t < 128) sW[t] = We[t];
    __syncthreads();
    int w = t >> 5, lane = t & 31;
    int base = (blockIdx.x * 4 + w) * 32;
    float* b = buf[w];
    int ed0 = base + lane;
    int slot = -1;
    if (ed0 < e) {
        int d = __ldg(dstp + ed0);
        slot = atomicAdd(&g_cur[d], 1);
        g_epk[slot] = __ldg(src + ed0);
        g_slot[ed0] = slot;
    }
#pragma unroll 4
    for (int j = 0; j < 32; j++) {
        int ed = base + j;
        b[j * 33 + lane] = (ed < e) ? __ldg(ef + (size_t)ed * 32 + lane) : 0.f;
    }
    __syncwarp();
    // fp16 copy of e0 (edge layers read this instead of re-streaming edgef)
#pragma unroll 4
    for (int j = 0; j < 32; j++) {
        int ed = base + j;
        if (ed < e) g_eh[(size_t)ed * 32 + lane] = __float2half(b[j * 33 + lane]);
    }
    if (ed0 >= e) return;
    float4 bb = make_float4(0.f, 0.f, 0.f, 0.f);
#pragma unroll
    for (int k = 0; k < 32; k++) {
        float ek = b[lane * 33 + k];
        float4 wv = *(const float4*)(sW + k * 4);
        bb.x += ek * wv.x; bb.y += ek * wv.y; bb.z += ek * wv.z; bb.w += ek * wv.w;
    }
    ((float4*)g_bias)[slot] = bb;
}

// ---------------- attention: warp/node, unroll-4, fp16 k/v (R11 operating point) ----------------
__global__ void k_attn(int n) {
    int lane = threadIdx.x & 31;
    int node = blockIdx.x * 8 + (threadIdx.x >> 5);
    if (node >= n) return;
    int half = lane >> 4;
    int sub = lane & 15;
    int head = sub >> 2;
    int beg = g_off[node], end = g_off[node + 1];
    if (beg >= end) {
        if (half == 0)
            *(float4*)(g_agg + (size_t)node * 64 + sub * 4) = make_float4(0.f, 0.f, 0.f, 0.f);
        return;
    }
    float4 q4 = *(const float4*)(g_q + (size_t)node * 64 + sub * 4);
    q4.x *= 0.25f; q4.y *= 0.25f; q4.z *= 0.25f; q4.w *= 0.25f;
    float4 acc = make_float4(0.f, 0.f, 0.f, 0.f);
    float d = 0.f;
    for (int p = beg; p < end; p += 4) {
        int i0 = p + half;
        int i1 = p + 2 + half;
        bool u0 = (i0 < end), u1 = (i1 < end);
        int e0 = u0 ? i0 : beg;          // clamped reads stay in-bounds
        int e1 = u1 ? i1 : beg;
        int s0 = __ldg(&g_epk[e0]);
        int s1 = __ldg(&g_epk[e1]);
        uint2 kr0 = __ldg((const uint2*)(g_kh + (size_t)s0 * 64) + sub);
        uint2 kr1 = __ldg((const uint2*)(g_kh + (size_t)s1 * 64) + sub);
        uint2 vr0 = __ldg((const uint2*)(g_vh + (size_t)s0 * 64) + sub);
        uint2 vr1 = __ldg((const uint2*)(g_vh + (size_t)s1 * 64) + sub);
        float b0 = __ldg(g_bias + (size_t)e0 * 4 + head);
        float b1 = __ldg(g_bias + (size_t)e1 * 4 + head);
        float2 k0a = __half22float2(*(__half2*)&kr0.x);
        float2 k0b = __half22float2(*(__half2*)&kr0.y);
        float2 k1a = __half22float2(*(__half2*)&kr1.x);
        float2 k1b = __half22float2(*(__half2*)&kr1.y);
        float dt0 = q4.x * k0a.x + q4.y * k0a.y + q4.z * k0b.x + q4.w * k0b.y;
        float dt1 = q4.x * k1a.x + q4.y * k1a.y + q4.z * k1b.x + q4.w * k1b.y;
        dt0 += __shfl_xor_sync(0xffffffffu, dt0, 1);
        dt1 += __shfl_xor_sync(0xffffffffu, dt1, 1);
        dt0 += __shfl_xor_sync(0xffffffffu, dt0, 2);
        dt1 += __shfl_xor_sync(0xffffffffu, dt1, 2);
        float ex0 = u0 ? __expf(dt0 + b0) : 0.f;
        float ex1 = u1 ? __expf(dt1 + b1) : 0.f;
        d += ex0; d += ex1;
        float2 v0a = __half22float2(*(__half2*)&vr0.x);
        float2 v0b = __half22float2(*(__half2*)&vr0.y);
        float2 v1a = __half22float2(*(__half2*)&vr1.x);
        float2 v1b = __half22float2(*(__half2*)&vr1.y);
        acc.x += ex0 * v0a.x; acc.y += ex0 * v0a.y; acc.z += ex0 * v0b.x; acc.w += ex0 * v0b.y;
        acc.x += ex1 * v1a.x; acc.y += ex1 * v1a.y; acc.z += ex1 * v1b.x; acc.w += ex1 * v1b.y;
    }
    acc.x += __shfl_xor_sync(0xffffffffu, acc.x, 16);
    acc.y += __shfl_xor_sync(0xffffffffu, acc.y, 16);
    acc.z += __shfl_xor_sync(0xffffffffu, acc.z, 16);
    acc.w += __shfl_xor_sync(0xffffffffu, acc.w, 16);
    d     += __shfl_xor_sync(0xffffffffu, d, 16);
    if (half == 0) {
        float inv = 1.f / (d + 1e-9f);
        float4 o;
        o.x = acc.x * inv; o.y = acc.y * inv;
        o.z = acc.z * inv; o.w = acc.w * inv;
        *(float4*)(g_agg + (size_t)node * 64 + sub * 4) = o;
    }
}

// ---------------- node update (512 thr): h = LN(h + agg@Wo); fused fp16 A,B ----------------
__global__ void __launch_bounds__(512)
k_lnnode(const float* __restrict__ hin, int useGin,
         const float* __restrict__ Wo, const float* __restrict__ gn,
         const float* __restrict__ bn, const float* __restrict__ Wab,
         float* __restrict__ outp, int useOut, int doAB, int n) {
    __shared__ float sWo[4096];
    __shared__ float sAB[4096];
    for (int i = threadIdx.x; i < 4096; i += 512) {
        sWo[i] = Wo[i];
        if (doAB) sAB[i] = Wab[i];
    }
    __syncthreads();
    int lane = threadIdx.x & 31, w = threadIdx.x >> 5;
    int row = blockIdx.x * 16 + w;
    if (row >= n) return;
    const float* h = useGin ? g_h : hin;
    float a0 = g_agg[row * 64 + lane], a1 = g_agg[row * 64 + lane + 32];
    float o0 = 0.f, o1 = 0.f;
#pragma unroll
    for (int j = 0; j < 32; j++) {
        float aj = __shfl_sync(0xffffffffu, a0, j);
        o0 += aj * sWo[j * 64 + lane];
        o1 += aj * sWo[j * 64 + lane + 32];
    }
#pragma unroll
    for (int j = 0; j < 32; j++) {
        float aj = __shfl_sync(0xffffffffu, a1, j);
        o0 += aj * sWo[(j + 32) * 64 + lane];
        o1 += aj * sWo[(j + 32) * 64 + lane + 32];
    }
    float x0 = h[row * 64 + lane] + o0;
    float x1 = h[row * 64 + lane + 32] + o1;
    float s = x0 + x1;
#pragma unroll
    for (int o = 16; o; o >>= 1) s += __shfl_xor_sync(0xffffffffu, s, o);
    float mu = s * (1.f / 64.f);
    float d0 = x0 - mu, d1 = x1 - mu;
    float vs = d0 * d0 + d1 * d1;
#pragma unroll
    for (int o = 16; o; o >>= 1) vs += __shfl_xor_sync(0xffffffffu, vs, o);
    float inv = rsqrtf(vs * (1.f / 64.f) + 1e-5f);
    float y0 = d0 * inv * __ldg(gn + lane) + __ldg(bn + lane);
    float y1 = d1 * inv * __ldg(gn + lane + 32) + __ldg(bn + lane + 32);
    float* hp = useOut ? outp : g_h;
    hp[row * 64 + lane] = y0;
    hp[row * 64 + lane + 32] = y1;
    if (doAB) {
        float A = 0.f, B = 0.f;
#pragma unroll
        for (int j = 0; j < 32; j++) {
            float yj = __shfl_sync(0xffffffffu, y0, j);
            A += yj * sAB[j * 32 + lane];
            B += yj * sAB[(j + 64) * 32 + lane];
        }
#pragma unroll
        for (int j = 0; j < 32; j++) {
            float yj = __shfl_sync(0xffffffffu, y1, j);
            A += yj * sAB[(j + 32) * 32 + lane];
            B += yj * sAB[(j + 96) * 32 + lane];
        }
        g_Ah[row * 32 + lane] = __float2half(A);
        g_Bh[row * 32 + lane] = __float2half(B);
    }
}

// ---------------- edge update: vectorized fp16 staging, low-reg, f32x2 GEMM ----------------
__global__ void __launch_bounds__(128)
k_edge(const float* __restrict__ Wem2, const float* __restrict__ bem,
       const float* __restrict__ ge, const float* __restrict__ be,
       const float* __restrict__ WeN,
       const int* __restrict__ src, const int* __restrict__ dstp,
       int e, int storeE) {
    __shared__ float sW[1024];
    __shared__ float sWeN[128];
    __shared__ float sbem[32], sge[32], sbe[32];
    __shared__ uint2 bufA[4][32 * 9];
    __shared__ uint2 bufB[4][32 * 9];
    __shared__ uint2 bufH[4][32 * 9];
    int t = threadIdx.x;
    for (int i = t; i < 1024; i += 128) sW[i] = Wem2[i];
    if (t < 128) sWeN[t] = WeN[t];
    if (t < 32) { sbem[t] = bem[t]; sge[t] = ge[t]; sbe[t] = be[t]; }
    __syncthreads();
    int w = t >> 5, lane = t & 31;
    int base = (blockIdx.x * 4 + w) * 32;
    uint2* bA = bufA[w];
    uint2* bB = bufB[w];
    uint2* bH = bufH[w];
    const __half* eHalf = (const __half*)bH;   // lane's e row k at [lane*36+k]
    const __half* aHalf = (const __half*)bA;
    const __half* bHalf = (const __half*)bB;

    // ---- stage e rows: 8 x LDG.64 per warp (4 halves/lane) ----
    int lrow = lane >> 3, lidx = lane & 7;
#pragma unroll
    for (int j = 0; j < 8; j++) {
        int r = j * 4 + lrow;
        int ed = base + r;
        uint2 v = make_uint2(0u, 0u);
        if (ed < e) v = __ldg((const uint2*)(g_eh + (size_t)ed * 32) + lidx);
        bH[r * 9 + lidx] = v;
    }

    int ed0 = base + lane;
    int s_l = (ed0 < e) ? __ldg(src + ed0)  : 0;
    int d_l = (ed0 < e) ? __ldg(dstp + ed0) : 0;

    // ---- stage fp16 A[src], B[dst]: 4 rows/iter via uint2 (LDG.64) ----
#pragma unroll
    for (int j8 = 0; j8 < 8; j8++) {
        int r = j8 * 4 + lrow;
        int sj = __shfl_sync(0xffffffffu, s_l, r);
        int dj = __shfl_sync(0xffffffffu, d_l, r);
        bA[r * 9 + lidx] = __ldg((const uint2*)(g_Ah + (size_t)sj * 32) + lidx);
        bB[r * 9 + lidx] = __ldg((const uint2*)(g_Bh + (size_t)dj * 32) + lidx);
    }
    __syncwarp();

    float acc[32];
#pragma unroll
    for (int k = 0; k < 32; k++)
        acc[k] = __half2float(aHalf[lane * 36 + k]) + __half2float(bHalf[lane * 36 + k]) + sbem[k];

    // ---- e @ Wem2 on packed f32x2; e-values read from smem (no er regs) ----
    unsigned long long acc2[16];
#pragma unroll
    for (int j = 0; j < 16; j++) acc2[j] = pk2(acc[2 * j], acc[2 * j + 1]);
#pragma unroll
    for (int k = 0; k < 32; k++) {
        float ek = __half2float(eHalf[lane * 36 + k]);
        unsigned long long ek2 = pk2(ek, ek);
        const ulonglong2* wr = (const ulonglong2*)(sW + k * 32);
#pragma unroll
        for (int j = 0; j < 8; j++) {
            ulonglong2 ww = wr[j];
            acc2[2 * j]     = fma2(ek2, ww.x, acc2[2 * j]);
            acc2[2 * j + 1] = fma2(ek2, ww.y, acc2[2 * j + 1]);
        }
    }
#pragma unroll
    for (int j = 0; j < 16; j++) upk2(acc2[j], acc[2 * j], acc[2 * j + 1]);

    // ---- gelu (tanh.approx) + residual + LN (residual re-read from smem) ----
    float mu = 0.f;
#pragma unroll
    for (int j = 0; j < 32; j++) {
        float u = acc[j];
        float z = 0.7978845608028654f * (u + 0.044715f * u * u * u);
        float x = __half2float(eHalf[lane * 36 + j]) + 0.5f * u * (1.f + tanh_approx(z));
        acc[j] = x;
        mu += x;
    }
    mu *= (1.f / 32.f);
    float var = 0.f;
#pragma unroll
    for (int j = 0; j < 32; j++) { float dx = acc[j] - mu; var += dx * dx; }
    float inv = rsqrtf(var * (1.f / 32.f) + 1e-5f);
    float4 bb = make_float4(0.f, 0.f, 0.f, 0.f);
#pragma unroll
    for (int j = 0; j < 32; j++) {
        float y = (acc[j] - mu) * inv * sge[j] + sbe[j];
        acc[j] = y;
        float4 wv = *(const float4*)(sWeN + j * 4);
        bb.x += y * wv.x; bb.y += y * wv.y; bb.z += y * wv.z; bb.w += y * wv.w;
    }
    if (ed0 < e) {
        int slot = __ldg(g_slot + ed0);
        ((float4*)g_bias)[slot] = bb;
    }
    if (storeE) {
        __syncwarp();
#pragma unroll
        for (int k = 0; k < 8; k++) {
            __half2 h0 = __floats2half2_rn(acc[k * 4 + 0], acc[k * 4 + 1]);
            __half2 h1 = __floats2half2_rn(acc[k * 4 + 2], acc[k * 4 + 3]);
            uint2 v;
            v.x = *(unsigned*)&h0;
            v.y = *(unsigned*)&h1;
            bH[lane * 9 + k] = v;
        }
        __syncwarp();
#pragma unroll
        for (int j = 0; j < 8; j++) {
            int r = j * 4 + lrow;
            int ed = base + r;
            if (ed < e)
                *((uint2*)(g_eh + (size_t)ed * 32) + lidx) = bH[r * 9 + lidx];
        }
    }
}

// ---------------- launch ----------------
extern "C" void kernel_launch(void* const* d_in, const int* in_sizes, int n_in,
                              void* d_out, int out_size) {
    const float* nodef = (const float*)d_in[0];
    const float* edgef = (const float*)d_in[1];
    const int*   ei    = (const int*)d_in[2];
    const float* Wq    = (const float*)d_in[3];
    const float* Wk    = (const float*)d_in[4];
    const float* Wv    = (const float*)d_in[5];
    const float* Wo    = (const float*)d_in[6];
    const float* We    = (const float*)d_in[7];
    const float* Wem   = (const float*)d_in[8];
    const float* bem   = (const float*)d_in[9];
    const float* gn    = (const float*)d_in[10];
    const float* bn    = (const float*)d_in[11];
    const float* ge    = (const float*)d_in[12];
    const float* be    = (const float*)d_in[13];
    float* out = (float*)d_out;

    int n = in_sizes[0] / 64;
    int e = in_sizes[1] / 32;
    const int* src = ei;
    const int* dst = ei + e;
    int projBlocks = (n + 127) / 128;

    // side stream + events for edge/proj overlap (created once; not during capture)
    static cudaStream_t s2 = 0;
    static cudaEvent_t evA = 0, evB = 0;
    static int tried = 0;
    if (!tried) {
        tried = 1;
        if (cudaStreamCreateWithFlags(&s2, cudaStreamNonBlocking) != cudaSuccess) s2 = 0;
        if (cudaEventCreateWithFlags(&evA, cudaEventDisableTiming) != cudaSuccess) evA = 0;
        if (cudaEventCreateWithFlags(&evB, cudaEventDisableTiming) != cudaSuccess) evB = 0;
    }
    bool useS2 = (s2 != 0) && (evA != 0) && (evB != 0);

    // 0: count  1: scan+proj(L0)  2: scatbias  3: attn(L0) <- profiled
    k_count<<<(e + 255) / 256, 256>>>(dst, e);
    k_scanproj<<<projBlocks + 1, 1024>>>(n, nodef, 0, Wq, Wk, Wv, 1);
    k_scatbias<<<(e + 127) / 128, 128>>>(src, dst, edgef, We, e);

    for (int i = 0; i < 3; i++) {
        if (i > 0) {
            k_scanproj<<<projBlocks, 1024>>>(n, nodef, 1,
                                             Wq + i * 4096, Wk + i * 4096, Wv + i * 4096, 0);
            if (useS2) cudaStreamWaitEvent(0, evB, 0);   // join edge(i-1) before attn(i)
        }
        k_attn<<<(n + 7) / 8, 256>>>(n);
        int last = (i == 2);
        k_lnnode<<<(n + 15) / 16, 512>>>(nodef, (i > 0),
                                         Wo + i * 4096, gn + i * 64, bn + i * 64,
                                         Wem + i * 5120, out, last, !last, n);
        if (!last) {
            if (useS2) {
                cudaEventRecord(evA, 0);
                cudaStreamWaitEvent(s2, evA, 0);
                k_edge<<<(e + 127) / 128, 128, 0, s2>>>(Wem + i * 5120 + 4096, bem + i * 32,
                                                        ge + i * 32, be + i * 32,
                                                        We + (i + 1) * 128,
                                                        src, dst, e, (i == 0) ? 1 : 0);
                cudaEventRecord(evB, s2);
            } else {
                k_edge<<<(e + 127) / 128, 128>>>(Wem + i * 5120 + 4096, bem + i * 32,
                                                 ge + i * 32, be + i * 32,
                                                 We + (i + 1) * 128,
                                                 src, dst, e, (i == 0) ? 1 : 0);
            }
        }
    }
}

// round 14
// speedup vs baseline: 1.5965x; 1.0600x over previous
#include <cuda_runtime.h>
#include <cuda_fp16.h>

#define NMAX 50000
#define EMAX 1600000

// ---------------- static device scratch ----------------
__device__ int    g_cnt[NMAX];
__device__ int    g_off[NMAX + 1];
__device__ int    g_cur[NMAX];
__device__ int    g_epk[EMAX];         // src node per CSR slot
__device__ int    g_slot[EMAX];        // edge id -> CSR slot
__device__ float  g_q[NMAX * 64];
__device__ __half g_kh[NMAX * 64];
__device__ __half g_vh[NMAX * 64];
__device__ float  g_agg[NMAX * 64];
__device__ float  g_h[NMAX * 64];
__device__ __half g_Ah[NMAX * 32];
__device__ __half g_Bh[NMAX * 32];
__device__ __half g_eh[EMAX * 32];
__device__ float  g_bias[EMAX * 4];

// ---------------- helpers ----------------
__device__ __forceinline__ float tanh_approx(float x) {
    float y;
    asm("tanh.approx.f32 %0, %1;" : "=f"(y) : "f"(x));
    return y;
}
__device__ __forceinline__ unsigned s2u(const void* p) {
    return (unsigned)__cvta_generic_to_shared(p);
}
__device__ __forceinline__ void ldsm4(unsigned& r0, unsigned& r1, unsigned& r2, unsigned& r3,
                                      unsigned addr) {
    asm volatile("ldmatrix.sync.aligned.m8n8.x4.shared.b16 {%0,%1,%2,%3}, [%4];"
                 : "=r"(r0), "=r"(r1), "=r"(r2), "=r"(r3) : "r"(addr));
}
__device__ __forceinline__ void ldsm4t(unsigned& r0, unsigned& r1, unsigned& r2, unsigned& r3,
                                       unsigned addr) {
    asm volatile("ldmatrix.sync.aligned.m8n8.x4.trans.shared.b16 {%0,%1,%2,%3}, [%4];"
                 : "=r"(r0), "=r"(r1), "=r"(r2), "=r"(r3) : "r"(addr));
}
__device__ __forceinline__ void mma16816(float& d0, float& d1, float& d2, float& d3,
                                         unsigned a0, unsigned a1, unsigned a2, unsigned a3,
                                         unsigned b0, unsigned b1) {
    asm volatile("mma.sync.aligned.m16n8k16.row.col.f32.f16.f16.f32 "
                 "{%0,%1,%2,%3}, {%4,%5,%6,%7}, {%8,%9}, {%0,%1,%2,%3};"
                 : "+f"(d0), "+f"(d1), "+f"(d2), "+f"(d3)
                 : "r"(a0), "r"(a1), "r"(a2), "r"(a3), "r"(b0), "r"(b1));
}

// ---------------- count ----------------
__global__ void k_count(const int* __restrict__ dst, int e) {
    int i = blockIdx.x * blockDim.x + threadIdx.x;
    if (i < e) atomicAdd(&g_cnt[dst[i]], 1);
}

// ---------------- fused: block0 = exclusive scan (+re-zero cnt), rest = qkv proj ----------------
__global__ void k_scanproj(int n, const float* __restrict__ hin, int useG,
                           const float* __restrict__ Wq, const float* __restrict__ Wk,
                           const float* __restrict__ Wv, int withScan) {
    __shared__ float sq[4096], sk[4096], sv[4096];
    __shared__ int swi[32];
    int t = threadIdx.x;
    if (withScan && blockIdx.x == 0) {
        int lane = t & 31, w = t >> 5;
        int carry = 0;
        for (int base = 0; base < n; base += 1024) {
            int i = base + t;
            int v = (i < n) ? g_cnt[i] : 0;
            if (i < n) g_cnt[i] = 0;
            int x = v;
#pragma unroll
            for (int o = 1; o < 32; o <<= 1) {
                int y = __shfl_up_sync(0xffffffffu, x, o);
                if (lane >= o) x += y;
            }
            if (lane == 31) swi[w] = x;
            __syncthreads();
            if (t < 32) {
                int s = swi[t];
#pragma unroll
                for (int o = 1; o < 32; o <<= 1) {
                    int y = __shfl_up_sync(0xffffffffu, s, o);
                    if (t >= o) s += y;
                }
                swi[t] = s;
            }
            __syncthreads();
            int pref = (w > 0) ? swi[w - 1] : 0;
            int excl = carry + pref + x - v;
            if (i < n) { g_off[i] = excl; g_cur[i] = excl; }
            carry += swi[31];
            __syncthreads();
        }
        if (t == 0) g_off[n] = carry;
        return;
    }
    int bp = blockIdx.x - withScan;
    for (int i = t; i < 4096; i += 1024) { sq[i] = Wq[i]; sk[i] = Wk[i]; sv[i] = Wv[i]; }
    __syncthreads();
    const float* h = useG ? g_h : hin;
    int lane = t & 31, w = t >> 5;
    int r0 = (bp * 32 + w) * 4;
    float h0[4], h1[4];
#pragma unroll
    for (int r = 0; r < 4; r++) {
        int row = r0 + r;
        h0[r] = (row < n) ? h[row * 64 + lane] : 0.f;
        h1[r] = (row < n) ? h[row * 64 + lane + 32] : 0.f;
    }
    float aq0[4] = {0,0,0,0}, aq1[4] = {0,0,0,0};
    float ak0[4] = {0,0,0,0}, ak1[4] = {0,0,0,0};
    float av0[4] = {0,0,0,0}, av1[4] = {0,0,0,0};
#pragma unroll
    for (int j = 0; j < 32; j++) {
        float wq0 = sq[j * 64 + lane], wq1 = sq[j * 64 + lane + 32];
        float wk0 = sk[j * 64 + lane], wk1 = sk[j * 64 + lane + 32];
        float wv0 = sv[j * 64 + lane], wv1 = sv[j * 64 + lane + 32];
#pragma unroll
        for (int r = 0; r < 4; r++) {
            float hj = __shfl_sync(0xffffffffu, h0[r], j);
            aq0[r] += hj * wq0; aq1[r] += hj * wq1;
            ak0[r] += hj * wk0; ak1[r] += hj * wk1;
            av0[r] += hj * wv0; av1[r] += hj * wv1;
        }
    }
#pragma unroll
    for (int j = 0; j < 32; j++) {
        float wq0 = sq[(j + 32) * 64 + lane], wq1 = sq[(j + 32) * 64 + lane + 32];
        float wk0 = sk[(j + 32) * 64 + lane], wk1 = sk[(j + 32) * 64 + lane + 32];
        float wv0 = sv[(j + 32) * 64 + lane], wv1 = sv[(j + 32) * 64 + lane + 32];
#pragma unroll
        for (int r = 0; r < 4; r++) {
            float hj = __shfl_sync(0xffffffffu, h1[r], j);
            aq0[r] += hj * wq0; aq1[r] += hj * wq1;
            ak0[r] += hj * wk0; ak1[r] += hj * wk1;
            av0[r] += hj * wv0; av1[r] += hj * wv1;
        }
    }
#pragma unroll
    for (int r = 0; r < 4; r++) {
        int row = r0 + r;
        if (row >= n) break;
        g_q[row * 64 + lane] = aq0[r]; g_q[row * 64 + lane + 32] = aq1[r];
        g_kh[row * 64 + lane] = __float2half(ak0[r]);
        g_kh[row * 64 + lane + 32] = __float2half(ak1[r]);
        g_vh[row * 64 + lane] = __float2half(av0[r]);
        g_vh[row * 64 + lane + 32] = __float2half(av1[r]);
    }
}

// ---------------- fused scatter + layer-0 bias + fp16 e copy ----------------
__global__ void k_scatbias(const int* __restrict__ src, const int* __restrict__ dstp,
                           const float* __restrict__ ef, const float* __restrict__ We, int e) {
    __shared__ float sW[128];
    __shared__ float buf[4][32 * 33];
    int t = threadIdx.x;
    if (t < 128) sW[t] = We[t];
    __syncthreads();
    int w = t >> 5, lane = t & 31;
    int base = (blockIdx.x * 4 + w) * 32;
    float* b = buf[w];
    int ed0 = base + lane;
    int slot = -1;
    if (ed0 < e) {
        int d = __ldg(dstp + ed0);
        slot = atomicAdd(&g_cur[d], 1);
        g_epk[slot] = __ldg(src + ed0);
        g_slot[ed0] = slot;
    }
#pragma unroll 4
    for (int j = 0; j < 32; j++) {
        int ed = base + j;
        b[j * 33 + lane] = (ed < e) ? __ldg(ef + (size_t)ed * 32 + lane) : 0.f;
    }
    __syncwarp();
#pragma unroll 4
    for (int j = 0; j < 32; j++) {
        int ed = base + j;
        if (ed < e) g_eh[(size_t)ed * 32 + lane] = __float2half(b[j * 33 + lane]);
    }
    if (ed0 >= e) return;
    float4 bb = make_float4(0.f, 0.f, 0.f, 0.f);
#pragma unroll
    for (int k = 0; k < 32; k++) {
        float ek = b[lane * 33 + k];
        float4 wv = *(const float4*)(sW + k * 4);
        bb.x += ek * wv.x; bb.y += ek * wv.y; bb.z += ek * wv.z; bb.w += ek * wv.w;
    }
    ((float4*)g_bias)[slot] = bb;
}

// ---------------- attention: warp/node, unroll-4, fp16 k/v ----------------
__global__ void k_attn(int n) {
    int lane = threadIdx.x & 31;
    int node = blockIdx.x * 8 + (threadIdx.x >> 5);
    if (node >= n) return;
    int half = lane >> 4;
    int sub = lane & 15;
    int head = sub >> 2;
    int beg = g_off[node], end = g_off[node + 1];
    if (beg >= end) {
        if (half == 0)
            *(float4*)(g_agg + (size_t)node * 64 + sub * 4) = make_float4(0.f, 0.f, 0.f, 0.f);
        return;
    }
    float4 q4 = *(const float4*)(g_q + (size_t)node * 64 + sub * 4);
    q4.x *= 0.25f; q4.y *= 0.25f; q4.z *= 0.25f; q4.w *= 0.25f;
    float4 acc = make_float4(0.f, 0.f, 0.f, 0.f);
    float d = 0.f;
    for (int p = beg; p < end; p += 4) {
        int i0 = p + half;
        int i1 = p + 2 + half;
        bool u0 = (i0 < end), u1 = (i1 < end);
        int e0 = u0 ? i0 : beg;
        int e1 = u1 ? i1 : beg;
        int s0 = __ldg(&g_epk[e0]);
        int s1 = __ldg(&g_epk[e1]);
        uint2 kr0 = __ldg((const uint2*)(g_kh + (size_t)s0 * 64) + sub);
        uint2 kr1 = __ldg((const uint2*)(g_kh + (size_t)s1 * 64) + sub);
        uint2 vr0 = __ldg((const uint2*)(g_vh + (size_t)s0 * 64) + sub);
        uint2 vr1 = __ldg((const uint2*)(g_vh + (size_t)s1 * 64) + sub);
        float b0 = __ldg(g_bias + (size_t)e0 * 4 + head);
        float b1 = __ldg(g_bias + (size_t)e1 * 4 + head);
        float2 k0a = __half22float2(*(__half2*)&kr0.x);
        float2 k0b = __half22float2(*(__half2*)&kr0.y);
        float2 k1a = __half22float2(*(__half2*)&kr1.x);
        float2 k1b = __half22float2(*(__half2*)&kr1.y);
        float dt0 = q4.x * k0a.x + q4.y * k0a.y + q4.z * k0b.x + q4.w * k0b.y;
        float dt1 = q4.x * k1a.x + q4.y * k1a.y + q4.z * k1b.x + q4.w * k1b.y;
        dt0 += __shfl_xor_sync(0xffffffffu, dt0, 1);
        dt1 += __shfl_xor_sync(0xffffffffu, dt1, 1);
        dt0 += __shfl_xor_sync(0xffffffffu, dt0, 2);
        dt1 += __shfl_xor_sync(0xffffffffu, dt1, 2);
        float ex0 = u0 ? __expf(dt0 + b0) : 0.f;
        float ex1 = u1 ? __expf(dt1 + b1) : 0.f;
        d += ex0; d += ex1;
        float2 v0a = __half22float2(*(__half2*)&vr0.x);
        float2 v0b = __half22float2(*(__half2*)&vr0.y);
        float2 v1a = __half22float2(*(__half2*)&vr1.x);
        float2 v1b = __half22float2(*(__half2*)&vr1.y);
        acc.x += ex0 * v0a.x; acc.y += ex0 * v0a.y; acc.z += ex0 * v0b.x; acc.w += ex0 * v0b.y;
        acc.x += ex1 * v1a.x; acc.y += ex1 * v1a.y; acc.z += ex1 * v1b.x; acc.w += ex1 * v1b.y;
    }
    acc.x += __shfl_xor_sync(0xffffffffu, acc.x, 16);
    acc.y += __shfl_xor_sync(0xffffffffu, acc.y, 16);
    acc.z += __shfl_xor_sync(0xffffffffu, acc.z, 16);
    acc.w += __shfl_xor_sync(0xffffffffu, acc.w, 16);
    d     += __shfl_xor_sync(0xffffffffu, d, 16);
    if (half == 0) {
        float inv = 1.f / (d + 1e-9f);
        float4 o;
        o.x = acc.x * inv; o.y = acc.y * inv;
        o.z = acc.z * inv; o.w = acc.w * inv;
        *(float4*)(g_agg + (size_t)node * 64 + sub * 4) = o;
    }
}

// ---------------- node update (512 thr): h = LN(h + agg@Wo); fused fp16 A,B ----------------
__global__ void __launch_bounds__(512)
k_lnnode(const float* __restrict__ hin, int useGin,
         const float* __restrict__ Wo, const float* __restrict__ gn,
         const float* __restrict__ bn, const float* __restrict__ Wab,
         float* __restrict__ outp, int useOut, int doAB, int n) {
    __shared__ float sWo[4096];
    __shared__ float sAB[4096];
    for (int i = threadIdx.x; i < 4096; i += 512) {
        sWo[i] = Wo[i];
        if (doAB) sAB[i] = Wab[i];
    }
    __syncthreads();
    int lane = threadIdx.x & 31, w = threadIdx.x >> 5;
    int row = blockIdx.x * 16 + w;
    if (row >= n) return;
    const float* h = useGin ? g_h : hin;
    float a0 = g_agg[row * 64 + lane], a1 = g_agg[row * 64 + lane + 32];
    float o0 = 0.f, o1 = 0.f;
#pragma unroll
    for (int j = 0; j < 32; j++) {
        float aj = __shfl_sync(0xffffffffu, a0, j);
        o0 += aj * sWo[j * 64 + lane];
        o1 += aj * sWo[j * 64 + lane + 32];
    }
#pragma unroll
    for (int j = 0; j < 32; j++) {
        float aj = __shfl_sync(0xffffffffu, a1, j);
        o0 += aj * sWo[(j + 32) * 64 + lane];
        o1 += aj * sWo[(j + 32) * 64 + lane + 32];
    }
    float x0 = h[row * 64 + lane] + o0;
    float x1 = h[row * 64 + lane + 32] + o1;
    float s = x0 + x1;
#pragma unroll
    for (int o = 16; o; o >>= 1) s += __shfl_xor_sync(0xffffffffu, s, o);
    float mu = s * (1.f / 64.f);
    float d0 = x0 - mu, d1 = x1 - mu;
    float vs = d0 * d0 + d1 * d1;
#pragma unroll
    for (int o = 16; o; o >>= 1) vs += __shfl_xor_sync(0xffffffffu, vs, o);
    float inv = rsqrtf(vs * (1.f / 64.f) + 1e-5f);
    float y0 = d0 * inv * __ldg(gn + lane) + __ldg(bn + lane);
    float y1 = d1 * inv * __ldg(gn + lane + 32) + __ldg(bn + lane + 32);
    float* hp = useOut ? outp : g_h;
    hp[row * 64 + lane] = y0;
    hp[row * 64 + lane + 32] = y1;
    if (doAB) {
        float A = 0.f, B = 0.f;
#pragma unroll
        for (int j = 0; j < 32; j++) {
            float yj = __shfl_sync(0xffffffffu, y0, j);
            A += yj * sAB[j * 32 + lane];
            B += yj * sAB[(j + 64) * 32 + lane];
        }
#pragma unroll
        for (int j = 0; j < 32; j++) {
            float yj = __shfl_sync(0xffffffffu, y1, j);
            A += yj * sAB[(j + 32) * 32 + lane];
            B += yj * sAB[(j + 96) * 32 + lane];
        }
        g_Ah[row * 32 + lane] = __float2half(A);
        g_Bh[row * 32 + lane] = __float2half(B);
    }
}

// ---------------- edge update: tensor-core (mma.m16n8k16) GEMM + quad epilogue ----------------
// Per warp: 32 edges. X = e-tile [32x32] fp16 in smem (80B row stride, ldmatrix-aligned).
// Y = (A[src]+B[dst]+bem) + X @ W  via 16 HMMA; then gelu+residual+LN+bias per row
// with quad (4-lane) reductions.
__global__ void __launch_bounds__(128)
k_edge(const float* __restrict__ Wem2, const float* __restrict__ bem,
       const float* __restrict__ ge, const float* __restrict__ be,
       const float* __restrict__ WeN,
       const int* __restrict__ src, const int* __restrict__ dstp,
       int e, int storeE) {
    __shared__ __align__(16) __half sWh[1024];     // W fp16 row-major [k][n] 32x32
    __shared__ float sWeN[128];
    __shared__ float sbem[32], sge[32], sbe[32];
    __shared__ uint2 bufA[4][32 * 9];              // A rows, 36-half stride
    __shared__ uint2 bufB[4][32 * 9];
    __shared__ __align__(16) uint2 bufH[4][32 * 10]; // e rows, 40-half (80B) stride
    int t = threadIdx.x;
    for (int i = t; i < 1024; i += 128) sWh[i] = __float2half(Wem2[i]);
    if (t < 128) sWeN[t] = WeN[t];
    if (t < 32) { sbem[t] = bem[t]; sge[t] = ge[t]; sbe[t] = be[t]; }
    __syncthreads();
    int w = t >> 5, lane = t & 31;
    int base = (blockIdx.x * 4 + w) * 32;
    uint2* bA = bufA[w];
    uint2* bB = bufB[w];
    uint2* bH = bufH[w];
    __half* eH = (__half*)bH;                       // row r col k at [r*40+k]
    const __half* aHalf = (const __half*)bA;        // [r*36+k]
    const __half* bHalf = (const __half*)bB;

    // ---- stage e rows (8 x LDG.64 per warp, 4 rows/iter) ----
    int lrow = lane >> 3, lidx = lane & 7;
#pragma unroll
    for (int j = 0; j < 8; j++) {
        int r = j * 4 + lrow;
        int ed = base + r;
        uint2 v = make_uint2(0u, 0u);
        if (ed < e) v = __ldg((const uint2*)(g_eh + (size_t)ed * 32) + lidx);
        bH[r * 10 + lidx] = v;
    }

    int ed0 = base + lane;
    int s_l = (ed0 < e) ? __ldg(src + ed0)   : 0;
    int d_l = (ed0 < e) ? __ldg(dstp + ed0)  : 0;
    int slot_l = (ed0 < e) ? __ldg(g_slot + ed0) : 0;

    // ---- stage fp16 A[src], B[dst]: 4 rows/iter via LDG.64 ----
#pragma unroll
    for (int j8 = 0; j8 < 8; j8++) {
        int r = j8 * 4 + lrow;
        int sj = __shfl_sync(0xffffffffu, s_l, r);
        int dj = __shfl_sync(0xffffffffu, d_l, r);
        bA[r * 9 + lidx] = __ldg((const uint2*)(g_Ah + (size_t)sj * 32) + lidx);
        bB[r * 9 + lidx] = __ldg((const uint2*)(g_Bh + (size_t)dj * 32) + lidx);
    }
    __syncwarp();

    int g = lane >> 2, t4 = lane & 3;

    // ---- load A fragments (X) via ldmatrix x4: [mt][kt] ----
    unsigned Af[2][2][4];
    {
        int q = lane >> 3, i = lane & 7;
#pragma unroll
        for (int mt = 0; mt < 2; mt++)
#pragma unroll
            for (int kt = 0; kt < 2; kt++) {
                int row = mt * 16 + (q & 1) * 8 + i;
                int hcol = kt * 16 + (q >> 1) * 8;
                unsigned addr = s2u(eH + row * 40 + hcol);
                ldsm4(Af[mt][kt][0], Af[mt][kt][1], Af[mt][kt][2], Af[mt][kt][3], addr);
            }
    }
    // ---- load B fragments (W) via ldmatrix x4 trans: [kt][nt][2] ----
    unsigned Bf[2][4][2];
    {
        int q = lane >> 3, i = lane & 7;
#pragma unroll
        for (int kt = 0; kt < 2; kt++)
#pragma unroll
            for (int p = 0; p < 2; p++) {
                int krow = kt * 16 + (q & 1) * 8 + i;
                int ncol = p * 16 + (q >> 1) * 8;
                unsigned addr = s2u(sWh + krow * 32 + ncol);
                unsigned r0, r1, r2, r3;
                ldsm4t(r0, r1, r2, r3, addr);
                Bf[kt][2 * p][0] = r0;     Bf[kt][2 * p][1] = r1;
                Bf[kt][2 * p + 1][0] = r2; Bf[kt][2 * p + 1][1] = r3;
            }
    }

    // ---- init C = A[src]+B[dst]+bem in mma layout, then 16 HMMA ----
    float d[2][4][4];
#pragma unroll
    for (int mt = 0; mt < 2; mt++)
#pragma unroll
        for (int nt = 0; nt < 4; nt++) {
            int c = nt * 8 + 2 * t4;
            int r0 = mt * 16 + g, r1 = r0 + 8;
            float2 a0 = __half22float2(*(const __half2*)(aHalf + r0 * 36 + c));
            float2 b0 = __half22float2(*(const __half2*)(bHalf + r0 * 36 + c));
            float2 a1 = __half22float2(*(const __half2*)(aHalf + r1 * 36 + c));
            float2 b1 = __half22float2(*(const __half2*)(bHalf + r1 * 36 + c));
            float m0 = sbem[c], m1 = sbem[c + 1];
            d[mt][nt][0] = a0.x + b0.x + m0;
            d[mt][nt][1] = a0.y + b0.y + m1;
            d[mt][nt][2] = a1.x + b1.x + m0;
            d[mt][nt][3] = a1.y + b1.y + m1;
        }
#pragma unroll
    for (int mt = 0; mt < 2; mt++)
#pragma unroll
        for (int nt = 0; nt < 4; nt++) {
            mma16816(d[mt][nt][0], d[mt][nt][1], d[mt][nt][2], d[mt][nt][3],
                     Af[mt][0][0], Af[mt][0][1], Af[mt][0][2], Af[mt][0][3],
                     Bf[0][nt][0], Bf[0][nt][1]);
            mma16816(d[mt][nt][0], d[mt][nt][1], d[mt][nt][2], d[mt][nt][3],
                     Af[mt][1][0], Af[mt][1][1], Af[mt][1][2], Af[mt][1][3],
                     Bf[1][nt][0], Bf[1][nt][1]);
        }

    // ---- epilogue: per owned row (g, g+8, 16+g, 24+g): gelu+residual+LN+bias ----
#pragma unroll
    for (int mt = 0; mt < 2; mt++)
#pragma unroll
        for (int hb = 0; hb < 2; hb++) {
            int row = mt * 16 + hb * 8 + g;
            float x[8];
            float mu = 0.f;
#pragma unroll
            for (int nt = 0; nt < 4; nt++) {
                int c = nt * 8 + 2 * t4;
                float2 er = __half22float2(*(const __half2*)(eH + row * 40 + c));
                float u0 = d[mt][nt][hb * 2 + 0];
                float u1 = d[mt][nt][hb * 2 + 1];
                float z0 = 0.7978845608028654f * (u0 + 0.044715f * u0 * u0 * u0);
                float z1 = 0.7978845608028654f * (u1 + 0.044715f * u1 * u1 * u1);
                float x0 = er.x + 0.5f * u0 * (1.f + tanh_approx(z0));
                float x1 = er.y + 0.5f * u1 * (1.f + tanh_approx(z1));
                x[2 * nt] = x0; x[2 * nt + 1] = x1;
                mu += x0 + x1;
            }
            mu += __shfl_xor_sync(0xffffffffu, mu, 1);
            mu += __shfl_xor_sync(0xffffffffu, mu, 2);
            mu *= (1.f / 32.f);
            float vr = 0.f;
#pragma unroll
            for (int i = 0; i < 8; i++) { float dx = x[i] - mu; vr += dx * dx; }
            vr += __shfl_xor_sync(0xffffffffu, vr, 1);
            vr += __shfl_xor_sync(0xffffffffu, vr, 2);
            float inv = rsqrtf(vr * (1.f / 32.f) + 1e-5f);
            float4 bb = make_float4(0.f, 0.f, 0.f, 0.f);
#pragma unroll
            for (int nt = 0; nt < 4; nt++) {
                int c = nt * 8 + 2 * t4;
                float y0 = (x[2 * nt] - mu) * inv * sge[c] + sbe[c];
                float y1 = (x[2 * nt + 1] - mu) * inv * sge[c + 1] + sbe[c + 1];
                float4 w0 = *(const float4*)(sWeN + c * 4);
                float4 w1 = *(const float4*)(sWeN + (c + 1) * 4);
                bb.x += y0 * w0.x + y1 * w1.x;
                bb.y += y0 * w0.y + y1 * w1.y;
                bb.z += y0 * w0.z + y1 * w1.z;
                bb.w += y0 * w0.w + y1 * w1.w;
                *(__half2*)(eH + row * 40 + c) = __floats2half2_rn(y0, y1);
            }
            bb.x += __shfl_xor_sync(0xffffffffu, bb.x, 1);
            bb.y += __shfl_xor_sync(0xffffffffu, bb.y, 1);
            bb.z += __shfl_xor_sync(0xffffffffu, bb.z, 1);
            bb.w += __shfl_xor_sync(0xffffffffu, bb.w, 1);
            bb.x += __shfl_xor_sync(0xffffffffu, bb.x, 2);
            bb.y += __shfl_xor_sync(0xffffffffu, bb.y, 2);
            bb.z += __shfl_xor_sync(0xffffffffu, bb.z, 2);
            bb.w += __shfl_xor_sync(0xffffffffu, bb.w, 2);
            int slot_r = __shfl_sync(0xffffffffu, slot_l, row);
            if (t4 == 0 && (base + row) < e)
                ((float4*)g_bias)[slot_r] = bb;
        }

    if (storeE) {
        __syncwarp();
#pragma unroll
        for (int j = 0; j < 8; j++) {
            int r = j * 4 + lrow;
            int ed = base + r;
            if (ed < e)
                *((uint2*)(g_eh + (size_t)ed * 32) + lidx) = bH[r * 10 + lidx];
        }
    }
}

// ---------------- launch ----------------
extern "C" void kernel_launch(void* const* d_in, const int* in_sizes, int n_in,
                              void* d_out, int out_size) {
    const float* nodef = (const float*)d_in[0];
    const float* edgef = (const float*)d_in[1];
    const int*   ei    = (const int*)d_in[2];
    const float* Wq    = (const float*)d_in[3];
    const float* Wk    = (const float*)d_in[4];
    const float* Wv    = (const float*)d_in[5];
    const float* Wo    = (const float*)d_in[6];
    const float* We    = (const float*)d_in[7];
    const float* Wem   = (const float*)d_in[8];
    const float* bem   = (const float*)d_in[9];
    const float* gn    = (const float*)d_in[10];
    const float* bn    = (const float*)d_in[11];
    const float* ge    = (const float*)d_in[12];
    const float* be    = (const float*)d_in[13];
    float* out = (float*)d_out;

    int n = in_sizes[0] / 64;
    int e = in_sizes[1] / 32;
    const int* src = ei;
    const int* dst = ei + e;
    int projBlocks = (n + 127) / 128;

    static cudaStream_t s2 = 0;
    static cudaEvent_t evA = 0, evB = 0;
    static int tried = 0;
    if (!tried) {
        tried = 1;
        if (cudaStreamCreateWithFlags(&s2, cudaStreamNonBlocking) != cudaSuccess) s2 = 0;
        if (cudaEventCreateWithFlags(&evA, cudaEventDisableTiming) != cudaSuccess) evA = 0;
        if (cudaEventCreateWithFlags(&evB, cudaEventDisableTiming) != cudaSuccess) evB = 0;
    }
    bool useS2 = (s2 != 0) && (evA != 0) && (evB != 0);

    // 0: count  1: scan+proj(L0)  2: scatbias  3: attn(L0) <- profiled
    k_count<<<(e + 255) / 256, 256>>>(dst, e);
    k_scanproj<<<projBlocks + 1, 1024>>>(n, nodef, 0, Wq, Wk, Wv, 1);
    k_scatbias<<<(e + 127) / 128, 128>>>(src, dst, edgef, We, e);

    for (int i = 0; i < 3; i++) {
        if (i > 0) {
            k_scanproj<<<projBlocks, 1024>>>(n, nodef, 1,
                                             Wq + i * 4096, Wk + i * 4096, Wv + i * 4096, 0);
            if (useS2) cudaStreamWaitEvent(0, evB, 0);
        }
        k_attn<<<(n + 7) / 8, 256>>>(n);
        int last = (i == 2);
        k_lnnode<<<(n + 15) / 16, 512>>>(nodef, (i > 0),
                                         Wo + i * 4096, gn + i * 64, bn + i * 64,
                                         Wem + i * 5120, out, last, !last, n);
        if (!last) {
            if (useS2) {
                cudaEventRecord(evA, 0);
                cudaStreamWaitEvent(s2, evA, 0);
                k_edge<<<(e + 127) / 128, 128, 0, s2>>>(Wem + i * 5120 + 4096, bem + i * 32,
                                                        ge + i * 32, be + i * 32,
                                                        We + (i + 1) * 128,
                                                        src, dst, e, (i == 0) ? 1 : 0);
                cudaEventRecord(evB, s2);
            } else {
                k_edge<<<(e + 127) / 128, 128>>>(Wem + i * 5120 + 4096, bem + i * 32,
                                                 ge + i * 32, be + i * 32,
                                                 We + (i + 1) * 128,
                                                 src, dst, e, (i == 0) ? 1 : 0);
            }
        }
    }
}

// round 15
// speedup vs baseline: 1.6214x; 1.0156x over previous
#include <cuda_runtime.h>
#include <cuda_fp16.h>

#define NMAX 50000
#define EMAX 1600000

// ---------------- static device scratch ----------------
__device__ int    g_cnt[NMAX];
__device__ int    g_off[NMAX + 1];
__device__ int    g_cur[NMAX];
__device__ int    g_epk[EMAX];         // src node per CSR slot
__device__ int    g_slot[EMAX];        // edge id -> CSR slot
__device__ float  g_q[NMAX * 64];
__device__ __half g_kh[NMAX * 64];
__device__ __half g_vh[NMAX * 64];
__device__ float  g_agg[NMAX * 64];
__device__ float  g_h[NMAX * 64];
__device__ __half g_Ah[NMAX * 32];
__device__ __half g_Bh[NMAX * 32];
__device__ __half g_eh[EMAX * 32];
__device__ float  g_bias[EMAX * 4];

// ---------------- helpers ----------------
__device__ __forceinline__ float tanh_approx(float x) {
    float y;
    asm("tanh.approx.f32 %0, %1;" : "=f"(y) : "f"(x));
    return y;
}
__device__ __forceinline__ unsigned s2u(const void* p) {
    return (unsigned)__cvta_generic_to_shared(p);
}
__device__ __forceinline__ void ldsm4(unsigned& r0, unsigned& r1, unsigned& r2, unsigned& r3,
                                      unsigned addr) {
    asm volatile("ldmatrix.sync.aligned.m8n8.x4.shared.b16 {%0,%1,%2,%3}, [%4];"
                 : "=r"(r0), "=r"(r1), "=r"(r2), "=r"(r3) : "r"(addr));
}
__device__ __forceinline__ void ldsm4t(unsigned& r0, unsigned& r1, unsigned& r2, unsigned& r3,
                                       unsigned addr) {
    asm volatile("ldmatrix.sync.aligned.m8n8.x4.trans.shared.b16 {%0,%1,%2,%3}, [%4];"
                 : "=r"(r0), "=r"(r1), "=r"(r2), "=r"(r3) : "r"(addr));
}
__device__ __forceinline__ void mma16816(float& d0, float& d1, float& d2, float& d3,
                                         unsigned a0, unsigned a1, unsigned a2, unsigned a3,
                                         unsigned b0, unsigned b1) {
    asm volatile("mma.sync.aligned.m16n8k16.row.col.f32.f16.f16.f32 "
                 "{%0,%1,%2,%3}, {%4,%5,%6,%7}, {%8,%9}, {%0,%1,%2,%3};"
                 : "+f"(d0), "+f"(d1), "+f"(d2), "+f"(d3)
                 : "r"(a0), "r"(a1), "r"(a2), "r"(a3), "r"(b0), "r"(b1));
}

// ---------------- count ----------------
__global__ void k_count(const int* __restrict__ dst, int e) {
    int i = blockIdx.x * blockDim.x + threadIdx.x;
    if (i < e) atomicAdd(&g_cnt[dst[i]], 1);
}

// ---------------- fused: block0 = exclusive scan (+re-zero cnt), rest = qkv proj ----------------
__global__ void k_scanproj(int n, const float* __restrict__ hin, int useG,
                           const float* __restrict__ Wq, const float* __restrict__ Wk,
                           const float* __restrict__ Wv, int withScan) {
    __shared__ float sq[4096], sk[4096], sv[4096];
    __shared__ int swi[32];
    int t = threadIdx.x;
    if (withScan && blockIdx.x == 0) {
        int lane = t & 31, w = t >> 5;
        int carry = 0;
        for (int base = 0; base < n; base += 1024) {
            int i = base + t;
            int v = (i < n) ? g_cnt[i] : 0;
            if (i < n) g_cnt[i] = 0;
            int x = v;
#pragma unroll
            for (int o = 1; o < 32; o <<= 1) {
                int y = __shfl_up_sync(0xffffffffu, x, o);
                if (lane >= o) x += y;
            }
            if (lane == 31) swi[w] = x;
            __syncthreads();
            if (t < 32) {
                int s = swi[t];
#pragma unroll
                for (int o = 1; o < 32; o <<= 1) {
                    int y = __shfl_up_sync(0xffffffffu, s, o);
                    if (t >= o) s += y;
                }
                swi[t] = s;
            }
            __syncthreads();
            int pref = (w > 0) ? swi[w - 1] : 0;
            int excl = carry + pref + x - v;
            if (i < n) { g_off[i] = excl; g_cur[i] = excl; }
            carry += swi[31];
            __syncthreads();
        }
        if (t == 0) g_off[n] = carry;
        return;
    }
    int bp = blockIdx.x - withScan;
    for (int i = t; i < 4096; i += 1024) { sq[i] = Wq[i]; sk[i] = Wk[i]; sv[i] = Wv[i]; }
    __syncthreads();
    const float* h = useG ? g_h : hin;
    int lane = t & 31, w = t >> 5;
    int r0 = (bp * 32 + w) * 4;
    float h0[4], h1[4];
#pragma unroll
    for (int r = 0; r < 4; r++) {
        int row = r0 + r;
        h0[r] = (row < n) ? h[row * 64 + lane] : 0.f;
        h1[r] = (row < n) ? h[row * 64 + lane + 32] : 0.f;
    }
    float aq0[4] = {0,0,0,0}, aq1[4] = {0,0,0,0};
    float ak0[4] = {0,0,0,0}, ak1[4] = {0,0,0,0};
    float av0[4] = {0,0,0,0}, av1[4] = {0,0,0,0};
#pragma unroll
    for (int j = 0; j < 32; j++) {
        float wq0 = sq[j * 64 + lane], wq1 = sq[j * 64 + lane + 32];
        float wk0 = sk[j * 64 + lane], wk1 = sk[j * 64 + lane + 32];
        float wv0 = sv[j * 64 + lane], wv1 = sv[j * 64 + lane + 32];
#pragma unroll
        for (int r = 0; r < 4; r++) {
            float hj = __shfl_sync(0xffffffffu, h0[r], j);
            aq0[r] += hj * wq0; aq1[r] += hj * wq1;
            ak0[r] += hj * wk0; ak1[r] += hj * wk1;
            av0[r] += hj * wv0; av1[r] += hj * wv1;
        }
    }
#pragma unroll
    for (int j = 0; j < 32; j++) {
        float wq0 = sq[(j + 32) * 64 + lane], wq1 = sq[(j + 32) * 64 + lane + 32];
        float wk0 = sk[(j + 32) * 64 + lane], wk1 = sk[(j + 32) * 64 + lane + 32];
        float wv0 = sv[(j + 32) * 64 + lane], wv1 = sv[(j + 32) * 64 + lane + 32];
#pragma unroll
        for (int r = 0; r < 4; r++) {
            float hj = __shfl_sync(0xffffffffu, h1[r], j);
            aq0[r] += hj * wq0; aq1[r] += hj * wq1;
            ak0[r] += hj * wk0; ak1[r] += hj * wk1;
            av0[r] += hj * wv0; av1[r] += hj * wv1;
        }
    }
#pragma unroll
    for (int r = 0; r < 4; r++) {
        int row = r0 + r;
        if (row >= n) break;
        g_q[row * 64 + lane] = aq0[r]; g_q[row * 64 + lane + 32] = aq1[r];
        g_kh[row * 64 + lane] = __float2half(ak0[r]);
        g_kh[row * 64 + lane + 32] = __float2half(ak1[r]);
        g_vh[row * 64 + lane] = __float2half(av0[r]);
        g_vh[row * 64 + lane + 32] = __float2half(av1[r]);
    }
}

// ---------------- fused scatter + layer-0 bias + fp16 e copy ----------------
__global__ void k_scatbias(const int* __restrict__ src, const int* __restrict__ dstp,
                           const float* __restrict__ ef, const float* __restrict__ We, int e) {
    __shared__ float sW[128];
    __shared__ float buf[4][32 * 33];
    int t = threadIdx.x;
    if (t < 128) sW[t] = We[t];
    __syncthreads();
    int w = t >> 5, lane = t & 31;
    int base = (blockIdx.x * 4 + w) * 32;
    float* b = buf[w];
    int ed0 = base + lane;
    int slot = -1;
    if (ed0 < e) {
        int d = __ldg(dstp + ed0);
        slot = atomicAdd(&g_cur[d], 1);
        g_epk[slot] = __ldg(src + ed0);
        g_slot[ed0] = slot;
    }
#pragma unroll 4
    for (int j = 0; j < 32; j++) {
        int ed = base + j;
        b[j * 33 + lane] = (ed < e) ? __ldg(ef + (size_t)ed * 32 + lane) : 0.f;
    }
    __syncwarp();
#pragma unroll 4
    for (int j = 0; j < 32; j++) {
        int ed = base + j;
        if (ed < e) g_eh[(size_t)ed * 32 + lane] = __float2half(b[j * 33 + lane]);
    }
    if (ed0 >= e) return;
    float4 bb = make_float4(0.f, 0.f, 0.f, 0.f);
#pragma unroll
    for (int k = 0; k < 32; k++) {
        float ek = b[lane * 33 + k];
        float4 wv = *(const float4*)(sW + k * 4);
        bb.x += ek * wv.x; bb.y += ek * wv.y; bb.z += ek * wv.z; bb.w += ek * wv.w;
    }
    ((float4*)g_bias)[slot] = bb;
}

// ---------------- attention: warp/node, unroll-4, fp16 k/v ----------------
__global__ void k_attn(int n) {
    int lane = threadIdx.x & 31;
    int node = blockIdx.x * 8 + (threadIdx.x >> 5);
    if (node >= n) return;
    int half = lane >> 4;
    int sub = lane & 15;
    int head = sub >> 2;
    int beg = g_off[node], end = g_off[node + 1];
    if (beg >= end) {
        if (half == 0)
            *(float4*)(g_agg + (size_t)node * 64 + sub * 4) = make_float4(0.f, 0.f, 0.f, 0.f);
        return;
    }
    float4 q4 = *(const float4*)(g_q + (size_t)node * 64 + sub * 4);
    q4.x *= 0.25f; q4.y *= 0.25f; q4.z *= 0.25f; q4.w *= 0.25f;
    float4 acc = make_float4(0.f, 0.f, 0.f, 0.f);
    float d = 0.f;
    for (int p = beg; p < end; p += 4) {
        int i0 = p + half;
        int i1 = p + 2 + half;
        bool u0 = (i0 < end), u1 = (i1 < end);
        int e0 = u0 ? i0 : beg;
        int e1 = u1 ? i1 : beg;
        int s0 = __ldg(&g_epk[e0]);
        int s1 = __ldg(&g_epk[e1]);
        uint2 kr0 = __ldg((const uint2*)(g_kh + (size_t)s0 * 64) + sub);
        uint2 kr1 = __ldg((const uint2*)(g_kh + (size_t)s1 * 64) + sub);
        uint2 vr0 = __ldg((const uint2*)(g_vh + (size_t)s0 * 64) + sub);
        uint2 vr1 = __ldg((const uint2*)(g_vh + (size_t)s1 * 64) + sub);
        float b0 = __ldg(g_bias + (size_t)e0 * 4 + head);
        float b1 = __ldg(g_bias + (size_t)e1 * 4 + head);
        float2 k0a = __half22float2(*(__half2*)&kr0.x);
        float2 k0b = __half22float2(*(__half2*)&kr0.y);
        float2 k1a = __half22float2(*(__half2*)&kr1.x);
        float2 k1b = __half22float2(*(__half2*)&kr1.y);
        float dt0 = q4.x * k0a.x + q4.y * k0a.y + q4.z * k0b.x + q4.w * k0b.y;
        float dt1 = q4.x * k1a.x + q4.y * k1a.y + q4.z * k1b.x + q4.w * k1b.y;
        dt0 += __shfl_xor_sync(0xffffffffu, dt0, 1);
        dt1 += __shfl_xor_sync(0xffffffffu, dt1, 1);
        dt0 += __shfl_xor_sync(0xffffffffu, dt0, 2);
        dt1 += __shfl_xor_sync(0xffffffffu, dt1, 2);
        float ex0 = u0 ? __expf(dt0 + b0) : 0.f;
        float ex1 = u1 ? __expf(dt1 + b1) : 0.f;
        d += ex0; d += ex1;
        float2 v0a = __half22float2(*(__half2*)&vr0.x);
        float2 v0b = __half22float2(*(__half2*)&vr0.y);
        float2 v1a = __half22float2(*(__half2*)&vr1.x);
        float2 v1b = __half22float2(*(__half2*)&vr1.y);
        acc.x += ex0 * v0a.x; acc.y += ex0 * v0a.y; acc.z += ex0 * v0b.x; acc.w += ex0 * v0b.y;
        acc.x += ex1 * v1a.x; acc.y += ex1 * v1a.y; acc.z += ex1 * v1b.x; acc.w += ex1 * v1b.y;
    }
    acc.x += __shfl_xor_sync(0xffffffffu, acc.x, 16);
    acc.y += __shfl_xor_sync(0xffffffffu, acc.y, 16);
    acc.z += __shfl_xor_sync(0xffffffffu, acc.z, 16);
    acc.w += __shfl_xor_sync(0xffffffffu, acc.w, 16);
    d     += __shfl_xor_sync(0xffffffffu, d, 16);
    if (half == 0) {
        float inv = 1.f / (d + 1e-9f);
        float4 o;
        o.x = acc.x * inv; o.y = acc.y * inv;
        o.z = acc.z * inv; o.w = acc.w * inv;
        *(float4*)(g_agg + (size_t)node * 64 + sub * 4) = o;
    }
}

// ---------------- node update (512 thr): h = LN(h + agg@Wo); fused fp16 A,B ----------------
__global__ void __launch_bounds__(512)
k_lnnode(const float* __restrict__ hin, int useGin,
         const float* __restrict__ Wo, const float* __restrict__ gn,
         const float* __restrict__ bn, const float* __restrict__ Wab,
         float* __restrict__ outp, int useOut, int doAB, int n) {
    __shared__ float sWo[4096];
    __shared__ float sAB[4096];
    for (int i = threadIdx.x; i < 4096; i += 512) {
        sWo[i] = Wo[i];
        if (doAB) sAB[i] = Wab[i];
    }
    __syncthreads();
    int lane = threadIdx.x & 31, w = threadIdx.x >> 5;
    int row = blockIdx.x * 16 + w;
    if (row >= n) return;
    const float* h = useGin ? g_h : hin;
    float a0 = g_agg[row * 64 + lane], a1 = g_agg[row * 64 + lane + 32];
    float o0 = 0.f, o1 = 0.f;
#pragma unroll
    for (int j = 0; j < 32; j++) {
        float aj = __shfl_sync(0xffffffffu, a0, j);
        o0 += aj * sWo[j * 64 + lane];
        o1 += aj * sWo[j * 64 + lane + 32];
    }
#pragma unroll
    for (int j = 0; j < 32; j++) {
        float aj = __shfl_sync(0xffffffffu, a1, j);
        o0 += aj * sWo[(j + 32) * 64 + lane];
        o1 += aj * sWo[(j + 32) * 64 + lane + 32];
    }
    float x0 = h[row * 64 + lane] + o0;
    float x1 = h[row * 64 + lane + 32] + o1;
    float s = x0 + x1;
#pragma unroll
    for (int o = 16; o; o >>= 1) s += __shfl_xor_sync(0xffffffffu, s, o);
    float mu = s * (1.f / 64.f);
    float d0 = x0 - mu, d1 = x1 - mu;
    float vs = d0 * d0 + d1 * d1;
#pragma unroll
    for (int o = 16; o; o >>= 1) vs += __shfl_xor_sync(0xffffffffu, vs, o);
    float inv = rsqrtf(vs * (1.f / 64.f) + 1e-5f);
    float y0 = d0 * inv * __ldg(gn + lane) + __ldg(bn + lane);
    float y1 = d1 * inv * __ldg(gn + lane + 32) + __ldg(bn + lane + 32);
    float* hp = useOut ? outp : g_h;
    hp[row * 64 + lane] = y0;
    hp[row * 64 + lane + 32] = y1;
    if (doAB) {
        float A = 0.f, B = 0.f;
#pragma unroll
        for (int j = 0; j < 32; j++) {
            float yj = __shfl_sync(0xffffffffu, y0, j);
            A += yj * sAB[j * 32 + lane];
            B += yj * sAB[(j + 64) * 32 + lane];
        }
#pragma unroll
        for (int j = 0; j < 32; j++) {
            float yj = __shfl_sync(0xffffffffu, y1, j);
            A += yj * sAB[(j + 32) * 32 + lane];
            B += yj * sAB[(j + 96) * 32 + lane];
        }
        g_Ah[row * 32 + lane] = __float2half(A);
        g_Bh[row * 32 + lane] = __float2half(B);
    }
}

// ---------------- edge update: tensor-core GEMM, merged A+B staging (low smem) ----------------
__global__ void __launch_bounds__(128)
k_edge(const float* __restrict__ Wem2, const float* __restrict__ bem,
       const float* __restrict__ ge, const float* __restrict__ be,
       const float* __restrict__ WeN,
       const int* __restrict__ src, const int* __restrict__ dstp,
       int e, int storeE) {
    __shared__ __align__(16) __half sWh[1024];     // W fp16 row-major [k][n] 32x32
    __shared__ float sWeN[128];
    __shared__ float sbem[32], sge[32], sbe[32];
    __shared__ uint2 bufAB[4][32 * 9];             // A[src]+B[dst] rows, 36-half stride
    __shared__ __align__(16) uint2 bufH[4][32 * 10]; // e rows, 40-half (80B) stride
    int t = threadIdx.x;
    for (int i = t; i < 1024; i += 128) sWh[i] = __float2half(Wem2[i]);
    if (t < 128) sWeN[t] = WeN[t];
    if (t < 32) { sbem[t] = bem[t]; sge[t] = ge[t]; sbe[t] = be[t]; }
    __syncthreads();
    int w = t >> 5, lane = t & 31;
    int base = (blockIdx.x * 4 + w) * 32;
    uint2* bAB = bufAB[w];
    uint2* bH = bufH[w];
    __half* eH = (__half*)bH;                       // row r col k at [r*40+k]
    const __half* abHalf = (const __half*)bAB;      // [r*36+k]

    // ---- stage e rows (8 x LDG.64 per warp, 4 rows/iter) ----
    int lrow = lane >> 3, lidx = lane & 7;
#pragma unroll
    for (int j = 0; j < 8; j++) {
        int r = j * 4 + lrow;
        int ed = base + r;
        uint2 v = make_uint2(0u, 0u);
        if (ed < e) v = __ldg((const uint2*)(g_eh + (size_t)ed * 32) + lidx);
        bH[r * 10 + lidx] = v;
    }

    int ed0 = base + lane;
    int s_l = (ed0 < e) ? __ldg(src + ed0)   : 0;
    int d_l = (ed0 < e) ? __ldg(dstp + ed0)  : 0;
    int slot_l = (ed0 < e) ? __ldg(g_slot + ed0) : 0;

    // ---- stage A[src]+B[dst] summed in fp16 (one buffer, half the smem) ----
#pragma unroll
    for (int j8 = 0; j8 < 8; j8++) {
        int r = j8 * 4 + lrow;
        int sj = __shfl_sync(0xffffffffu, s_l, r);
        int dj = __shfl_sync(0xffffffffu, d_l, r);
        uint2 va = __ldg((const uint2*)(g_Ah + (size_t)sj * 32) + lidx);
        uint2 vb = __ldg((const uint2*)(g_Bh + (size_t)dj * 32) + lidx);
        __half2 s0 = __hadd2(*(__half2*)&va.x, *(__half2*)&vb.x);
        __half2 s1 = __hadd2(*(__half2*)&va.y, *(__half2*)&vb.y);
        uint2 o;
        o.x = *(unsigned*)&s0;
        o.y = *(unsigned*)&s1;
        bAB[r * 9 + lidx] = o;
    }
    __syncwarp();

    int g = lane >> 2, t4 = lane & 3;

    // ---- load A fragments (X = e-tile) via ldmatrix x4: [mt][kt] ----
    unsigned Af[2][2][4];
    {
        int q = lane >> 3, i = lane & 7;
#pragma unroll
        for (int mt = 0; mt < 2; mt++)
#pragma unroll
            for (int kt = 0; kt < 2; kt++) {
                int row = mt * 16 + (q & 1) * 8 + i;
                int hcol = kt * 16 + (q >> 1) * 8;
                unsigned addr = s2u(eH + row * 40 + hcol);
                ldsm4(Af[mt][kt][0], Af[mt][kt][1], Af[mt][kt][2], Af[mt][kt][3], addr);
            }
    }
    // ---- load B fragments (W) via ldmatrix x4 trans: [kt][nt][2] ----
    unsigned Bf[2][4][2];
    {
        int q = lane >> 3, i = lane & 7;
#pragma unroll
        for (int kt = 0; kt < 2; kt++)
#pragma unroll
            for (int p = 0; p < 2; p++) {
                int krow = kt * 16 + (q & 1) * 8 + i;
                int ncol = p * 16 + (q >> 1) * 8;
                unsigned addr = s2u(sWh + krow * 32 + ncol);
                unsigned r0, r1, r2, r3;
                ldsm4t(r0, r1, r2, r3, addr);
                Bf[kt][2 * p][0] = r0;     Bf[kt][2 * p][1] = r1;
                Bf[kt][2 * p + 1][0] = r2; Bf[kt][2 * p + 1][1] = r3;
            }
    }

    // ---- init C = (A+B)[row] + bem in mma layout, then 16 HMMA ----
    float d[2][4][4];
#pragma unroll
    for (int mt = 0; mt < 2; mt++)
#pragma unroll
        for (int nt = 0; nt < 4; nt++) {
            int c = nt * 8 + 2 * t4;
            int r0 = mt * 16 + g, r1 = r0 + 8;
            float2 ab0 = __half22float2(*(const __half2*)(abHalf + r0 * 36 + c));
            float2 ab1 = __half22float2(*(const __half2*)(abHalf + r1 * 36 + c));
            float m0 = sbem[c], m1 = sbem[c + 1];
            d[mt][nt][0] = ab0.x + m0;
            d[mt][nt][1] = ab0.y + m1;
            d[mt][nt][2] = ab1.x + m0;
            d[mt][nt][3] = ab1.y + m1;
        }
#pragma unroll
    for (int mt = 0; mt < 2; mt++)
#pragma unroll
        for (int nt = 0; nt < 4; nt++) {
            mma16816(d[mt][nt][0], d[mt][nt][1], d[mt][nt][2], d[mt][nt][3],
                     Af[mt][0][0], Af[mt][0][1], Af[mt][0][2], Af[mt][0][3],
                     Bf[0][nt][0], Bf[0][nt][1]);
            mma16816(d[mt][nt][0], d[mt][nt][1], d[mt][nt][2], d[mt][nt][3],
                     Af[mt][1][0], Af[mt][1][1], Af[mt][1][2], Af[mt][1][3],
                     Bf[1][nt][0], Bf[1][nt][1]);
        }

    // ---- epilogue: per owned row (g, g+8, 16+g, 24+g): gelu+residual+LN+bias ----
#pragma unroll
    for (int mt = 0; mt < 2; mt++)
#pragma unroll
        for (int hb = 0; hb < 2; hb++) {
            int row = mt * 16 + hb * 8 + g;
            float x[8];
            float mu = 0.f;
#pragma unroll
            for (int nt = 0; nt < 4; nt++) {
                int c = nt * 8 + 2 * t4;
                float2 er = __half22float2(*(const __half2*)(eH + row * 40 + c));
                float u0 = d[mt][nt][hb * 2 + 0];
                float u1 = d[mt][nt][hb * 2 + 1];
                float z0 = 0.7978845608028654f * (u0 + 0.044715f * u0 * u0 * u0);
                float z1 = 0.7978845608028654f * (u1 + 0.044715f * u1 * u1 * u1);
                float x0 = er.x + 0.5f * u0 * (1.f + tanh_approx(z0));
                float x1 = er.y + 0.5f * u1 * (1.f + tanh_approx(z1));
                x[2 * nt] = x0; x[2 * nt + 1] = x1;
                mu += x0 + x1;
            }
            mu += __shfl_xor_sync(0xffffffffu, mu, 1);
            mu += __shfl_xor_sync(0xffffffffu, mu, 2);
            mu *= (1.f / 32.f);
            float vr = 0.f;
#pragma unroll
            for (int i = 0; i < 8; i++) { float dx = x[i] - mu; vr += dx * dx; }
            vr += __shfl_xor_sync(0xffffffffu, vr, 1);
            vr += __shfl_xor_sync(0xffffffffu, vr, 2);
            float inv = rsqrtf(vr * (1.f / 32.f) + 1e-5f);
            float4 bb = make_float4(0.f, 0.f, 0.f, 0.f);
#pragma unroll
            for (int nt = 0; nt < 4; nt++) {
                int c = nt * 8 + 2 * t4;
                float y0 = (x[2 * nt] - mu) * inv * sge[c] + sbe[c];
                float y1 = (x[2 * nt + 1] - mu) * inv * sge[c + 1] + sbe[c + 1];
                float4 w0 = *(const float4*)(sWeN + c * 4);
                float4 w1 = *(const float4*)(sWeN + (c + 1) * 4);
                bb.x += y0 * w0.x + y1 * w1.x;
                bb.y += y0 * w0.y + y1 * w1.y;
                bb.z += y0 * w0.z + y1 * w1.z;
                bb.w += y0 * w0.w + y1 * w1.w;
                *(__half2*)(eH + row * 40 + c) = __floats2half2_rn(y0, y1);
            }
            bb.x += __shfl_xor_sync(0xffffffffu, bb.x, 1);
            bb.y += __shfl_xor_sync(0xffffffffu, bb.y, 1);
            bb.z += __shfl_xor_sync(0xffffffffu, bb.z, 1);
            bb.w += __shfl_xor_sync(0xffffffffu, bb.w, 1);
            bb.x += __shfl_xor_sync(0xffffffffu, bb.x, 2);
            bb.y += __shfl_xor_sync(0xffffffffu, bb.y, 2);
            bb.z += __shfl_xor_sync(0xffffffffu, bb.z, 2);
            bb.w += __shfl_xor_sync(0xffffffffu, bb.w, 2);
            int slot_r = __shfl_sync(0xffffffffu, slot_l, row);
            if (t4 == 0 && (base + row) < e)
                ((float4*)g_bias)[slot_r] = bb;
        }

    if (storeE) {
        __syncwarp();
#pragma unroll
        for (int j = 0; j < 8; j++) {
            int r = j * 4 + lrow;
            int ed = base + r;
            if (ed < e)
                *((uint2*)(g_eh + (size_t)ed * 32) + lidx) = bH[r * 10 + lidx];
        }
    }
}

// ---------------- launch ----------------
extern "C" void kernel_launch(void* const* d_in, const int* in_sizes, int n_in,
                              void* d_out, int out_size) {
    const float* nodef = (const float*)d_in[0];
    const float* edgef = (const float*)d_in[1];
    const int*   ei    = (const int*)d_in[2];
    const float* Wq    = (const float*)d_in[3];
    const float* Wk    = (const float*)d_in[4];
    const float* Wv    = (const float*)d_in[5];
    const float* Wo    = (const float*)d_in[6];
    const float* We    = (const float*)d_in[7];
    const float* Wem   = (const float*)d_in[8];
    const float* bem   = (const float*)d_in[9];
    const float* gn    = (const float*)d_in[10];
    const float* bn    = (const float*)d_in[11];
    const float* ge    = (const float*)d_in[12];
    const float* be    = (const float*)d_in[13];
    float* out = (float*)d_out;

    int n = in_sizes[0] / 64;
    int e = in_sizes[1] / 32;
    const int* src = ei;
    const int* dst = ei + e;
    int projBlocks = (n + 127) / 128;

    static cudaStream_t s2 = 0;
    static cudaEvent_t evA = 0, evB = 0;
    static int tried = 0;
    if (!tried) {
        tried = 1;
        if (cudaStreamCreateWithFlags(&s2, cudaStreamNonBlocking) != cudaSuccess) s2 = 0;
        if (cudaEventCreateWithFlags(&evA, cudaEventDisableTiming) != cudaSuccess) evA = 0;
        if (cudaEventCreateWithFlags(&evB, cudaEventDisableTiming) != cudaSuccess) evB = 0;
    }
    bool useS2 = (s2 != 0) && (evA != 0) && (evB != 0);

    // 0: count  1: scan+proj(L0)  2: scatbias  3: attn(L0) <- profiled
    k_count<<<(e + 255) / 256, 256>>>(dst, e);
    k_scanproj<<<projBlocks + 1, 1024>>>(n, nodef, 0, Wq, Wk, Wv, 1);
    k_scatbias<<<(e + 127) / 128, 128>>>(src, dst, edgef, We, e);

    for (int i = 0; i < 3; i++) {
        if (i > 0) {
            k_scanproj<<<projBlocks, 1024>>>(n, nodef, 1,
                                             Wq + i * 4096, Wk + i * 4096, Wv + i * 4096, 0);
            if (useS2) cudaStreamWaitEvent(0, evB, 0);
        }
        k_attn<<<(n + 7) / 8, 256>>>(n);
        int last = (i == 2);
        k_lnnode<<<(n + 15) / 16, 512>>>(nodef, (i > 0),
                                         Wo + i * 4096, gn + i * 64, bn + i * 64,
                                         Wem + i * 5120, out, last, !last, n);
        if (!last) {
            if (useS2) {
                cudaEventRecord(evA, 0);
                cudaStreamWaitEvent(s2, evA, 0);
                k_edge<<<(e + 127) / 128, 128, 0, s2>>>(Wem + i * 5120 + 4096, bem + i * 32,
                                                        ge + i * 32, be + i * 32,
                                                        We + (i + 1) * 128,
                                                        src, dst, e, (i == 0) ? 1 : 0);
                cudaEventRecord(evB, s2);
            } else {
                k_edge<<<(e + 127) / 128, 128>>>(Wem + i * 5120 + 4096, bem + i * 32,
                                                 ge + i * 32, be + i * 32,
                                                 We + (i + 1) * 128,
                                                 src, dst, e, (i == 0) ? 1 : 0);
            }
        }
    }
}

// round 16
// speedup vs baseline: 1.7101x; 1.0548x over previous
#include <cuda_runtime.h>
#include <cuda_fp16.h>

#define NMAX 50000
#define EMAX 1600000

// ---------------- static device scratch ----------------
__device__ int    g_cnt[NMAX];
__device__ int    g_off[NMAX + 1];
__device__ int    g_cur[NMAX];
__device__ int    g_epk[EMAX];         // src node per CSR slot
__device__ int    g_slot[EMAX];        // edge id -> CSR slot
__device__ float  g_q[NMAX * 64];
__device__ __half g_kh[NMAX * 64];
__device__ __half g_vh[NMAX * 64];
__device__ float  g_agg[NMAX * 64];
__device__ float  g_h[NMAX * 64];
__device__ __half g_Ah[NMAX * 32];
__device__ __half g_Bh[NMAX * 32];
__device__ __half g_eh[EMAX * 32];
__device__ float  g_bias[EMAX * 4];

// ---------------- helpers ----------------
__device__ __forceinline__ float tanh_approx(float x) {
    float y;
    asm("tanh.approx.f32 %0, %1;" : "=f"(y) : "f"(x));
    return y;
}
__device__ __forceinline__ unsigned s2u(const void* p) {
    return (unsigned)__cvta_generic_to_shared(p);
}
__device__ __forceinline__ void ldsm4(unsigned& r0, unsigned& r1, unsigned& r2, unsigned& r3,
                                      unsigned addr) {
    asm volatile("ldmatrix.sync.aligned.m8n8.x4.shared.b16 {%0,%1,%2,%3}, [%4];"
                 : "=r"(r0), "=r"(r1), "=r"(r2), "=r"(r3) : "r"(addr));
}
__device__ __forceinline__ void ldsm4t(unsigned& r0, unsigned& r1, unsigned& r2, unsigned& r3,
                                       unsigned addr) {
    asm volatile("ldmatrix.sync.aligned.m8n8.x4.trans.shared.b16 {%0,%1,%2,%3}, [%4];"
                 : "=r"(r0), "=r"(r1), "=r"(r2), "=r"(r3) : "r"(addr));
}
__device__ __forceinline__ void mma16816(float& d0, float& d1, float& d2, float& d3,
                                         unsigned a0, unsigned a1, unsigned a2, unsigned a3,
                                         unsigned b0, unsigned b1) {
    asm volatile("mma.sync.aligned.m16n8k16.row.col.f32.f16.f16.f32 "
                 "{%0,%1,%2,%3}, {%4,%5,%6,%7}, {%8,%9}, {%0,%1,%2,%3};"
                 : "+f"(d0), "+f"(d1), "+f"(d2), "+f"(d3)
                 : "r"(a0), "r"(a1), "r"(a2), "r"(a3), "r"(b0), "r"(b1));
}

// ---------------- count ----------------
__global__ void k_count(const int* __restrict__ dst, int e) {
    int i = blockIdx.x * blockDim.x + threadIdx.x;
    if (i < e) atomicAdd(&g_cnt[dst[i]], 1);
}

// ---------------- fused: block0 = exclusive scan (+re-zero cnt), rest = qkv proj ----------------
__global__ void k_scanproj(int n, const float* __restrict__ hin, int useG,
                           const float* __restrict__ Wq, const float* __restrict__ Wk,
                           const float* __restrict__ Wv, int withScan) {
    __shared__ float sq[4096], sk[4096], sv[4096];
    __shared__ int swi[32];
    int t = threadIdx.x;
    if (withScan && blockIdx.x == 0) {
        int lane = t & 31, w = t >> 5;
        int carry = 0;
        for (int base = 0; base < n; base += 1024) {
            int i = base + t;
            int v = (i < n) ? g_cnt[i] : 0;
            if (i < n) g_cnt[i] = 0;
            int x = v;
#pragma unroll
            for (int o = 1; o < 32; o <<= 1) {
                int y = __shfl_up_sync(0xffffffffu, x, o);
                if (lane >= o) x += y;
            }
            if (lane == 31) swi[w] = x;
            __syncthreads();
            if (t < 32) {
                int s = swi[t];
#pragma unroll
                for (int o = 1; o < 32; o <<= 1) {
                    int y = __shfl_up_sync(0xffffffffu, s, o);
                    if (t >= o) s += y;
                }
                swi[t] = s;
            }
            __syncthreads();
            int pref = (w > 0) ? swi[w - 1] : 0;
            int excl = carry + pref + x - v;
            if (i < n) { g_off[i] = excl; g_cur[i] = excl; }
            carry += swi[31];
            __syncthreads();
        }
        if (t == 0) g_off[n] = carry;
        return;
    }
    int bp = blockIdx.x - withScan;
    for (int i = t; i < 4096; i += 1024) { sq[i] = Wq[i]; sk[i] = Wk[i]; sv[i] = Wv[i]; }
    __syncthreads();
    const float* h = useG ? g_h : hin;
    int lane = t & 31, w = t >> 5;
    int r0 = (bp * 32 + w) * 4;
    float h0[4], h1[4];
#pragma unroll
    for (int r = 0; r < 4; r++) {
        int row = r0 + r;
        h0[r] = (row < n) ? h[row * 64 + lane] : 0.f;
        h1[r] = (row < n) ? h[row * 64 + lane + 32] : 0.f;
    }
    float aq0[4] = {0,0,0,0}, aq1[4] = {0,0,0,0};
    float ak0[4] = {0,0,0,0}, ak1[4] = {0,0,0,0};
    float av0[4] = {0,0,0,0}, av1[4] = {0,0,0,0};
#pragma unroll
    for (int j = 0; j < 32; j++) {
        float wq0 = sq[j * 64 + lane], wq1 = sq[j * 64 + lane + 32];
        float wk0 = sk[j * 64 + lane], wk1 = sk[j * 64 + lane + 32];
        float wv0 = sv[j * 64 + lane], wv1 = sv[j * 64 + lane + 32];
#pragma unroll
        for (int r = 0; r < 4; r++) {
            float hj = __shfl_sync(0xffffffffu, h0[r], j);
            aq0[r] += hj * wq0; aq1[r] += hj * wq1;
            ak0[r] += hj * wk0; ak1[r] += hj * wk1;
            av0[r] += hj * wv0; av1[r] += hj * wv1;
        }
    }
#pragma unroll
    for (int j = 0; j < 32; j++) {
        float wq0 = sq[(j + 32) * 64 + lane], wq1 = sq[(j + 32) * 64 + lane + 32];
        float wk0 = sk[(j + 32) * 64 + lane], wk1 = sk[(j + 32) * 64 + lane + 32];
        float wv0 = sv[(j + 32) * 64 + lane], wv1 = sv[(j + 32) * 64 + lane + 32];
#pragma unroll
        for (int r = 0; r < 4; r++) {
            float hj = __shfl_sync(0xffffffffu, h1[r], j);
            aq0[r] += hj * wq0; aq1[r] += hj * wq1;
            ak0[r] += hj * wk0; ak1[r] += hj * wk1;
            av0[r] += hj * wv0; av1[r] += hj * wv1;
        }
    }
#pragma unroll
    for (int r = 0; r < 4; r++) {
        int row = r0 + r;
        if (row >= n) break;
        g_q[row * 64 + lane] = aq0[r]; g_q[row * 64 + lane + 32] = aq1[r];
        g_kh[row * 64 + lane] = __float2half(ak0[r]);
        g_kh[row * 64 + lane + 32] = __float2half(ak1[r]);
        g_vh[row * 64 + lane] = __float2half(av0[r]);
        g_vh[row * 64 + lane + 32] = __float2half(av1[r]);
    }
}

// ---------------- fused scatter + layer-0 bias + fp16 e copy ----------------
__global__ void k_scatbias(const int* __restrict__ src, const int* __restrict__ dstp,
                           const float* __restrict__ ef, const float* __restrict__ We, int e) {
    __shared__ float sW[128];
    __shared__ float buf[4][32 * 33];
    int t = threadIdx.x;
    if (t < 128) sW[t] = We[t];
    __syncthreads();
    int w = t >> 5, lane = t & 31;
    int base = (blockIdx.x * 4 + w) * 32;
    float* b = buf[w];
    int ed0 = base + lane;
    int slot = -1;
    if (ed0 < e) {
        int d = __ldg(dstp + ed0);
        slot = atomicAdd(&g_cur[d], 1);
        g_epk[slot] = __ldg(src + ed0);
        g_slot[ed0] = slot;
    }
#pragma unroll 4
    for (int j = 0; j < 32; j++) {
        int ed = base + j;
        b[j * 33 + lane] = (ed < e) ? __ldg(ef + (size_t)ed * 32 + lane) : 0.f;
    }
    __syncwarp();
#pragma unroll 4
    for (int j = 0; j < 32; j++) {
        int ed = base + j;
        if (ed < e) g_eh[(size_t)ed * 32 + lane] = __float2half(b[j * 33 + lane]);
    }
    if (ed0 >= e) return;
    float4 bb = make_float4(0.f, 0.f, 0.f, 0.f);
#pragma unroll
    for (int k = 0; k < 32; k++) {
        float ek = b[lane * 33 + k];
        float4 wv = *(const float4*)(sW + k * 4);
        bb.x += ek * wv.x; bb.y += ek * wv.y; bb.z += ek * wv.z; bb.w += ek * wv.w;
    }
    ((float4*)g_bias)[slot] = bb;
}

// ---------------- attention: warp/node, unroll-4, fp16 k/v, half2 dot ----------------
__global__ void k_attn(int n) {
    int lane = threadIdx.x & 31;
    int node = blockIdx.x * 8 + (threadIdx.x >> 5);
    if (node >= n) return;
    int half = lane >> 4;
    int sub = lane & 15;
    int head = sub >> 2;
    int beg = g_off[node], end = g_off[node + 1];
    if (beg >= end) {
        if (half == 0)
            *(float4*)(g_agg + (size_t)node * 64 + sub * 4) = make_float4(0.f, 0.f, 0.f, 0.f);
        return;
    }
    float4 q4 = *(const float4*)(g_q + (size_t)node * 64 + sub * 4);
    q4.x *= 0.25f; q4.y *= 0.25f; q4.z *= 0.25f; q4.w *= 0.25f;
    __half2 qh0 = __floats2half2_rn(q4.x, q4.y);
    __half2 qh1 = __floats2half2_rn(q4.z, q4.w);
    float4 acc = make_float4(0.f, 0.f, 0.f, 0.f);
    float d = 0.f;
    for (int p = beg; p < end; p += 4) {
        int i0 = p + half;
        int i1 = p + 2 + half;
        bool u0 = (i0 < end), u1 = (i1 < end);
        int e0 = u0 ? i0 : beg;
        int e1 = u1 ? i1 : beg;
        int s0 = __ldg(&g_epk[e0]);
        int s1 = __ldg(&g_epk[e1]);
        uint2 kr0 = __ldg((const uint2*)(g_kh + (size_t)s0 * 64) + sub);
        uint2 kr1 = __ldg((const uint2*)(g_kh + (size_t)s1 * 64) + sub);
        uint2 vr0 = __ldg((const uint2*)(g_vh + (size_t)s0 * 64) + sub);
        uint2 vr1 = __ldg((const uint2*)(g_vh + (size_t)s1 * 64) + sub);
        float b0 = __ldg(g_bias + (size_t)e0 * 4 + head);
        float b1 = __ldg(g_bias + (size_t)e1 * 4 + head);
        __half2 p0h = __hmul2(qh0, *(__half2*)&kr0.x);
        p0h = __hfma2(qh1, *(__half2*)&kr0.y, p0h);
        __half2 p1h = __hmul2(qh0, *(__half2*)&kr1.x);
        p1h = __hfma2(qh1, *(__half2*)&kr1.y, p1h);
        float2 p0f = __half22float2(p0h);
        float2 p1f = __half22float2(p1h);
        float dt0 = p0f.x + p0f.y;
        float dt1 = p1f.x + p1f.y;
        dt0 += __shfl_xor_sync(0xffffffffu, dt0, 1);
        dt1 += __shfl_xor_sync(0xffffffffu, dt1, 1);
        dt0 += __shfl_xor_sync(0xffffffffu, dt0, 2);
        dt1 += __shfl_xor_sync(0xffffffffu, dt1, 2);
        float ex0 = u0 ? __expf(dt0 + b0) : 0.f;
        float ex1 = u1 ? __expf(dt1 + b1) : 0.f;
        d += ex0; d += ex1;
        float2 v0a = __half22float2(*(__half2*)&vr0.x);
        float2 v0b = __half22float2(*(__half2*)&vr0.y);
        float2 v1a = __half22float2(*(__half2*)&vr1.x);
        float2 v1b = __half22float2(*(__half2*)&vr1.y);
        acc.x += ex0 * v0a.x; acc.y += ex0 * v0a.y; acc.z += ex0 * v0b.x; acc.w += ex0 * v0b.y;
        acc.x += ex1 * v1a.x; acc.y += ex1 * v1a.y; acc.z += ex1 * v1b.x; acc.w += ex1 * v1b.y;
    }
    acc.x += __shfl_xor_sync(0xffffffffu, acc.x, 16);
    acc.y += __shfl_xor_sync(0xffffffffu, acc.y, 16);
    acc.z += __shfl_xor_sync(0xffffffffu, acc.z, 16);
    acc.w += __shfl_xor_sync(0xffffffffu, acc.w, 16);
    d     += __shfl_xor_sync(0xffffffffu, d, 16);
    if (half == 0) {
        float inv = 1.f / (d + 1e-9f);
        float4 o;
        o.x = acc.x * inv; o.y = acc.y * inv;
        o.z = acc.z * inv; o.w = acc.w * inv;
        *(float4*)(g_agg + (size_t)node * 64 + sub * 4) = o;
    }
}

// ---------------- node update (512 thr): h = LN(h + agg@Wo); fused fp16 A,B ----------------
__global__ void __launch_bounds__(512)
k_lnnode(const float* __restrict__ hin, int useGin,
         const float* __restrict__ Wo, const float* __restrict__ gn,
         const float* __restrict__ bn, const float* __restrict__ Wab,
         float* __restrict__ outp, int useOut, int doAB, int n) {
    __shared__ float sWo[4096];
    __shared__ float sAB[4096];
    for (int i = threadIdx.x; i < 4096; i += 512) {
        sWo[i] = Wo[i];
        if (doAB) sAB[i] = Wab[i];
    }
    __syncthreads();
    int lane = threadIdx.x & 31, w = threadIdx.x >> 5;
    int row = blockIdx.x * 16 + w;
    if (row >= n) return;
    const float* h = useGin ? g_h : hin;
    float a0 = g_agg[row * 64 + lane], a1 = g_agg[row * 64 + lane + 32];
    float o0 = 0.f, o1 = 0.f;
#pragma unroll
    for (int j = 0; j < 32; j++) {
        float aj = __shfl_sync(0xffffffffu, a0, j);
        o0 += aj * sWo[j * 64 + lane];
        o1 += aj * sWo[j * 64 + lane + 32];
    }
#pragma unroll
    for (int j = 0; j < 32; j++) {
        float aj = __shfl_sync(0xffffffffu, a1, j);
        o0 += aj * sWo[(j + 32) * 64 + lane];
        o1 += aj * sWo[(j + 32) * 64 + lane + 32];
    }
    float x0 = h[row * 64 + lane] + o0;
    float x1 = h[row * 64 + lane + 32] + o1;
    float s = x0 + x1;
#pragma unroll
    for (int o = 16; o; o >>= 1) s += __shfl_xor_sync(0xffffffffu, s, o);
    float mu = s * (1.f / 64.f);
    float d0 = x0 - mu, d1 = x1 - mu;
    float vs = d0 * d0 + d1 * d1;
#pragma unroll
    for (int o = 16; o; o >>= 1) vs += __shfl_xor_sync(0xffffffffu, vs, o);
    float inv = rsqrtf(vs * (1.f / 64.f) + 1e-5f);
    float y0 = d0 * inv * __ldg(gn + lane) + __ldg(bn + lane);
    float y1 = d1 * inv * __ldg(gn + lane + 32) + __ldg(bn + lane + 32);
    float* hp = useOut ? outp : g_h;
    hp[row * 64 + lane] = y0;
    hp[row * 64 + lane + 32] = y1;
    if (doAB) {
        float A = 0.f, B = 0.f;
#pragma unroll
        for (int j = 0; j < 32; j++) {
            float yj = __shfl_sync(0xffffffffu, y0, j);
            A += yj * sAB[j * 32 + lane];
            B += yj * sAB[(j + 64) * 32 + lane];
        }
#pragma unroll
        for (int j = 0; j < 32; j++) {
            float yj = __shfl_sync(0xffffffffu, y1, j);
            A += yj * sAB[(j + 32) * 32 + lane];
            B += yj * sAB[(j + 96) * 32 + lane];
        }
        g_Ah[row * 32 + lane] = __float2half(A);
        g_Bh[row * 32 + lane] = __float2half(B);
    }
}

// ---------------- edge update: tensor-core GEMM + tensor-core bias epilogue ----------------
__global__ void __launch_bounds__(128)
k_edge(const float* __restrict__ Wem2, const float* __restrict__ bem,
       const float* __restrict__ ge, const float* __restrict__ be,
       const float* __restrict__ WeN,
       const int* __restrict__ src, const int* __restrict__ dstp,
       int e, int storeE) {
    __shared__ __align__(16) __half sWh[1024];     // W fp16 row-major [k][n] 32x32
    __shared__ __align__(16) __half sWeNh[512];    // WeN fp16 [32 x 16] (cols 4..15 zero)
    __shared__ float sbem[32], sge[32], sbe[32];
    __shared__ uint2 bufAB[4][32 * 9];             // A[src]+B[dst] rows, 36-half stride
    __shared__ __align__(16) uint2 bufH[4][32 * 10]; // e rows, 40-half (80B) stride
    int t = threadIdx.x;
    for (int i = t; i < 1024; i += 128) sWh[i] = __float2half(Wem2[i]);
    for (int i = t; i < 512; i += 128) {
        int r = i >> 4, c = i & 15;
        sWeNh[i] = (c < 4) ? __float2half(WeN[r * 4 + c]) : __float2half(0.f);
    }
    if (t < 32) { sbem[t] = bem[t]; sge[t] = ge[t]; sbe[t] = be[t]; }
    __syncthreads();
    int w = t >> 5, lane = t & 31;
    int base = (blockIdx.x * 4 + w) * 32;
    uint2* bAB = bufAB[w];
    uint2* bH = bufH[w];
    __half* eH = (__half*)bH;                       // row r col k at [r*40+k]
    const __half* abHalf = (const __half*)bAB;      // [r*36+k]

    // ---- stage e rows (8 x LDG.64 per warp, 4 rows/iter) ----
    int lrow = lane >> 3, lidx = lane & 7;
#pragma unroll
    for (int j = 0; j < 8; j++) {
        int r = j * 4 + lrow;
        int ed = base + r;
        uint2 v = make_uint2(0u, 0u);
        if (ed < e) v = __ldg((const uint2*)(g_eh + (size_t)ed * 32) + lidx);
        bH[r * 10 + lidx] = v;
    }

    int ed0 = base + lane;
    int s_l = (ed0 < e) ? __ldg(src + ed0)   : 0;
    int d_l = (ed0 < e) ? __ldg(dstp + ed0)  : 0;
    int slot_l = (ed0 < e) ? __ldg(g_slot + ed0) : 0;

    // ---- stage A[src]+B[dst] summed in fp16 ----
#pragma unroll
    for (int j8 = 0; j8 < 8; j8++) {
        int r = j8 * 4 + lrow;
        int sj = __shfl_sync(0xffffffffu, s_l, r);
        int dj = __shfl_sync(0xffffffffu, d_l, r);
        uint2 va = __ldg((const uint2*)(g_Ah + (size_t)sj * 32) + lidx);
        uint2 vb = __ldg((const uint2*)(g_Bh + (size_t)dj * 32) + lidx);
        __half2 s0 = __hadd2(*(__half2*)&va.x, *(__half2*)&vb.x);
        __half2 s1 = __hadd2(*(__half2*)&va.y, *(__half2*)&vb.y);
        uint2 o;
        o.x = *(unsigned*)&s0;
        o.y = *(unsigned*)&s1;
        bAB[r * 9 + lidx] = o;
    }
    __syncwarp();

    int g = lane >> 2, t4 = lane & 3;
    int q = lane >> 3, iq = lane & 7;

    // ---- load A fragments (X = e-tile) via ldmatrix x4: [mt][kt] ----
    unsigned Af[2][2][4];
#pragma unroll
    for (int mt = 0; mt < 2; mt++)
#pragma unroll
        for (int kt = 0; kt < 2; kt++) {
            int row = mt * 16 + (q & 1) * 8 + iq;
            int hcol = kt * 16 + (q >> 1) * 8;
            unsigned addr = s2u(eH + row * 40 + hcol);
            ldsm4(Af[mt][kt][0], Af[mt][kt][1], Af[mt][kt][2], Af[mt][kt][3], addr);
        }
    // ---- load B fragments (W) via ldmatrix x4 trans: [kt][nt][2] ----
    unsigned Bf[2][4][2];
#pragma unroll
    for (int kt = 0; kt < 2; kt++)
#pragma unroll
        for (int p = 0; p < 2; p++) {
            int krow = kt * 16 + (q & 1) * 8 + iq;
            int ncol = p * 16 + (q >> 1) * 8;
            unsigned addr = s2u(sWh + krow * 32 + ncol);
            unsigned r0, r1, r2, r3;
            ldsm4t(r0, r1, r2, r3, addr);
            Bf[kt][2 * p][0] = r0;     Bf[kt][2 * p][1] = r1;
            Bf[kt][2 * p + 1][0] = r2; Bf[kt][2 * p + 1][1] = r3;
        }

    // ---- init C = (A+B)[row] + bem in mma layout, then 16 HMMA ----
    float d[2][4][4];
#pragma unroll
    for (int mt = 0; mt < 2; mt++)
#pragma unroll
        for (int nt = 0; nt < 4; nt++) {
            int c = nt * 8 + 2 * t4;
            int r0 = mt * 16 + g, r1 = r0 + 8;
            float2 ab0 = __half22float2(*(const __half2*)(abHalf + r0 * 36 + c));
            float2 ab1 = __half22float2(*(const __half2*)(abHalf + r1 * 36 + c));
            float m0 = sbem[c], m1 = sbem[c + 1];
            d[mt][nt][0] = ab0.x + m0;
            d[mt][nt][1] = ab0.y + m1;
            d[mt][nt][2] = ab1.x + m0;
            d[mt][nt][3] = ab1.y + m1;
        }
#pragma unroll
    for (int mt = 0; mt < 2; mt++)
#pragma unroll
        for (int nt = 0; nt < 4; nt++) {
            mma16816(d[mt][nt][0], d[mt][nt][1], d[mt][nt][2], d[mt][nt][3],
                     Af[mt][0][0], Af[mt][0][1], Af[mt][0][2], Af[mt][0][3],
                     Bf[0][nt][0], Bf[0][nt][1]);
            mma16816(d[mt][nt][0], d[mt][nt][1], d[mt][nt][2], d[mt][nt][3],
                     Af[mt][1][0], Af[mt][1][1], Af[mt][1][2], Af[mt][1][3],
                     Bf[1][nt][0], Bf[1][nt][1]);
        }

    // ---- epilogue: gelu+residual+LN per row; y (fp16) written back into eH ----
#pragma unroll
    for (int mt = 0; mt < 2; mt++)
#pragma unroll
        for (int hb = 0; hb < 2; hb++) {
            int row = mt * 16 + hb * 8 + g;
            float x[8];
            float mu = 0.f;
#pragma unroll
            for (int nt = 0; nt < 4; nt++) {
                int c = nt * 8 + 2 * t4;
                float2 er = __half22float2(*(const __half2*)(eH + row * 40 + c));
                float u0 = d[mt][nt][hb * 2 + 0];
                float u1 = d[mt][nt][hb * 2 + 1];
                float z0 = 0.7978845608028654f * (u0 + 0.044715f * u0 * u0 * u0);
                float z1 = 0.7978845608028654f * (u1 + 0.044715f * u1 * u1 * u1);
                float x0 = er.x + 0.5f * u0 * (1.f + tanh_approx(z0));
                float x1 = er.y + 0.5f * u1 * (1.f + tanh_approx(z1));
                x[2 * nt] = x0; x[2 * nt + 1] = x1;
                mu += x0 + x1;
            }
            mu += __shfl_xor_sync(0xffffffffu, mu, 1);
            mu += __shfl_xor_sync(0xffffffffu, mu, 2);
            mu *= (1.f / 32.f);
            float vr = 0.f;
#pragma unroll
            for (int i = 0; i < 8; i++) { float dx = x[i] - mu; vr += dx * dx; }
            vr += __shfl_xor_sync(0xffffffffu, vr, 1);
            vr += __shfl_xor_sync(0xffffffffu, vr, 2);
            float inv = rsqrtf(vr * (1.f / 32.f) + 1e-5f);
#pragma unroll
            for (int nt = 0; nt < 4; nt++) {
                int c = nt * 8 + 2 * t4;
                float y0 = (x[2 * nt] - mu) * inv * sge[c] + sbe[c];
                float y1 = (x[2 * nt + 1] - mu) * inv * sge[c + 1] + sbe[c + 1];
                *(__half2*)(eH + row * 40 + c) = __floats2half2_rn(y0, y1);
            }
        }
    __syncwarp();

    // ---- bias = Y @ WeN via tensor core (Y fp16 now in eH) ----
    {
        unsigned Yf[2][2][4];
#pragma unroll
        for (int mt = 0; mt < 2; mt++)
#pragma unroll
            for (int kt = 0; kt < 2; kt++) {
                int row = mt * 16 + (q & 1) * 8 + iq;
                int hcol = kt * 16 + (q >> 1) * 8;
                unsigned addr = s2u(eH + row * 40 + hcol);
                ldsm4(Yf[mt][kt][0], Yf[mt][kt][1], Yf[mt][kt][2], Yf[mt][kt][3], addr);
            }
        unsigned Nf[2][2];
#pragma unroll
        for (int kt = 0; kt < 2; kt++) {
            int krow = kt * 16 + (q & 1) * 8 + iq;
            int ncol = (q >> 1) * 8;
            unsigned addr = s2u(sWeNh + krow * 16 + ncol);
            unsigned r0, r1, r2, r3;
            ldsm4t(r0, r1, r2, r3, addr);
            Nf[kt][0] = r0; Nf[kt][1] = r1;   // nt=0 (cols 0..7; 4..7 are zero)
        }
        float db[2][4];
#pragma unroll
        for (int mt = 0; mt < 2; mt++) {
            db[mt][0] = db[mt][1] = db[mt][2] = db[mt][3] = 0.f;
            mma16816(db[mt][0], db[mt][1], db[mt][2], db[mt][3],
                     Yf[mt][0][0], Yf[mt][0][1], Yf[mt][0][2], Yf[mt][0][3],
                     Nf[0][0], Nf[0][1]);
            mma16816(db[mt][0], db[mt][1], db[mt][2], db[mt][3],
                     Yf[mt][1][0], Yf[mt][1][1], Yf[mt][1][2], Yf[mt][1][3],
                     Nf[1][0], Nf[1][1]);
        }
        // lanes t4<2 hold the 4 valid bias cols: t4=0 -> cols 0,1; t4=1 -> cols 2,3
#pragma unroll
        for (int mt = 0; mt < 2; mt++) {
            int r0 = mt * 16 + g, r1 = r0 + 8;
            int slot0 = __shfl_sync(0xffffffffu, slot_l, r0);
            int slot1 = __shfl_sync(0xffffffffu, slot_l, r1);
            if (t4 < 2) {
                if ((base + r0) < e)
                    *(float2*)(g_bias + (size_t)slot0 * 4 + 2 * t4) =
                        make_float2(db[mt][0], db[mt][1]);
                if ((base + r1) < e)
                    *(float2*)(g_bias + (size_t)slot1 * 4 + 2 * t4) =
                        make_float2(db[mt][2], db[mt][3]);
            }
        }
    }

    if (storeE) {
#pragma unroll
        for (int j = 0; j < 8; j++) {
            int r = j * 4 + lrow;
            int ed = base + r;
            if (ed < e)
                *((uint2*)(g_eh + (size_t)ed * 32) + lidx) = bH[r * 10 + lidx];
        }
    }
}

// ---------------- launch ----------------
extern "C" void kernel_launch(void* const* d_in, const int* in_sizes, int n_in,
                              void* d_out, int out_size) {
    const float* nodef = (const float*)d_in[0];
    const float* edgef = (const float*)d_in[1];
    const int*   ei    = (const int*)d_in[2];
    const float* Wq    = (const float*)d_in[3];
    const float* Wk    = (const float*)d_in[4];
    const float* Wv    = (const float*)d_in[5];
    const float* Wo    = (const float*)d_in[6];
    const float* We    = (const float*)d_in[7];
    const float* Wem   = (const float*)d_in[8];
    const float* bem   = (const float*)d_in[9];
    const float* gn    = (const float*)d_in[10];
    const float* bn    = (const float*)d_in[11];
    const float* ge    = (const float*)d_in[12];
    const float* be    = (const float*)d_in[13];
    float* out = (float*)d_out;

    int n = in_sizes[0] / 64;
    int e = in_sizes[1] / 32;
    const int* src = ei;
    const int* dst = ei + e;
    int projBlocks = (n + 127) / 128;

    static cudaStream_t s2 = 0;
    static cudaEvent_t evA = 0, evB = 0;
    static int tried = 0;
    if (!tried) {
        tried = 1;
        if (cudaStreamCreateWithFlags(&s2, cudaStreamNonBlocking) != cudaSuccess) s2 = 0;
        if (cudaEventCreateWithFlags(&evA, cudaEventDisableTiming) != cudaSuccess) evA = 0;
        if (cudaEventCreateWithFlags(&evB, cudaEventDisableTiming) != cudaSuccess) evB = 0;
    }
    bool useS2 = (s2 != 0) && (evA != 0) && (evB != 0);

    // 0: count  1: scan+proj(L0)  2: scatbias  3: attn(L0) <- profiled
    k_count<<<(e + 255) / 256, 256>>>(dst, e);
    k_scanproj<<<projBlocks + 1, 1024>>>(n, nodef, 0, Wq, Wk, Wv, 1);
    k_scatbias<<<(e + 127) / 128, 128>>>(src, dst, edgef, We, e);

    for (int i = 0; i < 3; i++) {
        if (i > 0) {
            k_scanproj<<<projBlocks, 1024>>>(n, nodef, 1,
                                             Wq + i * 4096, Wk + i * 4096, Wv + i * 4096, 0);
            if (useS2) cudaStreamWaitEvent(0, evB, 0);
        }
        k_attn<<<(n + 7) / 8, 256>>>(n);
        int last = (i == 2);
        k_lnnode<<<(n + 15) / 16, 512>>>(nodef, (i > 0),
                                         Wo + i * 4096, gn + i * 64, bn + i * 64,
                                         Wem + i * 5120, out, last, !last, n);
        if (!last) {
            if (useS2) {
                cudaEventRecord(evA, 0);
                cudaStreamWaitEvent(s2, evA, 0);
                k_edge<<<(e + 127) / 128, 128, 0, s2>>>(Wem + i * 5120 + 4096, bem + i * 32,
                                                        ge + i * 32, be + i * 32,
                                                        We + (i + 1) * 128,
                                                        src, dst, e, (i == 0) ? 1 : 0);
                cudaEventRecord(evB, s2);
            } else {
                k_edge<<<(e + 127) / 128, 128>>>(Wem + i * 5120 + 4096, bem + i * 32,
                                                 ge + i * 32, be + i * 32,
                                                 We + (i + 1) * 128,
                                                 src, dst, e, (i == 0) ? 1 : 0);
            }
        }
    }
}